// round 8
// baseline (speedup 1.0000x reference)
#include <cuda_runtime.h>
#include <cuda_fp16.h>
#include <cstdint>
#include <cstddef>

// Problem constants
#define SEQ   2048
#define NB    4
#define NH    16
#define HD    64
#define MDIM  8192     // NB*SEQ
#define NDIM  1024
#define KDIM  1024

// ---------------- scratch (static device globals: allocation-free) -------------
__device__ __half g_xq[(size_t)MDIM * KDIM];
__device__ __half g_xk[(size_t)MDIM * KDIM];
__device__ __half g_xv[(size_t)MDIM * KDIM];
__device__ __half g_oh[(size_t)MDIM * NDIM];
__device__ __half g_wqh[(size_t)NDIM * KDIM];
__device__ __half g_wql[(size_t)NDIM * KDIM];
__device__ __half g_wkh[(size_t)NDIM * KDIM];
__device__ __half g_wkl[(size_t)NDIM * KDIM];
__device__ __half g_wvh[(size_t)NDIM * KDIM];
__device__ __half g_wvl[(size_t)NDIM * KDIM];
__device__ __half g_woh[(size_t)NDIM * KDIM];
__device__ __half g_wol[(size_t)NDIM * KDIM];
__device__ __half g_qh[(size_t)NB * NH * SEQ * HD];   // Q (single fp16)
__device__ __half g_kh[(size_t)NB * NH * SEQ * HD];   // K hi
__device__ __half g_kl[(size_t)NB * NH * SEQ * HD];   // K lo
__device__ __half g_vh[(size_t)NB * NH * SEQ * HD];   // V (single fp16)
__device__ unsigned char g_mask8[(size_t)NB * SEQ * SEQ];
__device__ int g_mode;                              // 0=u8, 1=i32, 2=f32

// ================= helpers =====================================================
__device__ __forceinline__ uint32_t smem_u32(const void* p) {
    uint32_t a;
    asm("{ .reg .u64 t; cvta.to.shared.u64 t, %1; cvt.u32.u64 %0, t; }"
        : "=r"(a) : "l"(p));
    return a;
}

__device__ __forceinline__ uint32_t pack_h2(__half a, __half b) {
    __half2 t;
    t.x = a; t.y = b;
    return *(uint32_t*)&t;
}

__device__ __forceinline__ uint32_t cvt_h2(float x0, float x1) {
    return pack_h2(__float2half_rn(x0), __float2half_rn(x1));
}

__device__ __forceinline__ void cvt_hl2(float x0, float x1,
                                        uint32_t& hp, uint32_t& lp) {
    __half h0 = __float2half_rn(x0), h1 = __float2half_rn(x1);
    hp = pack_h2(h0, h1);
    lp = pack_h2(__float2half_rn(x0 - __half2float(h0)),
                 __float2half_rn(x1 - __half2float(h1)));
}

#define LDSM4(r, a) \
    asm volatile("ldmatrix.sync.aligned.m8n8.x4.shared.b16 {%0,%1,%2,%3}, [%4];" \
        : "=r"((r)[0]), "=r"((r)[1]), "=r"((r)[2]), "=r"((r)[3]) : "r"(a))

#define LDSM4T(r, a) \
    asm volatile("ldmatrix.sync.aligned.m8n8.x4.trans.shared.b16 {%0,%1,%2,%3}, [%4];" \
        : "=r"((r)[0]), "=r"((r)[1]), "=r"((r)[2]), "=r"((r)[3]) : "r"(a))

#define MMA_F16(c, a, b0, b1) \
    asm volatile("mma.sync.aligned.m16n8k16.row.col.f32.f16.f16.f32 " \
        "{%0,%1,%2,%3}, {%4,%5,%6,%7}, {%8,%9}, {%0,%1,%2,%3};" \
        : "+f"((c)[0]), "+f"((c)[1]), "+f"((c)[2]), "+f"((c)[3]) \
        : "r"((a)[0]), "r"((a)[1]), "r"((a)[2]), "r"((a)[3]), "r"(b0), "r"(b1))

#define CP_A16(dst, src) \
    asm volatile("cp.async.cg.shared.global [%0], [%1], 16;" :: "r"(dst), "l"(src))
#define CP_COMMIT() asm volatile("cp.async.commit_group;" ::: "memory")
#define CP_WAIT0()  asm volatile("cp.async.wait_group 0;" ::: "memory")
#define CP_WAIT1()  asm volatile("cp.async.wait_group 1;" ::: "memory")

// ---------------- mask dtype detection + conversion ---------------------------
__global__ void detect_mask_kernel(const unsigned int* __restrict__ w)
{
    __shared__ int s_not_i32, s_not_u8;
    if (threadIdx.x == 0) { s_not_i32 = 0; s_not_u8 = 0; }
    __syncthreads();
    int not_i32 = 0, not_u8 = 0;
    for (int i = threadIdx.x; i < 65536; i += 256) {
        unsigned v = w[i];
        unsigned b0 = v & 255u, b1 = (v >> 8) & 255u,
                 b2 = (v >> 16) & 255u, b3 = v >> 24;
        if ((b1 | b2 | b3) != 0u || b0 > 1u) not_i32 = 1;
        if (b0 > 1u || b1 > 1u || b2 > 1u || b3 > 1u) not_u8 = 1;
    }
    if (not_i32) atomicOr(&s_not_i32, 1);
    if (not_u8)  atomicOr(&s_not_u8, 1);
    __syncthreads();
    if (threadIdx.x == 0)
        g_mode = (!s_not_i32) ? 1 : ((!s_not_u8) ? 0 : 2);
}

__global__ void convert_mask_kernel(const void* __restrict__ m,
                                    unsigned char* __restrict__ o)
{
    const int mode = g_mode;
    const size_t n4 = (size_t)NB * SEQ * SEQ / 4;
    for (size_t i = (size_t)blockIdx.x * blockDim.x + threadIdx.x; i < n4;
         i += (size_t)gridDim.x * blockDim.x) {
        uchar4 r;
        if (mode == 1) {
            int4 v = ((const int4*)m)[i];
            r = make_uchar4(v.x != 0, v.y != 0, v.z != 0, v.w != 0);
        } else if (mode == 2) {
            float4 v = ((const float4*)m)[i];
            r = make_uchar4(v.x != 0.f, v.y != 0.f, v.z != 0.f, v.w != 0.f);
        } else {
            uchar4 v = ((const uchar4*)m)[i];
            r = make_uchar4(v.x != 0, v.y != 0, v.z != 0, v.w != 0);
        }
        ((uchar4*)o)[i] = r;
    }
}

// ---------------- fp32 -> fp16 streaming converters ----------------------------
__global__ void convert_h(const float4* __restrict__ in,
                          uint2* __restrict__ hi, size_t n4)
{
    for (size_t i = (size_t)blockIdx.x * blockDim.x + threadIdx.x; i < n4;
         i += (size_t)gridDim.x * blockDim.x) {
        float4 x = in[i];
        hi[i] = make_uint2(cvt_h2(x.x, x.y), cvt_h2(x.z, x.w));
    }
}

__global__ void convert_hl(const float4* __restrict__ in,
                           uint2* __restrict__ hi, uint2* __restrict__ lo,
                           size_t n4)
{
    for (size_t i = (size_t)blockIdx.x * blockDim.x + threadIdx.x; i < n4;
         i += (size_t)gridDim.x * blockDim.x) {
        float4 x = in[i];
        uint32_t h0, l0, h1, l1;
        cvt_hl2(x.x, x.y, h0, l0);
        cvt_hl2(x.z, x.w, h1, l1);
        hi[i] = make_uint2(h0, h1);
        lo[i] = make_uint2(l0, l1);
    }
}

// ================= 2-term fp16 HMMA GEMM (3-stage cp.async) ====================
// C[M,N] = A[M,K] @ W[N,K]^T  via  Ah*Wh + Ah*Wl  (mma.m16n8k16.f16)
#define GBK  32
#define NKT  (KDIM / GBK)     // 32
#define PADK 40               // fp16 pitch per row (80B)
#define T_A  0
#define T_WH 10240
#define T_WL 20480
#define STG_B 30720
#define GSMEM (3 * STG_B)     // 90 KB

__global__ void __launch_bounds__(256, 2)
gemm_f16(const __half* __restrict__ Ah,
         const __half* __restrict__ Wh, const __half* __restrict__ Wl,
         float* __restrict__ Cf,
         __half* __restrict__ Ch, __half* __restrict__ Cl,
         int mode)   // 0: fp32 out; 1: half out (Ch); 2: half h+l out (Ch, Cl)
{
    extern __shared__ char smc[];
    const uint32_t smb = smem_u32(smc);
    const int tid  = threadIdx.x;
    const int lane = tid & 31, wid = tid >> 5;
    const int wm = wid & 3;        // 4 warp-rows of 32
    const int wn = wid >> 2;       // 2 warp-cols of 64
    const int m0 = blockIdx.y * 128, n0 = blockIdx.x * 128;

    const int row0 = tid >> 2;     // 0..63
    const int ch   = tid & 3;      // 16B chunk (8 fp16) within 32-col stage

    float acc[2][8][4];
#pragma unroll
    for (int i = 0; i < 2; i++)
#pragma unroll
        for (int j = 0; j < 8; j++)
#pragma unroll
            for (int q = 0; q < 4; q++) acc[i][j][q] = 0.f;

    auto issue = [&](int kt) {
        if (kt < NKT) {
            const int k0 = kt * GBK;
            const uint32_t sb = smb + (kt % 3) * STG_B;
#pragma unroll
            for (int half = 0; half < 2; half++) {
                int r = row0 + half * 64;
                uint32_t doff = (uint32_t)(r * PADK + ch * 8) * 2;
                const size_t asrc = (size_t)(m0 + r) * KDIM + k0 + ch * 8;
                const size_t wsrc = (size_t)(n0 + r) * KDIM + k0 + ch * 8;
                CP_A16(sb + T_A  + doff, Ah + asrc);
                CP_A16(sb + T_WH + doff, Wh + wsrc);
                CP_A16(sb + T_WL + doff, Wl + wsrc);
            }
        }
        CP_COMMIT();
    };

    issue(0);
    issue(1);

    const int a_r = lane & 15;
    const int a_c = (lane >> 4) << 3;
    const int b_r = (lane & 7) + ((lane >> 4) << 3);
    const int b_c = ((lane >> 3) & 1) << 3;

    for (int kt = 0; kt < NKT; kt++) {
        CP_WAIT1();            // stage kt ready
        __syncthreads();       // also: all warps done with stage (kt-1)
        issue(kt + 2);         // refill the buffer consumed at (kt-1)

        const uint32_t sb = smb + (kt % 3) * STG_B;
#pragma unroll
        for (int ks = 0; ks < 2; ks++) {
            uint32_t af[2][4];
#pragma unroll
            for (int i = 0; i < 2; i++) {
                uint32_t off =
                    ((wm * 32 + i * 16 + a_r) * PADK + a_c + ks * 16) * 2;
                LDSM4(af[i], sb + T_A + off);
            }
#pragma unroll
            for (int p = 0; p < 4; p++) {
                uint32_t bh[4], bl[4];
                uint32_t off =
                    ((wn * 64 + p * 16 + b_r) * PADK + b_c + ks * 16) * 2;
                LDSM4(bh, sb + T_WH + off);
                LDSM4(bl, sb + T_WL + off);
#pragma unroll
                for (int i = 0; i < 2; i++)
#pragma unroll
                    for (int hf = 0; hf < 2; hf++) {
                        int j = p * 2 + hf;
                        MMA_F16(acc[i][j], af[i], bh[2*hf], bh[2*hf+1]);
                        MMA_F16(acc[i][j], af[i], bl[2*hf], bl[2*hf+1]);
                    }
            }
        }
    }

    // epilogue
#pragma unroll
    for (int i = 0; i < 2; i++) {
#pragma unroll
        for (int j = 0; j < 8; j++) {
            int mrow = m0 + wm * 32 + i * 16 + (lane >> 2);
            int ncol = n0 + wn * 64 + j * 8 + (lane & 3) * 2;
#pragma unroll
            for (int hf = 0; hf < 2; hf++) {
                int m = mrow + hf * 8;
                float v0 = acc[i][j][hf*2], v1 = acc[i][j][hf*2+1];
                if (mode == 0) {
                    *(float2*)(Cf + (size_t)m * NDIM + ncol) =
                        make_float2(v0, v1);
                } else {
                    int bb = m >> 11, s = m & 2047;
                    int hh = ncol >> 6, d = ncol & 63;
                    size_t off = ((size_t)(bb*NH + hh) * SEQ + s) * HD + d;
                    if (mode == 1) {
                        *(uint32_t*)(Ch + off) = cvt_h2(v0, v1);
                    } else {
                        uint32_t hp, lp;
                        cvt_hl2(v0, v1, hp, lp);
                        *(uint32_t*)(Ch + off) = hp;
                        *(uint32_t*)(Cl + off) = lp;
                    }
                }
            }
        }
    }
}

// ================= fp16 HMMA fused attention (cp.async double-buffer) ==========
// S = Qh*(Kh+Kl) ; T = relu(S/8+b)^2 split (Th+Tl) ; O += (Th+Tl)*Vh
#define APCH 72
#define A_Q   0
#define A_ST0 (128 * APCH * 2)        // 18432
#define S_KH  0
#define S_KL  9216
#define S_VH  18432
#define S_MS  27648
#define STG_A 35840                   // per stage
#define A_BYTES (A_ST0 + 2 * STG_A)   // 90112

__global__ void __launch_bounds__(256, 2)
attn_f16(const __half* __restrict__ qh,
         const __half* __restrict__ kh, const __half* __restrict__ kl,
         const __half* __restrict__ vh,
         const unsigned char* __restrict__ mask,
         const float* __restrict__ sn_bias,
         __half* __restrict__ oh)
{
    extern __shared__ char sm[];
    const uint32_t smb = smem_u32(sm);
    const int tid  = threadIdx.x;
    const int lane = tid & 31, wid = tid >> 5;
    const int bh = blockIdx.y;
    const int b = bh >> 4, h = bh & 15;
    const int q0g = blockIdx.x * 128;
    const float bias = sn_bias[0];

    const size_t kvbase = (size_t)bh * SEQ * HD;
    const unsigned char* msrc = mask + ((size_t)b * SEQ + q0g) * SEQ;

    // cp.async stage issue for K hi/lo, V, mask
    auto issue = [&](int kt) {
        if (kt < SEQ / 64) {
            const uint32_t sb = smb + A_ST0 + (kt & 1) * STG_A;
            const size_t tb = kvbase + (size_t)kt * 64 * HD;
#pragma unroll
            for (int i = 0; i < 2; i++) {
                int lin = tid + i * 256;    // 0..511
                int row = lin >> 3, c = lin & 7;
                const size_t off = tb + (size_t)row * HD + c * 8;
                uint32_t doff = (uint32_t)(row * APCH + c * 8) * 2;
                CP_A16(sb + S_KH + doff, kh + off);
                CP_A16(sb + S_KL + doff, kl + off);
                CP_A16(sb + S_VH + doff, vh + off);
            }
#pragma unroll
            for (int i = 0; i < 2; i++) {
                int lin = tid + i * 256;
                int q = lin >> 2, kg = lin & 3;
                CP_A16(sb + S_MS + q * 64 + kg * 16,
                       msrc + (size_t)q * SEQ + kt * 64 + kg * 16);
            }
        }
        CP_COMMIT();
    };

    issue(0);

    // stage Q tile [128 x 64] fp16 (plain loads, once)
    {
        const size_t qbase = ((size_t)bh * SEQ + q0g) * HD;
#pragma unroll
        for (int i = 0; i < 4; i++) {
            int lin = tid + i * 256;        // 0..1023
            int row = lin >> 3, c = lin & 7;
            *(uint4*)(sm + A_Q + (uint32_t)(row * APCH + c * 8) * 2) =
                *(const uint4*)(qh + qbase + (size_t)row * HD + c * 8);
        }
    }
    __syncthreads();

    const int a_r = lane & 15;
    const int a_c = (lane >> 4) << 3;
    const int b_r = (lane & 7) + ((lane >> 4) << 3);
    const int b_c = ((lane >> 3) & 1) << 3;
    const int v_r = ((lane >> 3) & 1) * 8 + (lane & 7);
    const int v_c = (lane >> 4) << 3;
    const int mrow0 = wid * 16 + (lane >> 2);

    // hoist Q fragments for the whole K loop
    uint32_t qf[4][4];
#pragma unroll
    for (int dc = 0; dc < 4; dc++)
        LDSM4(qf[dc], smb + A_Q + ((wid * 16 + a_r) * APCH + dc * 16 + a_c) * 2);

    float oacc[8][4];
#pragma unroll
    for (int j = 0; j < 8; j++)
#pragma unroll
        for (int e = 0; e < 4; e++) oacc[j][e] = 0.f;
    float rsum0 = 0.f, rsum1 = 0.f;

    for (int kt = 0; kt < SEQ / 64; kt++) {
        CP_WAIT0();            // stage kt data arrived
        __syncthreads();       // all warps done with stage (kt-1)
        issue(kt + 1);         // refill the other buffer

        const uint32_t sb = smb + A_ST0 + (kt & 1) * STG_A;

        // ---- S = Q K^T (per warp: 16 q x 64 k) ------------------------------
        uint32_t aph[4][4], apl[4][4];
#pragma unroll
        for (int nc = 0; nc < 4; nc++) {
            float sc[2][4];
#pragma unroll
            for (int hf = 0; hf < 2; hf++)
#pragma unroll
                for (int e = 0; e < 4; e++) sc[hf][e] = 0.f;

#pragma unroll
            for (int dc = 0; dc < 4; dc++) {
                uint32_t khf[4], klf[4];
                uint32_t ka = sb + S_KH +
                    ((nc * 16 + b_r) * APCH + dc * 16 + b_c) * 2;
                LDSM4(khf, ka);
                LDSM4(klf, ka + (S_KL - S_KH));
#pragma unroll
                for (int hf = 0; hf < 2; hf++) {
                    MMA_F16(sc[hf], qf[dc], khf[2*hf], khf[2*hf+1]);
                    MMA_F16(sc[hf], qf[dc], klf[2*hf], klf[2*hf+1]);
                }
            }

            // mask + bias + relu^2, rowsum, split T to hi/lo fp16 fragments
#pragma unroll
            for (int hf = 0; hf < 2; hf++) {
                int kcol = nc * 16 + hf * 8 + 2 * (lane & 3);
                uchar2 m0 = *(const uchar2*)(sm + A_ST0 + (kt & 1) * STG_A +
                                             S_MS + mrow0 * 64 + kcol);
                uchar2 m1 = *(const uchar2*)(sm + A_ST0 + (kt & 1) * STG_A +
                                             S_MS + (mrow0 + 8) * 64 + kcol);
                float t0 = fmaxf(fmaf(sc[hf][0], 0.125f, bias), 0.f);
                float t1 = fmaxf(fmaf(sc[hf][1], 0.125f, bias), 0.f);
                float t2 = fmaxf(fmaf(sc[hf][2], 0.125f, bias), 0.f);
                float t3 = fmaxf(fmaf(sc[hf][3], 0.125f, bias), 0.f);
                if (m0.x) t0 = 0.f;
                if (m0.y) t1 = 0.f;
                if (m1.x) t2 = 0.f;
                if (m1.y) t3 = 0.f;
                t0 *= t0; t1 *= t1; t2 *= t2; t3 *= t3;
                rsum0 += t0 + t1;
                rsum1 += t2 + t3;
                uint32_t hp, lp;
                cvt_hl2(t0, t1, hp, lp);
                aph[nc][2*hf + 0] = hp;
                apl[nc][2*hf + 0] = lp;
                cvt_hl2(t2, t3, hp, lp);
                aph[nc][2*hf + 1] = hp;
                apl[nc][2*hf + 1] = lp;
            }
        }

        // ---- O += T * V  (V via ldmatrix.trans) -----------------------------
#pragma unroll
        for (int kc = 0; kc < 4; kc++) {
#pragma unroll
            for (int dch = 0; dch < 4; dch++) {
                uint32_t vf[4];
                LDSM4T(vf, sb + S_VH +
                           ((kc * 16 + v_r) * APCH + dch * 16 + v_c) * 2);
#pragma unroll
                for (int hf = 0; hf < 2; hf++) {
                    int j = dch * 2 + hf;
                    MMA_F16(oacc[j], aph[kc], vf[2*hf], vf[2*hf+1]);
                    MMA_F16(oacc[j], apl[kc], vf[2*hf], vf[2*hf+1]);
                }
            }
        }
    }

    rsum0 += __shfl_xor_sync(0xffffffffu, rsum0, 1);
    rsum0 += __shfl_xor_sync(0xffffffffu, rsum0, 2);
    rsum1 += __shfl_xor_sync(0xffffffffu, rsum1, 1);
    rsum1 += __shfl_xor_sync(0xffffffffu, rsum1, 2);
    const float inv0 = 1.f / (rsum0 + 1e-32f);
    const float inv1 = 1.f / (rsum1 + 1e-32f);

    // store O (fp16) into [B, NQ, HSIZE] layout
    const int qr0 = q0g + mrow0;
#pragma unroll
    for (int j = 0; j < 8; j++) {
        int d = h * HD + j * 8 + 2 * (lane & 3);
        *(uint32_t*)(oh + (size_t)(b * SEQ + qr0) * NDIM + d) =
            cvt_h2(oacc[j][0] * inv0, oacc[j][1] * inv0);
        *(uint32_t*)(oh + (size_t)(b * SEQ + qr0 + 8) * NDIM + d) =
            cvt_h2(oacc[j][2] * inv1, oacc[j][3] * inv1);
    }
}

// ---------------- launcher ----------------------------------------------------
extern "C" void kernel_launch(void* const* d_in, const int* in_sizes, int n_in,
                              void* d_out, int out_size)
{
    const float* iQ      = (const float*)d_in[0];
    const float* iK      = (const float*)d_in[1];
    const float* iV      = (const float*)d_in[2];
    const void*  mask    = d_in[3];
    const float* Wq      = (const float*)d_in[4];
    const float* Wk      = (const float*)d_in[5];
    const float* Wv      = (const float*)d_in[6];
    const float* Wo      = (const float*)d_in[7];
    const float* sn_bias = (const float*)d_in[8];
    float*       out     = (float*)d_out;

    __half *xq, *xk, *xv, *ohb, *wqh, *wql, *wkh, *wkl, *wvh, *wvl, *woh, *wol;
    __half *qh, *kh, *kl, *vh;
    unsigned char* gm;
    cudaGetSymbolAddress((void**)&xq, g_xq);
    cudaGetSymbolAddress((void**)&xk, g_xk);
    cudaGetSymbolAddress((void**)&xv, g_xv);
    cudaGetSymbolAddress((void**)&ohb, g_oh);
    cudaGetSymbolAddress((void**)&wqh, g_wqh);
    cudaGetSymbolAddress((void**)&wql, g_wql);
    cudaGetSymbolAddress((void**)&wkh, g_wkh);
    cudaGetSymbolAddress((void**)&wkl, g_wkl);
    cudaGetSymbolAddress((void**)&wvh, g_wvh);
    cudaGetSymbolAddress((void**)&wvl, g_wvl);
    cudaGetSymbolAddress((void**)&woh, g_woh);
    cudaGetSymbolAddress((void**)&wol, g_wol);
    cudaGetSymbolAddress((void**)&qh, g_qh);
    cudaGetSymbolAddress((void**)&kh, g_kh);
    cudaGetSymbolAddress((void**)&kl, g_kl);
    cudaGetSymbolAddress((void**)&vh, g_vh);
    cudaGetSymbolAddress((void**)&gm, g_mask8);

    cudaFuncSetAttribute(gemm_f16,
                         cudaFuncAttributeMaxDynamicSharedMemorySize, GSMEM);
    cudaFuncSetAttribute(attn_f16,
                         cudaFuncAttributeMaxDynamicSharedMemorySize, A_BYTES);

    // mask dtype autodetect + conversion to u8 scratch
    detect_mask_kernel<<<1, 256>>>((const unsigned int*)mask);
    convert_mask_kernel<<<4096, 256>>>(mask, gm);

    const size_t nA4 = (size_t)MDIM * KDIM / 4;
    const size_t nW4 = (size_t)NDIM * KDIM / 4;
    dim3 gg(NDIM / 128, MDIM / 128);              // (8, 64)

    // all converts up front (independent, back-to-back)
    convert_h<<<2048, 256>>>((const float4*)iQ, (uint2*)xq, nA4);
    convert_h<<<2048, 256>>>((const float4*)iK, (uint2*)xk, nA4);
    convert_h<<<2048, 256>>>((const float4*)iV, (uint2*)xv, nA4);
    convert_hl<<<1024, 256>>>((const float4*)Wq, (uint2*)wqh, (uint2*)wql, nW4);
    convert_hl<<<1024, 256>>>((const float4*)Wk, (uint2*)wkh, (uint2*)wkl, nW4);
    convert_hl<<<1024, 256>>>((const float4*)Wv, (uint2*)wvh, (uint2*)wvl, nW4);
    convert_hl<<<1024, 256>>>((const float4*)Wo, (uint2*)woh, (uint2*)wol, nW4);

    gemm_f16<<<gg, 256, GSMEM>>>(xq, wqh, wql, nullptr, qh, nullptr, 1);
    gemm_f16<<<gg, 256, GSMEM>>>(xk, wkh, wkl, nullptr, kh, kl, 2);
    gemm_f16<<<gg, 256, GSMEM>>>(xv, wvh, wvl, nullptr, vh, nullptr, 1);

    attn_f16<<<dim3(SEQ / 128, NB * NH), 256, A_BYTES>>>(
        qh, kh, kl, vh, gm, sn_bias, ohb);

    gemm_f16<<<gg, 256, GSMEM>>>(ohb, woh, wol, out, nullptr, nullptr, 0);
}

// round 9
// speedup vs baseline: 1.0948x; 1.0948x over previous
#include <cuda_runtime.h>
#include <cuda_fp16.h>
#include <cstdint>
#include <cstddef>

// Problem constants
#define SEQ   2048
#define NB    4
#define NH    16
#define HD    64
#define MDIM  8192     // NB*SEQ
#define NDIM  1024
#define KDIM  1024

// ---------------- scratch (static device globals: allocation-free) -------------
__device__ __half g_xq[(size_t)MDIM * KDIM];
__device__ __half g_xk[(size_t)MDIM * KDIM];
__device__ __half g_xv[(size_t)MDIM * KDIM];
__device__ __half g_oh[(size_t)MDIM * NDIM];
__device__ __half g_wqh[(size_t)NDIM * KDIM];
__device__ __half g_wql[(size_t)NDIM * KDIM];
__device__ __half g_wkh[(size_t)NDIM * KDIM];
__device__ __half g_wkl[(size_t)NDIM * KDIM];
__device__ __half g_wvh[(size_t)NDIM * KDIM];
__device__ __half g_wvl[(size_t)NDIM * KDIM];
__device__ __half g_woh[(size_t)NDIM * KDIM];
__device__ __half g_wol[(size_t)NDIM * KDIM];
__device__ __half g_qh[(size_t)NB * NH * SEQ * HD];   // Q (single fp16)
__device__ __half g_kh[(size_t)NB * NH * SEQ * HD];   // K hi
__device__ __half g_kl[(size_t)NB * NH * SEQ * HD];   // K lo
__device__ __half g_vh[(size_t)NB * NH * SEQ * HD];   // V (single fp16)
__device__ unsigned char g_mask8[(size_t)NB * SEQ * SEQ];
__device__ int g_mode;                              // 0=u8, 1=i32, 2=f32

// ================= helpers =====================================================
__device__ __forceinline__ uint32_t smem_u32(const void* p) {
    uint32_t a;
    asm("{ .reg .u64 t; cvta.to.shared.u64 t, %1; cvt.u32.u64 %0, t; }"
        : "=r"(a) : "l"(p));
    return a;
}

__device__ __forceinline__ uint32_t pack_h2(__half a, __half b) {
    __half2 t;
    t.x = a; t.y = b;
    return *(uint32_t*)&t;
}

__device__ __forceinline__ uint32_t cvt_h2(float x0, float x1) {
    return pack_h2(__float2half_rn(x0), __float2half_rn(x1));
}

__device__ __forceinline__ void cvt_hl2(float x0, float x1,
                                        uint32_t& hp, uint32_t& lp) {
    __half h0 = __float2half_rn(x0), h1 = __float2half_rn(x1);
    hp = pack_h2(h0, h1);
    lp = pack_h2(__float2half_rn(x0 - __half2float(h0)),
                 __float2half_rn(x1 - __half2float(h1)));
}

#define LDSM4(r, a) \
    asm volatile("ldmatrix.sync.aligned.m8n8.x4.shared.b16 {%0,%1,%2,%3}, [%4];" \
        : "=r"((r)[0]), "=r"((r)[1]), "=r"((r)[2]), "=r"((r)[3]) : "r"(a))

#define LDSM4T(r, a) \
    asm volatile("ldmatrix.sync.aligned.m8n8.x4.trans.shared.b16 {%0,%1,%2,%3}, [%4];" \
        : "=r"((r)[0]), "=r"((r)[1]), "=r"((r)[2]), "=r"((r)[3]) : "r"(a))

#define MMA_F16(c, a, b0, b1) \
    asm volatile("mma.sync.aligned.m16n8k16.row.col.f32.f16.f16.f32 " \
        "{%0,%1,%2,%3}, {%4,%5,%6,%7}, {%8,%9}, {%0,%1,%2,%3};" \
        : "+f"((c)[0]), "+f"((c)[1]), "+f"((c)[2]), "+f"((c)[3]) \
        : "r"((a)[0]), "r"((a)[1]), "r"((a)[2]), "r"((a)[3]), "r"(b0), "r"(b1))

#define CP_A16(dst, src) \
    asm volatile("cp.async.cg.shared.global [%0], [%1], 16;" :: "r"(dst), "l"(src))
#define CP_COMMIT() asm volatile("cp.async.commit_group;" ::: "memory")
#define CP_WAIT1()  asm volatile("cp.async.wait_group 1;" ::: "memory")

// ---------------- mask dtype detection + conversion ---------------------------
__global__ void detect_mask_kernel(const unsigned int* __restrict__ w)
{
    __shared__ int s_not_i32, s_not_u8;
    if (threadIdx.x == 0) { s_not_i32 = 0; s_not_u8 = 0; }
    __syncthreads();
    int not_i32 = 0, not_u8 = 0;
    for (int i = threadIdx.x; i < 65536; i += 256) {
        unsigned v = w[i];
        unsigned b0 = v & 255u, b1 = (v >> 8) & 255u,
                 b2 = (v >> 16) & 255u, b3 = v >> 24;
        if ((b1 | b2 | b3) != 0u || b0 > 1u) not_i32 = 1;
        if (b0 > 1u || b1 > 1u || b2 > 1u || b3 > 1u) not_u8 = 1;
    }
    if (not_i32) atomicOr(&s_not_i32, 1);
    if (not_u8)  atomicOr(&s_not_u8, 1);
    __syncthreads();
    if (threadIdx.x == 0)
        g_mode = (!s_not_i32) ? 1 : ((!s_not_u8) ? 0 : 2);
}

__global__ void convert_mask_kernel(const void* __restrict__ m,
                                    unsigned char* __restrict__ o)
{
    const int mode = g_mode;
    const size_t n4 = (size_t)NB * SEQ * SEQ / 4;
    for (size_t i = (size_t)blockIdx.x * blockDim.x + threadIdx.x; i < n4;
         i += (size_t)gridDim.x * blockDim.x) {
        uchar4 r;
        if (mode == 1) {
            int4 v = ((const int4*)m)[i];
            r = make_uchar4(v.x != 0, v.y != 0, v.z != 0, v.w != 0);
        } else if (mode == 2) {
            float4 v = ((const float4*)m)[i];
            r = make_uchar4(v.x != 0.f, v.y != 0.f, v.z != 0.f, v.w != 0.f);
        } else {
            uchar4 v = ((const uchar4*)m)[i];
            r = make_uchar4(v.x != 0, v.y != 0, v.z != 0, v.w != 0);
        }
        ((uchar4*)o)[i] = r;
    }
}

// ---------------- merged fp32 -> fp16 streaming converters ---------------------
// one launch converts iQ, iK, iV (single fp16 each)
__global__ void convert_h3(const float4* __restrict__ i0,
                           const float4* __restrict__ i1,
                           const float4* __restrict__ i2,
                           uint2* __restrict__ o0, uint2* __restrict__ o1,
                           uint2* __restrict__ o2, size_t n4)
{
    for (size_t i = (size_t)blockIdx.x * blockDim.x + threadIdx.x; i < 3 * n4;
         i += (size_t)gridDim.x * blockDim.x) {
        const float4* in = (i < n4) ? i0 : (i < 2 * n4) ? i1 : i2;
        uint2* out = (i < n4) ? o0 : (i < 2 * n4) ? o1 : o2;
        size_t j = (i < n4) ? i : (i < 2 * n4) ? i - n4 : i - 2 * n4;
        float4 x = in[j];
        out[j] = make_uint2(cvt_h2(x.x, x.y), cvt_h2(x.z, x.w));
    }
}

// one launch converts Wq, Wk, Wv, Wo (hi+lo each)
__global__ void convert_hl4(const float4* __restrict__ i0, const float4* __restrict__ i1,
                            const float4* __restrict__ i2, const float4* __restrict__ i3,
                            uint2* __restrict__ h0, uint2* __restrict__ l0,
                            uint2* __restrict__ h1, uint2* __restrict__ l1,
                            uint2* __restrict__ h2, uint2* __restrict__ l2,
                            uint2* __restrict__ h3, uint2* __restrict__ l3,
                            size_t n4)
{
    for (size_t i = (size_t)blockIdx.x * blockDim.x + threadIdx.x; i < 4 * n4;
         i += (size_t)gridDim.x * blockDim.x) {
        int seg = (int)(i / n4);
        size_t j = i - (size_t)seg * n4;
        const float4* in = (seg == 0) ? i0 : (seg == 1) ? i1 : (seg == 2) ? i2 : i3;
        uint2* hh = (seg == 0) ? h0 : (seg == 1) ? h1 : (seg == 2) ? h2 : h3;
        uint2* ll = (seg == 0) ? l0 : (seg == 1) ? l1 : (seg == 2) ? l2 : l3;
        float4 x = in[j];
        uint32_t a0, b0, a1, b1;
        cvt_hl2(x.x, x.y, a0, b0);
        cvt_hl2(x.z, x.w, a1, b1);
        hh[j] = make_uint2(a0, a1);
        ll[j] = make_uint2(b0, b1);
    }
}

// ================= 2-term fp16 HMMA GEMM (2-stage cp.async, round-7 proven) ====
// C[M,N] = A[M,K] @ W[N,K]^T  via  Ah*Wh + Ah*Wl  (mma.m16n8k16.f16)
#define GBK  32
#define NKT  (KDIM / GBK)     // 32
#define PADK 40               // fp16 pitch per row (80B)
#define T_A  0
#define T_WH 10240
#define T_WL 20480
#define STG_B 30720
#define GSMEM (2 * STG_B)     // 60 KB

struct GemmSeg {
    const __half* Ah;
    const __half* Wh;
    const __half* Wl;
    float* Cf;
    __half* Ch;
    __half* Cl;
    int mode;   // 0: fp32 out; 1: half out; 2: half hi+lo out
};

__device__ __forceinline__ void gemm_body(
    const __half* __restrict__ Ah,
    const __half* __restrict__ Wh, const __half* __restrict__ Wl,
    float* __restrict__ Cf, __half* __restrict__ Ch, __half* __restrict__ Cl,
    int mode, int m0, int n0, char* smc)
{
    const uint32_t smb = smem_u32(smc);
    const int tid  = threadIdx.x;
    const int lane = tid & 31, wid = tid >> 5;
    const int wm = wid & 3;
    const int wn = wid >> 2;

    const int row0 = tid >> 2;
    const int ch   = tid & 3;

    float acc[2][8][4];
#pragma unroll
    for (int i = 0; i < 2; i++)
#pragma unroll
        for (int j = 0; j < 8; j++)
#pragma unroll
            for (int q = 0; q < 4; q++) acc[i][j][q] = 0.f;

    auto issue = [&](int kt) {
        if (kt < NKT) {
            const int k0 = kt * GBK;
            const uint32_t sb = smb + (kt & 1) * STG_B;
#pragma unroll
            for (int half = 0; half < 2; half++) {
                int r = row0 + half * 64;
                uint32_t doff = (uint32_t)(r * PADK + ch * 8) * 2;
                const size_t asrc = (size_t)(m0 + r) * KDIM + k0 + ch * 8;
                const size_t wsrc = (size_t)(n0 + r) * KDIM + k0 + ch * 8;
                CP_A16(sb + T_A  + doff, Ah + asrc);
                CP_A16(sb + T_WH + doff, Wh + wsrc);
                CP_A16(sb + T_WL + doff, Wl + wsrc);
            }
        }
        CP_COMMIT();
    };

    issue(0);
    issue(1);
    CP_WAIT1();
    __syncthreads();

    const int a_r = lane & 15;
    const int a_c = (lane >> 4) << 3;
    const int b_r = (lane & 7) + ((lane >> 4) << 3);
    const int b_c = ((lane >> 3) & 1) << 3;

    for (int kt = 0; kt < NKT; kt++) {
        const uint32_t sb = smb + (kt & 1) * STG_B;

#pragma unroll
        for (int ks = 0; ks < 2; ks++) {
            uint32_t af[2][4];
#pragma unroll
            for (int i = 0; i < 2; i++) {
                uint32_t off =
                    ((wm * 32 + i * 16 + a_r) * PADK + a_c + ks * 16) * 2;
                LDSM4(af[i], sb + T_A + off);
            }
#pragma unroll
            for (int p = 0; p < 4; p++) {
                uint32_t bh[4], bl[4];
                uint32_t off =
                    ((wn * 64 + p * 16 + b_r) * PADK + b_c + ks * 16) * 2;
                LDSM4(bh, sb + T_WH + off);
                LDSM4(bl, sb + T_WL + off);
#pragma unroll
                for (int i = 0; i < 2; i++)
#pragma unroll
                    for (int hf = 0; hf < 2; hf++) {
                        int j = p * 2 + hf;
                        MMA_F16(acc[i][j], af[i], bh[2*hf], bh[2*hf+1]);
                        MMA_F16(acc[i][j], af[i], bl[2*hf], bl[2*hf+1]);
                    }
            }
        }
        __syncthreads();
        issue(kt + 2);
        CP_WAIT1();
        __syncthreads();
    }

    // epilogue
#pragma unroll
    for (int i = 0; i < 2; i++) {
#pragma unroll
        for (int j = 0; j < 8; j++) {
            int mrow = m0 + wm * 32 + i * 16 + (lane >> 2);
            int ncol = n0 + wn * 64 + j * 8 + (lane & 3) * 2;
#pragma unroll
            for (int hf = 0; hf < 2; hf++) {
                int m = mrow + hf * 8;
                float v0 = acc[i][j][hf*2], v1 = acc[i][j][hf*2+1];
                if (mode == 0) {
                    *(float2*)(Cf + (size_t)m * NDIM + ncol) =
                        make_float2(v0, v1);
                } else {
                    int bb = m >> 11, s = m & 2047;
                    int hh = ncol >> 6, d = ncol & 63;
                    size_t off = ((size_t)(bb*NH + hh) * SEQ + s) * HD + d;
                    if (mode == 1) {
                        *(uint32_t*)(Ch + off) = cvt_h2(v0, v1);
                    } else {
                        uint32_t hp, lp;
                        cvt_hl2(v0, v1, hp, lp);
                        *(uint32_t*)(Ch + off) = hp;
                        *(uint32_t*)(Cl + off) = lp;
                    }
                }
            }
        }
    }
}

// merged Q/K/V projection: grid.y = 192 (seg = y/64: 0=Q, 1=K, 2=V)
__global__ void __launch_bounds__(256, 2)
gemm_qkv(const __half* __restrict__ xq, const __half* __restrict__ xk,
         const __half* __restrict__ xv,
         const __half* __restrict__ wqh, const __half* __restrict__ wql,
         const __half* __restrict__ wkh, const __half* __restrict__ wkl,
         const __half* __restrict__ wvh, const __half* __restrict__ wvl,
         __half* __restrict__ qh, __half* __restrict__ kh,
         __half* __restrict__ kl, __half* __restrict__ vh)
{
    extern __shared__ char smc[];
    const int seg = blockIdx.y >> 6;           // 0,1,2
    const int m0 = (blockIdx.y & 63) * 128;
    const int n0 = blockIdx.x * 128;
    const __half* Ah = (seg == 0) ? xq  : (seg == 1) ? xk  : xv;
    const __half* Wh = (seg == 0) ? wqh : (seg == 1) ? wkh : wvh;
    const __half* Wl = (seg == 0) ? wql : (seg == 1) ? wkl : wvl;
    __half* Ch = (seg == 0) ? qh : (seg == 1) ? kh : vh;
    __half* Cl = (seg == 1) ? kl : nullptr;
    const int mode = (seg == 1) ? 2 : 1;
    gemm_body(Ah, Wh, Wl, nullptr, Ch, Cl, mode, m0, n0, smc);
}

// output projection (fp32 out)
__global__ void __launch_bounds__(256, 2)
gemm_out(const __half* __restrict__ Ah,
         const __half* __restrict__ Wh, const __half* __restrict__ Wl,
         float* __restrict__ Cf)
{
    extern __shared__ char smc[];
    gemm_body(Ah, Wh, Wl, Cf, nullptr, nullptr, 0,
              blockIdx.y * 128, blockIdx.x * 128, smc);
}

// ================= fp16 HMMA fused attention (round-7 proven) ==================
// S = Qh*(Kh+Kl) ; T = relu(S/8+b)^2 split (Th+Tl) ; O += (Th+Tl)*Vh
#define APCH 72
#define A_Q  0
#define A_KH (A_Q  + 128 * APCH * 2)  // 18432
#define A_KL (A_KH + 64 * APCH * 2)   // 27648
#define A_VH (A_KL + 64 * APCH * 2)   // 36864
#define A_MS (A_VH + 64 * APCH * 2)   // 46080
#define A_BYTES (A_MS + 128 * 64)     // 54272

__global__ void __launch_bounds__(256, 2)
attn_f16(const __half* __restrict__ qh,
         const __half* __restrict__ kh, const __half* __restrict__ kl,
         const __half* __restrict__ vh,
         const unsigned char* __restrict__ mask,
         const float* __restrict__ sn_bias,
         __half* __restrict__ oh)
{
    extern __shared__ char sm[];
    const uint32_t smb = smem_u32(sm);
    const int tid  = threadIdx.x;
    const int lane = tid & 31, wid = tid >> 5;
    const int bh = blockIdx.y;
    const int b = bh >> 4, h = bh & 15;
    const int q0g = blockIdx.x * 128;
    const float bias = sn_bias[0];

    // stage Q tile [128 x 64] fp16
    {
        const size_t qbase = ((size_t)bh * SEQ + q0g) * HD;
#pragma unroll
        for (int i = 0; i < 4; i++) {
            int lin = tid + i * 256;        // 0..1023
            int row = lin >> 3, c = lin & 7;
            *(uint4*)(sm + A_Q + (uint32_t)(row * APCH + c * 8) * 2) =
                *(const uint4*)(qh + qbase + (size_t)row * HD + c * 8);
        }
    }
    __syncthreads();

    const int a_r = lane & 15;
    const int a_c = (lane >> 4) << 3;
    const int b_r = (lane & 7) + ((lane >> 4) << 3);
    const int b_c = ((lane >> 3) & 1) << 3;
    const int v_r = ((lane >> 3) & 1) * 8 + (lane & 7);
    const int v_c = (lane >> 4) << 3;
    const int mrow0 = wid * 16 + (lane >> 2);

    // hoist Q fragments for the whole K loop
    uint32_t qf[4][4];
#pragma unroll
    for (int dc = 0; dc < 4; dc++)
        LDSM4(qf[dc], smb + A_Q + ((wid * 16 + a_r) * APCH + dc * 16 + a_c) * 2);

    float oacc[8][4];
#pragma unroll
    for (int j = 0; j < 8; j++)
#pragma unroll
        for (int e = 0; e < 4; e++) oacc[j][e] = 0.f;
    float rsum0 = 0.f, rsum1 = 0.f;

    const size_t kvbase = (size_t)bh * SEQ * HD;
    const unsigned char* msrc = mask + ((size_t)b * SEQ + q0g) * SEQ;

    for (int kt = 0; kt < SEQ / 64; kt++) {
        __syncthreads();
        // stage K hi/lo, V (64x64) + mask (128x64)
        {
            const size_t tb = kvbase + (size_t)kt * 64 * HD;
#pragma unroll
            for (int i = 0; i < 2; i++) {
                int lin = tid + i * 256;    // 0..511
                int row = lin >> 3, c = lin & 7;
                size_t off = tb + (size_t)row * HD + c * 8;
                uint32_t doff = (uint32_t)(row * APCH + c * 8) * 2;
                *(uint4*)(sm + A_KH + doff) = *(const uint4*)(kh + off);
                *(uint4*)(sm + A_KL + doff) = *(const uint4*)(kl + off);
                *(uint4*)(sm + A_VH + doff) = *(const uint4*)(vh + off);
            }
#pragma unroll
            for (int i = 0; i < 2; i++) {
                int lin = tid + i * 256;
                int q = lin >> 2, kg = lin & 3;
                *((uint4*)(sm + A_MS + q * 64) + kg) =
                    *((const uint4*)(msrc + (size_t)q * SEQ + kt * 64) + kg);
            }
        }
        __syncthreads();

        // ---- S = Q K^T (per warp: 16 q x 64 k) ------------------------------
        uint32_t aph[4][4], apl[4][4];
#pragma unroll
        for (int nc = 0; nc < 4; nc++) {
            float sc[2][4];
#pragma unroll
            for (int hf = 0; hf < 2; hf++)
#pragma unroll
                for (int e = 0; e < 4; e++) sc[hf][e] = 0.f;

#pragma unroll
            for (int dc = 0; dc < 4; dc++) {
                uint32_t khf[4], klf[4];
                uint32_t ka = smb + A_KH +
                    ((nc * 16 + b_r) * APCH + dc * 16 + b_c) * 2;
                LDSM4(khf, ka);
                LDSM4(klf, ka + (A_KL - A_KH));
#pragma unroll
                for (int hf = 0; hf < 2; hf++) {
                    MMA_F16(sc[hf], qf[dc], khf[2*hf], khf[2*hf+1]);
                    MMA_F16(sc[hf], qf[dc], klf[2*hf], klf[2*hf+1]);
                }
            }

            // mask + bias + relu^2, rowsum, split T to hi/lo fp16 fragments
#pragma unroll
            for (int hf = 0; hf < 2; hf++) {
                int kcol = nc * 16 + hf * 8 + 2 * (lane & 3);
                uchar2 m0 = *(const uchar2*)(sm + A_MS + mrow0 * 64 + kcol);
                uchar2 m1 = *(const uchar2*)(sm + A_MS + (mrow0 + 8) * 64 + kcol);
                float t0 = fmaxf(fmaf(sc[hf][0], 0.125f, bias), 0.f);
                float t1 = fmaxf(fmaf(sc[hf][1], 0.125f, bias), 0.f);
                float t2 = fmaxf(fmaf(sc[hf][2], 0.125f, bias), 0.f);
                float t3 = fmaxf(fmaf(sc[hf][3], 0.125f, bias), 0.f);
                if (m0.x) t0 = 0.f;
                if (m0.y) t1 = 0.f;
                if (m1.x) t2 = 0.f;
                if (m1.y) t3 = 0.f;
                t0 *= t0; t1 *= t1; t2 *= t2; t3 *= t3;
                rsum0 += t0 + t1;
                rsum1 += t2 + t3;
                uint32_t hp, lp;
                cvt_hl2(t0, t1, hp, lp);
                aph[nc][2*hf + 0] = hp;
                apl[nc][2*hf + 0] = lp;
                cvt_hl2(t2, t3, hp, lp);
                aph[nc][2*hf + 1] = hp;
                apl[nc][2*hf + 1] = lp;
            }
        }

        // ---- O += T * V  (V via ldmatrix.trans) -----------------------------
#pragma unroll
        for (int kc = 0; kc < 4; kc++) {
#pragma unroll
            for (int dch = 0; dch < 4; dch++) {
                uint32_t vf[4];
                LDSM4T(vf, smb + A_VH +
                           ((kc * 16 + v_r) * APCH + dch * 16 + v_c) * 2);
#pragma unroll
                for (int hf = 0; hf < 2; hf++) {
                    int j = dch * 2 + hf;
                    MMA_F16(oacc[j], aph[kc], vf[2*hf], vf[2*hf+1]);
                    MMA_F16(oacc[j], apl[kc], vf[2*hf], vf[2*hf+1]);
                }
            }
        }
    }

    rsum0 += __shfl_xor_sync(0xffffffffu, rsum0, 1);
    rsum0 += __shfl_xor_sync(0xffffffffu, rsum0, 2);
    rsum1 += __shfl_xor_sync(0xffffffffu, rsum1, 1);
    rsum1 += __shfl_xor_sync(0xffffffffu, rsum1, 2);
    const float inv0 = 1.f / (rsum0 + 1e-32f);
    const float inv1 = 1.f / (rsum1 + 1e-32f);

    // store O (fp16) into [B, NQ, HSIZE] layout
    const int qr0 = q0g + mrow0;
#pragma unroll
    for (int j = 0; j < 8; j++) {
        int d = h * HD + j * 8 + 2 * (lane & 3);
        *(uint32_t*)(oh + (size_t)(b * SEQ + qr0) * NDIM + d) =
            cvt_h2(oacc[j][0] * inv0, oacc[j][1] * inv0);
        *(uint32_t*)(oh + (size_t)(b * SEQ + qr0 + 8) * NDIM + d) =
            cvt_h2(oacc[j][2] * inv1, oacc[j][3] * inv1);
    }
}

// ---------------- launcher ----------------------------------------------------
extern "C" void kernel_launch(void* const* d_in, const int* in_sizes, int n_in,
                              void* d_out, int out_size)
{
    const float* iQ      = (const float*)d_in[0];
    const float* iK      = (const float*)d_in[1];
    const float* iV      = (const float*)d_in[2];
    const void*  mask    = d_in[3];
    const float* Wq      = (const float*)d_in[4];
    const float* Wk      = (const float*)d_in[5];
    const float* Wv      = (const float*)d_in[6];
    const float* Wo      = (const float*)d_in[7];
    const float* sn_bias = (const float*)d_in[8];
    float*       out     = (float*)d_out;

    __half *xq, *xk, *xv, *ohb, *wqh, *wql, *wkh, *wkl, *wvh, *wvl, *woh, *wol;
    __half *qh, *kh, *kl, *vh;
    unsigned char* gm;
    cudaGetSymbolAddress((void**)&xq, g_xq);
    cudaGetSymbolAddress((void**)&xk, g_xk);
    cudaGetSymbolAddress((void**)&xv, g_xv);
    cudaGetSymbolAddress((void**)&ohb, g_oh);
    cudaGetSymbolAddress((void**)&wqh, g_wqh);
    cudaGetSymbolAddress((void**)&wql, g_wql);
    cudaGetSymbolAddress((void**)&wkh, g_wkh);
    cudaGetSymbolAddress((void**)&wkl, g_wkl);
    cudaGetSymbolAddress((void**)&wvh, g_wvh);
    cudaGetSymbolAddress((void**)&wvl, g_wvl);
    cudaGetSymbolAddress((void**)&woh, g_woh);
    cudaGetSymbolAddress((void**)&wol, g_wol);
    cudaGetSymbolAddress((void**)&qh, g_qh);
    cudaGetSymbolAddress((void**)&kh, g_kh);
    cudaGetSymbolAddress((void**)&kl, g_kl);
    cudaGetSymbolAddress((void**)&vh, g_vh);
    cudaGetSymbolAddress((void**)&gm, g_mask8);

    cudaFuncSetAttribute(gemm_qkv,
                         cudaFuncAttributeMaxDynamicSharedMemorySize, GSMEM);
    cudaFuncSetAttribute(gemm_out,
                         cudaFuncAttributeMaxDynamicSharedMemorySize, GSMEM);
    cudaFuncSetAttribute(attn_f16,
                         cudaFuncAttributeMaxDynamicSharedMemorySize, A_BYTES);

    // mask dtype autodetect + conversion to u8 scratch
    detect_mask_kernel<<<1, 256>>>((const unsigned int*)mask);
    convert_mask_kernel<<<4096, 256>>>(mask, gm);

    const size_t nA4 = (size_t)MDIM * KDIM / 4;
    const size_t nW4 = (size_t)NDIM * KDIM / 4;

    // merged converts (2 launches)
    convert_h3<<<4096, 256>>>((const float4*)iQ, (const float4*)iK,
                              (const float4*)iV,
                              (uint2*)xq, (uint2*)xk, (uint2*)xv, nA4);
    convert_hl4<<<2048, 256>>>((const float4*)Wq, (const float4*)Wk,
                               (const float4*)Wv, (const float4*)Wo,
                               (uint2*)wqh, (uint2*)wql, (uint2*)wkh, (uint2*)wkl,
                               (uint2*)wvh, (uint2*)wvl, (uint2*)woh, (uint2*)wol,
                               nW4);

    // merged Q/K/V projections: one launch, 1536 CTAs
    gemm_qkv<<<dim3(NDIM / 128, 192), 256, GSMEM>>>(
        xq, xk, xv, wqh, wql, wkh, wkl, wvh, wvl, qh, kh, kl, vh);

    attn_f16<<<dim3(SEQ / 128, NB * NH), 256, A_BYTES>>>(
        qh, kh, kl, vh, gm, sn_bias, ohb);

    gemm_out<<<dim3(NDIM / 128, MDIM / 128), 256, GSMEM>>>(ohb, woh, wol, out);
}

// round 12
// speedup vs baseline: 1.1192x; 1.0224x over previous
#include <cuda_runtime.h>
#include <cuda_fp16.h>
#include <cstdint>
#include <cstddef>

// Problem constants
#define SEQ   2048
#define NB    4
#define NH    16
#define HD    64
#define MDIM  8192     // NB*SEQ
#define NDIM  1024
#define KDIM  1024

// ---------------- scratch (static device globals: allocation-free) -------------
__device__ __half g_xq[(size_t)MDIM * KDIM];
__device__ __half g_xk[(size_t)MDIM * KDIM];
__device__ __half g_xv[(size_t)MDIM * KDIM];
__device__ __half g_oh[(size_t)MDIM * NDIM];
__device__ __half g_wqh[(size_t)NDIM * KDIM];
__device__ __half g_wql[(size_t)NDIM * KDIM];
__device__ __half g_wkh[(size_t)NDIM * KDIM];
__device__ __half g_wkl[(size_t)NDIM * KDIM];
__device__ __half g_wvh[(size_t)NDIM * KDIM];
__device__ __half g_wvl[(size_t)NDIM * KDIM];
__device__ __half g_woh[(size_t)NDIM * KDIM];
__device__ __half g_wol[(size_t)NDIM * KDIM];
__device__ __half g_qh[(size_t)NB * NH * SEQ * HD];   // Q (single fp16)
__device__ __half g_kh[(size_t)NB * NH * SEQ * HD];   // K hi
__device__ __half g_kl[(size_t)NB * NH * SEQ * HD];   // K lo
__device__ __half g_vh[(size_t)NB * NH * SEQ * HD];   // V (single fp16)
__device__ uint32_t g_maskb[(size_t)NB * SEQ * SEQ / 32];  // bit-packed mask
__device__ int g_mode;                              // 0=u8, 1=i32, 2=f32

// ================= helpers =====================================================
__device__ __forceinline__ uint32_t smem_u32(const void* p) {
    uint32_t a;
    asm("{ .reg .u64 t; cvta.to.shared.u64 t, %1; cvt.u32.u64 %0, t; }"
        : "=r"(a) : "l"(p));
    return a;
}

__device__ __forceinline__ uint32_t pack_h2(__half a, __half b) {
    __half2 t;
    t.x = a; t.y = b;
    return *(uint32_t*)&t;
}

__device__ __forceinline__ uint32_t cvt_h2(float x0, float x1) {
    return pack_h2(__float2half_rn(x0), __float2half_rn(x1));
}

__device__ __forceinline__ void cvt_hl2(float x0, float x1,
                                        uint32_t& hp, uint32_t& lp) {
    __half h0 = __float2half_rn(x0), h1 = __float2half_rn(x1);
    hp = pack_h2(h0, h1);
    lp = pack_h2(__float2half_rn(x0 - __half2float(h0)),
                 __float2half_rn(x1 - __half2float(h1)));
}

__device__ __forceinline__ uint32_t u4sel(const uint4& v, int i) {
    return (i == 0) ? v.x : (i == 1) ? v.y : (i == 2) ? v.z : v.w;
}

#define LDSM4(r, a) \
    asm volatile("ldmatrix.sync.aligned.m8n8.x4.shared.b16 {%0,%1,%2,%3}, [%4];" \
        : "=r"((r)[0]), "=r"((r)[1]), "=r"((r)[2]), "=r"((r)[3]) : "r"(a))

#define LDSM4T(r, a) \
    asm volatile("ldmatrix.sync.aligned.m8n8.x4.trans.shared.b16 {%0,%1,%2,%3}, [%4];" \
        : "=r"((r)[0]), "=r"((r)[1]), "=r"((r)[2]), "=r"((r)[3]) : "r"(a))

#define MMA_F16(c, a, b0, b1) \
    asm volatile("mma.sync.aligned.m16n8k16.row.col.f32.f16.f16.f32 " \
        "{%0,%1,%2,%3}, {%4,%5,%6,%7}, {%8,%9}, {%0,%1,%2,%3};" \
        : "+f"((c)[0]), "+f"((c)[1]), "+f"((c)[2]), "+f"((c)[3]) \
        : "r"((a)[0]), "r"((a)[1]), "r"((a)[2]), "r"((a)[3]), "r"(b0), "r"(b1))

#define CP_A16(dst, src) \
    asm volatile("cp.async.cg.shared.global [%0], [%1], 16;" :: "r"(dst), "l"(src))
#define CP_COMMIT() asm volatile("cp.async.commit_group;" ::: "memory")
#define CP_WAIT1()  asm volatile("cp.async.wait_group 1;" ::: "memory")

// ---------------- mask dtype detection + bit-pack conversion -------------------
__global__ void detect_mask_kernel(const unsigned int* __restrict__ w)
{
    __shared__ int s_not_i32, s_not_u8;
    if (threadIdx.x == 0) { s_not_i32 = 0; s_not_u8 = 0; }
    __syncthreads();
    int not_i32 = 0, not_u8 = 0;
    for (int i = threadIdx.x; i < 65536; i += 256) {
        unsigned v = w[i];
        unsigned b0 = v & 255u, b1 = (v >> 8) & 255u,
                 b2 = (v >> 16) & 255u, b3 = v >> 24;
        if ((b1 | b2 | b3) != 0u || b0 > 1u) not_i32 = 1;
        if (b0 > 1u || b1 > 1u || b2 > 1u || b3 > 1u) not_u8 = 1;
    }
    if (not_i32) atomicOr(&s_not_i32, 1);
    if (not_u8)  atomicOr(&s_not_u8, 1);
    __syncthreads();
    if (threadIdx.x == 0)
        g_mode = (!s_not_i32) ? 1 : ((!s_not_u8) ? 0 : 2);
}

// build bit-packed mask: word w holds elements [32w, 32w+32), bit set = masked
__global__ void convert_maskb(const void* __restrict__ m, uint32_t* __restrict__ o)
{
    const int mode = g_mode;
    const size_t nw = (size_t)NB * SEQ * SEQ / 32;
    for (size_t w = (size_t)blockIdx.x * blockDim.x + threadIdx.x; w < nw;
         w += (size_t)gridDim.x * blockDim.x) {
        uint32_t bits = 0;
        if (mode == 1) {
            const uint4* p = (const uint4*)((const int*)m + w * 32);
#pragma unroll
            for (int g = 0; g < 8; g++) {
                uint4 v = p[g];
                bits |= (v.x ? 1u : 0u) << (g * 4 + 0);
                bits |= (v.y ? 1u : 0u) << (g * 4 + 1);
                bits |= (v.z ? 1u : 0u) << (g * 4 + 2);
                bits |= (v.w ? 1u : 0u) << (g * 4 + 3);
            }
        } else if (mode == 2) {
            const float4* p = (const float4*)((const float*)m + w * 32);
#pragma unroll
            for (int g = 0; g < 8; g++) {
                float4 v = p[g];
                bits |= (v.x != 0.f ? 1u : 0u) << (g * 4 + 0);
                bits |= (v.y != 0.f ? 1u : 0u) << (g * 4 + 1);
                bits |= (v.z != 0.f ? 1u : 0u) << (g * 4 + 2);
                bits |= (v.w != 0.f ? 1u : 0u) << (g * 4 + 3);
            }
        } else {
            const uint4* p = (const uint4*)((const unsigned char*)m + w * 32);
#pragma unroll
            for (int g = 0; g < 2; g++) {
                uint4 v = p[g];
                uint32_t ws[4] = {v.x, v.y, v.z, v.w};
#pragma unroll
                for (int q = 0; q < 4; q++)
#pragma unroll
                    for (int e = 0; e < 4; e++)
                        bits |= (((ws[q] >> (e * 8)) & 255u) ? 1u : 0u)
                                << (g * 16 + q * 4 + e);
            }
        }
        o[w] = bits;
    }
}

// ---------------- merged fp32 -> fp16 streaming converters ---------------------
__global__ void convert_h3(const float4* __restrict__ i0,
                           const float4* __restrict__ i1,
                           const float4* __restrict__ i2,
                           uint2* __restrict__ o0, uint2* __restrict__ o1,
                           uint2* __restrict__ o2, size_t n4)
{
    for (size_t i = (size_t)blockIdx.x * blockDim.x + threadIdx.x; i < 3 * n4;
         i += (size_t)gridDim.x * blockDim.x) {
        const float4* in = (i < n4) ? i0 : (i < 2 * n4) ? i1 : i2;
        uint2* out = (i < n4) ? o0 : (i < 2 * n4) ? o1 : o2;
        size_t j = (i < n4) ? i : (i < 2 * n4) ? i - n4 : i - 2 * n4;
        float4 x = in[j];
        out[j] = make_uint2(cvt_h2(x.x, x.y), cvt_h2(x.z, x.w));
    }
}

__global__ void convert_hl4(const float4* __restrict__ i0, const float4* __restrict__ i1,
                            const float4* __restrict__ i2, const float4* __restrict__ i3,
                            uint2* __restrict__ h0, uint2* __restrict__ l0,
                            uint2* __restrict__ h1, uint2* __restrict__ l1,
                            uint2* __restrict__ h2, uint2* __restrict__ l2,
                            uint2* __restrict__ h3, uint2* __restrict__ l3,
                            size_t n4)
{
    for (size_t i = (size_t)blockIdx.x * blockDim.x + threadIdx.x; i < 4 * n4;
         i += (size_t)gridDim.x * blockDim.x) {
        int seg = (int)(i / n4);
        size_t j = i - (size_t)seg * n4;
        const float4* in = (seg == 0) ? i0 : (seg == 1) ? i1 : (seg == 2) ? i2 : i3;
        uint2* hh = (seg == 0) ? h0 : (seg == 1) ? h1 : (seg == 2) ? h2 : h3;
        uint2* ll = (seg == 0) ? l0 : (seg == 1) ? l1 : (seg == 2) ? l2 : l3;
        float4 x = in[j];
        uint32_t a0, b0, a1, b1;
        cvt_hl2(x.x, x.y, a0, b0);
        cvt_hl2(x.z, x.w, a1, b1);
        hh[j] = make_uint2(a0, a1);
        ll[j] = make_uint2(b0, b1);
    }
}

// ================= 2-term fp16 HMMA GEMM (2-stage cp.async, proven) ============
#define GBK  32
#define NKT  (KDIM / GBK)     // 32
#define PADK 40               // fp16 pitch per row (80B)
#define T_A  0
#define T_WH 10240
#define T_WL 20480
#define STG_B 30720
#define GSMEM (2 * STG_B)     // 60 KB

__device__ __forceinline__ void gemm_body(
    const __half* __restrict__ Ah,
    const __half* __restrict__ Wh, const __half* __restrict__ Wl,
    float* __restrict__ Cf, __half* __restrict__ Ch, __half* __restrict__ Cl,
    int mode, int m0, int n0, char* smc)
{
    const uint32_t smb = smem_u32(smc);
    const int tid  = threadIdx.x;
    const int lane = tid & 31, wid = tid >> 5;
    const int wm = wid & 3;
    const int wn = wid >> 2;

    const int row0 = tid >> 2;
    const int ch   = tid & 3;

    float acc[2][8][4];
#pragma unroll
    for (int i = 0; i < 2; i++)
#pragma unroll
        for (int j = 0; j < 8; j++)
#pragma unroll
            for (int q = 0; q < 4; q++) acc[i][j][q] = 0.f;

    auto issue = [&](int kt) {
        if (kt < NKT) {
            const int k0 = kt * GBK;
            const uint32_t sb = smb + (kt & 1) * STG_B;
#pragma unroll
            for (int half = 0; half < 2; half++) {
                int r = row0 + half * 64;
                uint32_t doff = (uint32_t)(r * PADK + ch * 8) * 2;
                const size_t asrc = (size_t)(m0 + r) * KDIM + k0 + ch * 8;
                const size_t wsrc = (size_t)(n0 + r) * KDIM + k0 + ch * 8;
                CP_A16(sb + T_A  + doff, Ah + asrc);
                CP_A16(sb + T_WH + doff, Wh + wsrc);
                CP_A16(sb + T_WL + doff, Wl + wsrc);
            }
        }
        CP_COMMIT();
    };

    issue(0);
    issue(1);
    CP_WAIT1();
    __syncthreads();

    const int a_r = lane & 15;
    const int a_c = (lane >> 4) << 3;
    const int b_r = (lane & 7) + ((lane >> 4) << 3);
    const int b_c = ((lane >> 3) & 1) << 3;

    for (int kt = 0; kt < NKT; kt++) {
        const uint32_t sb = smb + (kt & 1) * STG_B;

#pragma unroll
        for (int ks = 0; ks < 2; ks++) {
            uint32_t af[2][4];
#pragma unroll
            for (int i = 0; i < 2; i++) {
                uint32_t off =
                    ((wm * 32 + i * 16 + a_r) * PADK + a_c + ks * 16) * 2;
                LDSM4(af[i], sb + T_A + off);
            }
#pragma unroll
            for (int p = 0; p < 4; p++) {
                uint32_t bh[4], bl[4];
                uint32_t off =
                    ((wn * 64 + p * 16 + b_r) * PADK + b_c + ks * 16) * 2;
                LDSM4(bh, sb + T_WH + off);
                LDSM4(bl, sb + T_WL + off);
#pragma unroll
                for (int i = 0; i < 2; i++)
#pragma unroll
                    for (int hf = 0; hf < 2; hf++) {
                        int j = p * 2 + hf;
                        MMA_F16(acc[i][j], af[i], bh[2*hf], bh[2*hf+1]);
                        MMA_F16(acc[i][j], af[i], bl[2*hf], bl[2*hf+1]);
                    }
            }
        }
        __syncthreads();
        issue(kt + 2);
        CP_WAIT1();
        __syncthreads();
    }

    // epilogue
#pragma unroll
    for (int i = 0; i < 2; i++) {
#pragma unroll
        for (int j = 0; j < 8; j++) {
            int mrow = m0 + wm * 32 + i * 16 + (lane >> 2);
            int ncol = n0 + wn * 64 + j * 8 + (lane & 3) * 2;
#pragma unroll
            for (int hf = 0; hf < 2; hf++) {
                int m = mrow + hf * 8;
                float v0 = acc[i][j][hf*2], v1 = acc[i][j][hf*2+1];
                if (mode == 0) {
                    *(float2*)(Cf + (size_t)m * NDIM + ncol) =
                        make_float2(v0, v1);
                } else {
                    int bb = m >> 11, s = m & 2047;
                    int hh = ncol >> 6, d = ncol & 63;
                    size_t off = ((size_t)(bb*NH + hh) * SEQ + s) * HD + d;
                    if (mode == 1) {
                        *(uint32_t*)(Ch + off) = cvt_h2(v0, v1);
                    } else {
                        uint32_t hp, lp;
                        cvt_hl2(v0, v1, hp, lp);
                        *(uint32_t*)(Ch + off) = hp;
                        *(uint32_t*)(Cl + off) = lp;
                    }
                }
            }
        }
    }
}

// merged Q/K/V projection: grid.y = 192 (seg = y/64: 0=Q, 1=K, 2=V)
__global__ void __launch_bounds__(256, 2)
gemm_qkv(const __half* __restrict__ xq, const __half* __restrict__ xk,
         const __half* __restrict__ xv,
         const __half* __restrict__ wqh, const __half* __restrict__ wql,
         const __half* __restrict__ wkh, const __half* __restrict__ wkl,
         const __half* __restrict__ wvh, const __half* __restrict__ wvl,
         __half* __restrict__ qh, __half* __restrict__ kh,
         __half* __restrict__ kl, __half* __restrict__ vh)
{
    extern __shared__ char smc[];
    const int seg = blockIdx.y >> 6;           // 0,1,2
    const int m0 = (blockIdx.y & 63) * 128;
    const int n0 = blockIdx.x * 128;
    const __half* Ah = (seg == 0) ? xq  : (seg == 1) ? xk  : xv;
    const __half* Wh = (seg == 0) ? wqh : (seg == 1) ? wkh : wvh;
    const __half* Wl = (seg == 0) ? wql : (seg == 1) ? wkl : wvl;
    __half* Ch = (seg == 0) ? qh : (seg == 1) ? kh : vh;
    __half* Cl = (seg == 1) ? kl : nullptr;
    const int mode = (seg == 1) ? 2 : 1;
    gemm_body(Ah, Wh, Wl, nullptr, Ch, Cl, mode, m0, n0, smc);
}

// output projection (fp32 out)
__global__ void __launch_bounds__(256, 2)
gemm_out(const __half* __restrict__ Ah,
         const __half* __restrict__ Wh, const __half* __restrict__ Wl,
         float* __restrict__ Cf)
{
    extern __shared__ char smc[];
    gemm_body(Ah, Wh, Wl, Cf, nullptr, nullptr, 0,
              blockIdx.y * 128, blockIdx.x * 128, smc);
}

// ================= fp16 HMMA fused attention (KTILE=128, interleaved S/O) ======
// S = Qh*(Kh+Kl) ; T = relu(S/8+b)^2 split (Th+Tl) ; O += (Th+Tl)*Vh
#define KTILE 128
#define NCT   (KTILE / 16)            // 8
#define APCH  72
#define A_Q   0
#define A_KH  (A_Q  + 128 * APCH * 2)   // 18432
#define A_KL  (A_KH + KTILE * APCH * 2) // 36864
#define A_VH  (A_KL + KTILE * APCH * 2) // 55296
#define A_MS  (A_VH + KTILE * APCH * 2) // 73728 (128 rows x 16B bit-mask)
#define A_BYTES (A_MS + 128 * 16)       // 75776

__global__ void __launch_bounds__(256, 2)
attn_f16(const __half* __restrict__ qh,
         const __half* __restrict__ kh, const __half* __restrict__ kl,
         const __half* __restrict__ vh,
         const uint32_t* __restrict__ maskb,
         const float* __restrict__ sn_bias,
         __half* __restrict__ oh)
{
    extern __shared__ char sm[];
    const uint32_t smb = smem_u32(sm);
    const int tid  = threadIdx.x;
    const int lane = tid & 31, wid = tid >> 5;
    const int bh = blockIdx.y;
    const int b = bh >> 4, h = bh & 15;
    const int q0g = blockIdx.x * 128;
    const float bias = sn_bias[0];

    // stage Q tile [128 x 64] fp16
    {
        const size_t qbase = ((size_t)bh * SEQ + q0g) * HD;
#pragma unroll
        for (int i = 0; i < 4; i++) {
            int lin = tid + i * 256;        // 0..1023
            int row = lin >> 3, c = lin & 7;
            *(uint4*)(sm + A_Q + (uint32_t)(row * APCH + c * 8) * 2) =
                *(const uint4*)(qh + qbase + (size_t)row * HD + c * 8);
        }
    }
    __syncthreads();

    const int a_r = lane & 15;
    const int a_c = (lane >> 4) << 3;
    const int b_r = (lane & 7) + ((lane >> 4) << 3);
    const int b_c = ((lane >> 3) & 1) << 3;
    const int v_r = ((lane >> 3) & 1) * 8 + (lane & 7);
    const int v_c = (lane >> 4) << 3;
    const int mrow0 = wid * 16 + (lane >> 2);
    const int shl = 2 * (lane & 3);

    // hoist Q fragments for the whole K loop
    uint32_t qf[4][4];
#pragma unroll
    for (int dc = 0; dc < 4; dc++)
        LDSM4(qf[dc], smb + A_Q + ((wid * 16 + a_r) * APCH + dc * 16 + a_c) * 2);

    float oacc[8][4];
#pragma unroll
    for (int j = 0; j < 8; j++)
#pragma unroll
        for (int e = 0; e < 4; e++) oacc[j][e] = 0.f;
    float rsum0 = 0.f, rsum1 = 0.f;

    const size_t kvbase = (size_t)bh * SEQ * HD;
    // bit-packed mask: per q-row SEQ/32 = 64 words = 16 uint4; tile kt = uint4 #kt
    const uint4* mrow_base =
        (const uint4*)(maskb + ((size_t)b * SEQ + q0g) * (SEQ / 32));

    for (int kt = 0; kt < SEQ / KTILE; kt++) {
        __syncthreads();
        // stage K hi/lo, V (128x64) + bit-mask (128 rows x 16B)
        {
            const size_t tb = kvbase + (size_t)kt * KTILE * HD;
#pragma unroll
            for (int i = 0; i < 4; i++) {
                int lin = tid + i * 256;    // 0..1023
                int row = lin >> 3, c = lin & 7;
                size_t off = tb + (size_t)row * HD + c * 8;
                uint32_t doff = (uint32_t)(row * APCH + c * 8) * 2;
                *(uint4*)(sm + A_KH + doff) = *(const uint4*)(kh + off);
                *(uint4*)(sm + A_KL + doff) = *(const uint4*)(kl + off);
                *(uint4*)(sm + A_VH + doff) = *(const uint4*)(vh + off);
            }
            // row r's 64 words = 16 uint4; tile kt (128 bits) = uint4 index r*16+kt
            if (tid < 128)
                *(uint4*)(sm + A_MS + tid * 16) = mrow_base[(size_t)tid * 16 + kt];
        }
        __syncthreads();

        // per-thread mask words for this tile (2 q-rows x 128 k-bits)
        const uint4 mw0 = *(const uint4*)(sm + A_MS + mrow0 * 16);
        const uint4 mw1 = *(const uint4*)(sm + A_MS + (mrow0 + 8) * 16);

        // ---- interleaved S chunk -> T -> O chunk, per 16 k-rows -------------
#pragma unroll
        for (int nc = 0; nc < NCT; nc++) {
            float sc[2][4];
#pragma unroll
            for (int hf = 0; hf < 2; hf++)
#pragma unroll
                for (int e = 0; e < 4; e++) sc[hf][e] = 0.f;

#pragma unroll
            for (int dc = 0; dc < 4; dc++) {
                uint32_t khf[4], klf[4];
                uint32_t ka = smb + A_KH +
                    ((nc * 16 + b_r) * APCH + dc * 16 + b_c) * 2;
                LDSM4(khf, ka);
                LDSM4(klf, ka + (A_KL - A_KH));
#pragma unroll
                for (int hf = 0; hf < 2; hf++) {
                    MMA_F16(sc[hf], qf[dc], khf[2*hf], khf[2*hf+1]);
                    MMA_F16(sc[hf], qf[dc], klf[2*hf], klf[2*hf+1]);
                }
            }

            // mask + bias + relu^2, rowsum, split T to hi/lo fp16 fragments
            uint32_t aph[4], apl[4];
#pragma unroll
            for (int hf = 0; hf < 2; hf++) {
                const int base = nc * 16 + hf * 8;       // 0..120, const
                const uint32_t w0 = u4sel(mw0, base >> 5);
                const uint32_t w1 = u4sel(mw1, base >> 5);
                const int sh = (base & 31) + shl;
                float t0 = fmaxf(fmaf(sc[hf][0], 0.125f, bias), 0.f);
                float t1 = fmaxf(fmaf(sc[hf][1], 0.125f, bias), 0.f);
                float t2 = fmaxf(fmaf(sc[hf][2], 0.125f, bias), 0.f);
                float t3 = fmaxf(fmaf(sc[hf][3], 0.125f, bias), 0.f);
                if ((w0 >> sh) & 1u)       t0 = 0.f;
                if ((w0 >> (sh + 1)) & 1u) t1 = 0.f;
                if ((w1 >> sh) & 1u)       t2 = 0.f;
                if ((w1 >> (sh + 1)) & 1u) t3 = 0.f;
                t0 *= t0; t1 *= t1; t2 *= t2; t3 *= t3;
                rsum0 += t0 + t1;
                rsum1 += t2 + t3;
                uint32_t hp, lp;
                cvt_hl2(t0, t1, hp, lp);
                aph[2*hf + 0] = hp;
                apl[2*hf + 0] = lp;
                cvt_hl2(t2, t3, hp, lp);
                aph[2*hf + 1] = hp;
                apl[2*hf + 1] = lp;
            }

            // O += T * V for this k-chunk (V via ldmatrix.trans)
#pragma unroll
            for (int dch = 0; dch < 4; dch++) {
                uint32_t vf[4];
                LDSM4T(vf, smb + A_VH +
                           ((nc * 16 + v_r) * APCH + dch * 16 + v_c) * 2);
#pragma unroll
                for (int hf = 0; hf < 2; hf++) {
                    int j = dch * 2 + hf;
                    MMA_F16(oacc[j], aph, vf[2*hf], vf[2*hf+1]);
                    MMA_F16(oacc[j], apl, vf[2*hf], vf[2*hf+1]);
                }
            }
        }
    }

    rsum0 += __shfl_xor_sync(0xffffffffu, rsum0, 1);
    rsum0 += __shfl_xor_sync(0xffffffffu, rsum0, 2);
    rsum1 += __shfl_xor_sync(0xffffffffu, rsum1, 1);
    rsum1 += __shfl_xor_sync(0xffffffffu, rsum1, 2);
    const float inv0 = 1.f / (rsum0 + 1e-32f);
    const float inv1 = 1.f / (rsum1 + 1e-32f);

    // store O (fp16) into [B, NQ, HSIZE] layout
    const int qr0 = q0g + mrow0;
#pragma unroll
    for (int j = 0; j < 8; j++) {
        int d = h * HD + j * 8 + 2 * (lane & 3);
        *(uint32_t*)(oh + (size_t)(b * SEQ + qr0) * NDIM + d) =
            cvt_h2(oacc[j][0] * inv0, oacc[j][1] * inv0);
        *(uint32_t*)(oh + (size_t)(b * SEQ + qr0 + 8) * NDIM + d) =
            cvt_h2(oacc[j][2] * inv1, oacc[j][3] * inv1);
    }
}

// ---------------- launcher ----------------------------------------------------
extern "C" void kernel_launch(void* const* d_in, const int* in_sizes, int n_in,
                              void* d_out, int out_size)
{
    const float* iQ      = (const float*)d_in[0];
    const float* iK      = (const float*)d_in[1];
    const float* iV      = (const float*)d_in[2];
    const void*  mask    = d_in[3];
    const float* Wq      = (const float*)d_in[4];
    const float* Wk      = (const float*)d_in[5];
    const float* Wv      = (const float*)d_in[6];
    const float* Wo      = (const float*)d_in[7];
    const float* sn_bias = (const float*)d_in[8];
    float*       out     = (float*)d_out;

    __half *xq, *xk, *xv, *ohb, *wqh, *wql, *wkh, *wkl, *wvh, *wvl, *woh, *wol;
    __half *qh, *kh, *kl, *vh;
    uint32_t* gmb;
    cudaGetSymbolAddress((void**)&xq, g_xq);
    cudaGetSymbolAddress((void**)&xk, g_xk);
    cudaGetSymbolAddress((void**)&xv, g_xv);
    cudaGetSymbolAddress((void**)&ohb, g_oh);
    cudaGetSymbolAddress((void**)&wqh, g_wqh);
    cudaGetSymbolAddress((void**)&wql, g_wql);
    cudaGetSymbolAddress((void**)&wkh, g_wkh);
    cudaGetSymbolAddress((void**)&wkl, g_wkl);
    cudaGetSymbolAddress((void**)&wvh, g_wvh);
    cudaGetSymbolAddress((void**)&wvl, g_wvl);
    cudaGetSymbolAddress((void**)&woh, g_woh);
    cudaGetSymbolAddress((void**)&wol, g_wol);
    cudaGetSymbolAddress((void**)&qh, g_qh);
    cudaGetSymbolAddress((void**)&kh, g_kh);
    cudaGetSymbolAddress((void**)&kl, g_kl);
    cudaGetSymbolAddress((void**)&vh, g_vh);
    cudaGetSymbolAddress((void**)&gmb, g_maskb);

    cudaFuncSetAttribute(gemm_qkv,
                         cudaFuncAttributeMaxDynamicSharedMemorySize, GSMEM);
    cudaFuncSetAttribute(gemm_out,
                         cudaFuncAttributeMaxDynamicSharedMemorySize, GSMEM);
    cudaFuncSetAttribute(attn_f16,
                         cudaFuncAttributeMaxDynamicSharedMemorySize, A_BYTES);

    // mask dtype autodetect + bit-pack
    detect_mask_kernel<<<1, 256>>>((const unsigned int*)mask);
    convert_maskb<<<2048, 256>>>(mask, gmb);

    const size_t nA4 = (size_t)MDIM * KDIM / 4;
    const size_t nW4 = (size_t)NDIM * KDIM / 4;

    // merged converts (2 launches)
    convert_h3<<<4096, 256>>>((const float4*)iQ, (const float4*)iK,
                              (const float4*)iV,
                              (uint2*)xq, (uint2*)xk, (uint2*)xv, nA4);
    convert_hl4<<<2048, 256>>>((const float4*)Wq, (const float4*)Wk,
                               (const float4*)Wv, (const float4*)Wo,
                               (uint2*)wqh, (uint2*)wql, (uint2*)wkh, (uint2*)wkl,
                               (uint2*)wvh, (uint2*)wvl, (uint2*)woh, (uint2*)wol,
                               nW4);

    // merged Q/K/V projections: one launch, 1536 CTAs
    gemm_qkv<<<dim3(NDIM / 128, 192), 256, GSMEM>>>(
        xq, xk, xv, wqh, wql, wkh, wkl, wvh, wvl, qh, kh, kl, vh);

    attn_f16<<<dim3(SEQ / 128, NB * NH), 256, A_BYTES>>>(
        qh, kh, kl, vh, gmb, sn_bias, ohb);

    gemm_out<<<dim3(NDIM / 128, MDIM / 128), 256, GSMEM>>>(ohb, woh, wol, out);
}

// round 13
// speedup vs baseline: 1.1357x; 1.0147x over previous
#include <cuda_runtime.h>
#include <cuda_fp16.h>
#include <cstdint>
#include <cstddef>

// Problem constants
#define SEQ   2048
#define NB    4
#define NH    16
#define HD    64
#define MDIM  8192     // NB*SEQ
#define NDIM  1024
#define KDIM  1024

// ---------------- scratch (static device globals: allocation-free) -------------
__device__ __half g_xq[(size_t)MDIM * KDIM];
__device__ __half g_xk[(size_t)MDIM * KDIM];
__device__ __half g_xv[(size_t)MDIM * KDIM];
__device__ __half g_oh[(size_t)MDIM * NDIM];
__device__ __half g_wqh[(size_t)NDIM * KDIM];
__device__ __half g_wql[(size_t)NDIM * KDIM];
__device__ __half g_wkh[(size_t)NDIM * KDIM];
__device__ __half g_wkl[(size_t)NDIM * KDIM];
__device__ __half g_wvh[(size_t)NDIM * KDIM];
__device__ __half g_wvl[(size_t)NDIM * KDIM];
__device__ __half g_woh[(size_t)NDIM * KDIM];
__device__ __half g_wol[(size_t)NDIM * KDIM];
__device__ __half g_qh[(size_t)NB * NH * SEQ * HD];   // Q (single fp16)
__device__ __half g_kh[(size_t)NB * NH * SEQ * HD];   // K hi
__device__ __half g_kl[(size_t)NB * NH * SEQ * HD];   // K lo
__device__ __half g_vh[(size_t)NB * NH * SEQ * HD];   // V (single fp16)
__device__ uint32_t g_maskb[(size_t)NB * SEQ * SEQ / 32];  // bit-packed mask
__device__ int g_mode;                              // 0=u8, 1=i32, 2=f32

// ================= helpers =====================================================
__device__ __forceinline__ uint32_t smem_u32(const void* p) {
    uint32_t a;
    asm("{ .reg .u64 t; cvta.to.shared.u64 t, %1; cvt.u32.u64 %0, t; }"
        : "=r"(a) : "l"(p));
    return a;
}

__device__ __forceinline__ uint32_t pack_h2(__half a, __half b) {
    __half2 t;
    t.x = a; t.y = b;
    return *(uint32_t*)&t;
}

__device__ __forceinline__ uint32_t cvt_h2(float x0, float x1) {
    return pack_h2(__float2half_rn(x0), __float2half_rn(x1));
}

__device__ __forceinline__ void cvt_hl2(float x0, float x1,
                                        uint32_t& hp, uint32_t& lp) {
    __half h0 = __float2half_rn(x0), h1 = __float2half_rn(x1);
    hp = pack_h2(h0, h1);
    lp = pack_h2(__float2half_rn(x0 - __half2float(h0)),
                 __float2half_rn(x1 - __half2float(h1)));
}

__device__ __forceinline__ uint32_t u4sel(const uint4& v, int i) {
    return (i == 0) ? v.x : (i == 1) ? v.y : (i == 2) ? v.z : v.w;
}

#define LDSM4(r, a) \
    asm volatile("ldmatrix.sync.aligned.m8n8.x4.shared.b16 {%0,%1,%2,%3}, [%4];" \
        : "=r"((r)[0]), "=r"((r)[1]), "=r"((r)[2]), "=r"((r)[3]) : "r"(a))

#define LDSM4T(r, a) \
    asm volatile("ldmatrix.sync.aligned.m8n8.x4.trans.shared.b16 {%0,%1,%2,%3}, [%4];" \
        : "=r"((r)[0]), "=r"((r)[1]), "=r"((r)[2]), "=r"((r)[3]) : "r"(a))

#define MMA_F16(c, a, b0, b1) \
    asm volatile("mma.sync.aligned.m16n8k16.row.col.f32.f16.f16.f32 " \
        "{%0,%1,%2,%3}, {%4,%5,%6,%7}, {%8,%9}, {%0,%1,%2,%3};" \
        : "+f"((c)[0]), "+f"((c)[1]), "+f"((c)[2]), "+f"((c)[3]) \
        : "r"((a)[0]), "r"((a)[1]), "r"((a)[2]), "r"((a)[3]), "r"(b0), "r"(b1))

#define CP_A16(dst, src) \
    asm volatile("cp.async.cg.shared.global [%0], [%1], 16;" :: "r"(dst), "l"(src))
#define CP_COMMIT() asm volatile("cp.async.commit_group;" ::: "memory")
#define CP_WAIT1()  asm volatile("cp.async.wait_group 1;" ::: "memory")

// ---------------- mask dtype detection + bit-pack conversion -------------------
__global__ void detect_mask_kernel(const unsigned int* __restrict__ w)
{
    __shared__ int s_not_i32, s_not_u8;
    if (threadIdx.x == 0) { s_not_i32 = 0; s_not_u8 = 0; }
    __syncthreads();
    int not_i32 = 0, not_u8 = 0;
    for (int i = threadIdx.x; i < 65536; i += 256) {
        unsigned v = w[i];
        unsigned b0 = v & 255u, b1 = (v >> 8) & 255u,
                 b2 = (v >> 16) & 255u, b3 = v >> 24;
        if ((b1 | b2 | b3) != 0u || b0 > 1u) not_i32 = 1;
        if (b0 > 1u || b1 > 1u || b2 > 1u || b3 > 1u) not_u8 = 1;
    }
    if (not_i32) atomicOr(&s_not_i32, 1);
    if (not_u8)  atomicOr(&s_not_u8, 1);
    __syncthreads();
    if (threadIdx.x == 0)
        g_mode = (!s_not_i32) ? 1 : ((!s_not_u8) ? 0 : 2);
}

// build bit-packed mask: word w holds elements [32w, 32w+32), bit set = masked
__global__ void convert_maskb(const void* __restrict__ m, uint32_t* __restrict__ o)
{
    const int mode = g_mode;
    const size_t nw = (size_t)NB * SEQ * SEQ / 32;
    for (size_t w = (size_t)blockIdx.x * blockDim.x + threadIdx.x; w < nw;
         w += (size_t)gridDim.x * blockDim.x) {
        uint32_t bits = 0;
        if (mode == 1) {
            const uint4* p = (const uint4*)((const int*)m + w * 32);
#pragma unroll
            for (int g = 0; g < 8; g++) {
                uint4 v = p[g];
                bits |= (v.x ? 1u : 0u) << (g * 4 + 0);
                bits |= (v.y ? 1u : 0u) << (g * 4 + 1);
                bits |= (v.z ? 1u : 0u) << (g * 4 + 2);
                bits |= (v.w ? 1u : 0u) << (g * 4 + 3);
            }
        } else if (mode == 2) {
            const float4* p = (const float4*)((const float*)m + w * 32);
#pragma unroll
            for (int g = 0; g < 8; g++) {
                float4 v = p[g];
                bits |= (v.x != 0.f ? 1u : 0u) << (g * 4 + 0);
                bits |= (v.y != 0.f ? 1u : 0u) << (g * 4 + 1);
                bits |= (v.z != 0.f ? 1u : 0u) << (g * 4 + 2);
                bits |= (v.w != 0.f ? 1u : 0u) << (g * 4 + 3);
            }
        } else {
            const uint4* p = (const uint4*)((const unsigned char*)m + w * 32);
#pragma unroll
            for (int g = 0; g < 2; g++) {
                uint4 v = p[g];
                uint32_t ws[4] = {v.x, v.y, v.z, v.w};
#pragma unroll
                for (int q = 0; q < 4; q++)
#pragma unroll
                    for (int e = 0; e < 4; e++)
                        bits |= (((ws[q] >> (e * 8)) & 255u) ? 1u : 0u)
                                << (g * 16 + q * 4 + e);
            }
        }
        o[w] = bits;
    }
}

// ---------------- merged fp32 -> fp16 streaming converters ---------------------
__global__ void convert_h3(const float4* __restrict__ i0,
                           const float4* __restrict__ i1,
                           const float4* __restrict__ i2,
                           uint2* __restrict__ o0, uint2* __restrict__ o1,
                           uint2* __restrict__ o2, size_t n4)
{
    for (size_t i = (size_t)blockIdx.x * blockDim.x + threadIdx.x; i < 3 * n4;
         i += (size_t)gridDim.x * blockDim.x) {
        const float4* in = (i < n4) ? i0 : (i < 2 * n4) ? i1 : i2;
        uint2* out = (i < n4) ? o0 : (i < 2 * n4) ? o1 : o2;
        size_t j = (i < n4) ? i : (i < 2 * n4) ? i - n4 : i - 2 * n4;
        float4 x = in[j];
        out[j] = make_uint2(cvt_h2(x.x, x.y), cvt_h2(x.z, x.w));
    }
}

__global__ void convert_hl4(const float4* __restrict__ i0, const float4* __restrict__ i1,
                            const float4* __restrict__ i2, const float4* __restrict__ i3,
                            uint2* __restrict__ h0, uint2* __restrict__ l0,
                            uint2* __restrict__ h1, uint2* __restrict__ l1,
                            uint2* __restrict__ h2, uint2* __restrict__ l2,
                            uint2* __restrict__ h3, uint2* __restrict__ l3,
                            size_t n4)
{
    for (size_t i = (size_t)blockIdx.x * blockDim.x + threadIdx.x; i < 4 * n4;
         i += (size_t)gridDim.x * blockDim.x) {
        int seg = (int)(i / n4);
        size_t j = i - (size_t)seg * n4;
        const float4* in = (seg == 0) ? i0 : (seg == 1) ? i1 : (seg == 2) ? i2 : i3;
        uint2* hh = (seg == 0) ? h0 : (seg == 1) ? h1 : (seg == 2) ? h2 : h3;
        uint2* ll = (seg == 0) ? l0 : (seg == 1) ? l1 : (seg == 2) ? l2 : l3;
        float4 x = in[j];
        uint32_t a0, b0, a1, b1;
        cvt_hl2(x.x, x.y, a0, b0);
        cvt_hl2(x.z, x.w, a1, b1);
        hh[j] = make_uint2(a0, a1);
        ll[j] = make_uint2(b0, b1);
    }
}

// ================= 2-term fp16 HMMA GEMM (GBK=64, 2-stage cp.async) ============
#define GBK  64
#define NKT  (KDIM / GBK)     // 16
#define PADK 72               // fp16 pitch per row (144B, LDSM conflict-free)
#define T_A  0
#define T_WH 18432
#define T_WL 36864
#define STG_B 55296
#define GSMEM (2 * STG_B)     // 108 KB (x2 CTAs = 216 KB <= 228 KB/SM)

__device__ __forceinline__ void gemm_body(
    const __half* __restrict__ Ah,
    const __half* __restrict__ Wh, const __half* __restrict__ Wl,
    float* __restrict__ Cf, __half* __restrict__ Ch, __half* __restrict__ Cl,
    int mode, int m0, int n0, char* smc)
{
    const uint32_t smb = smem_u32(smc);
    const int tid  = threadIdx.x;
    const int lane = tid & 31, wid = tid >> 5;
    const int wm = wid & 3;
    const int wn = wid >> 2;

    const int row0 = tid >> 3;     // 0..31
    const int ch   = tid & 7;      // 16B chunk (8 fp16) within 64-col stage

    float acc[2][8][4];
#pragma unroll
    for (int i = 0; i < 2; i++)
#pragma unroll
        for (int j = 0; j < 8; j++)
#pragma unroll
            for (int q = 0; q < 4; q++) acc[i][j][q] = 0.f;

    auto issue = [&](int kt) {
        if (kt < NKT) {
            const int k0 = kt * GBK;
            const uint32_t sb = smb + (kt & 1) * STG_B;
#pragma unroll
            for (int g = 0; g < 4; g++) {
                int r = row0 + g * 32;
                uint32_t doff = (uint32_t)(r * PADK + ch * 8) * 2;
                const size_t asrc = (size_t)(m0 + r) * KDIM + k0 + ch * 8;
                const size_t wsrc = (size_t)(n0 + r) * KDIM + k0 + ch * 8;
                CP_A16(sb + T_A  + doff, Ah + asrc);
                CP_A16(sb + T_WH + doff, Wh + wsrc);
                CP_A16(sb + T_WL + doff, Wl + wsrc);
            }
        }
        CP_COMMIT();
    };

    issue(0);
    issue(1);
    CP_WAIT1();
    __syncthreads();

    const int a_r = lane & 15;
    const int a_c = (lane >> 4) << 3;
    const int b_r = (lane & 7) + ((lane >> 4) << 3);
    const int b_c = ((lane >> 3) & 1) << 3;

    for (int kt = 0; kt < NKT; kt++) {
        const uint32_t sb = smb + (kt & 1) * STG_B;

#pragma unroll
        for (int ks = 0; ks < 4; ks++) {
            uint32_t af[2][4];
#pragma unroll
            for (int i = 0; i < 2; i++) {
                uint32_t off =
                    ((wm * 32 + i * 16 + a_r) * PADK + a_c + ks * 16) * 2;
                LDSM4(af[i], sb + T_A + off);
            }
#pragma unroll
            for (int p = 0; p < 4; p++) {
                uint32_t bh[4], bl[4];
                uint32_t off =
                    ((wn * 64 + p * 16 + b_r) * PADK + b_c + ks * 16) * 2;
                LDSM4(bh, sb + T_WH + off);
                LDSM4(bl, sb + T_WL + off);
#pragma unroll
                for (int i = 0; i < 2; i++)
#pragma unroll
                    for (int hf = 0; hf < 2; hf++) {
                        int j = p * 2 + hf;
                        MMA_F16(acc[i][j], af[i], bh[2*hf], bh[2*hf+1]);
                        MMA_F16(acc[i][j], af[i], bl[2*hf], bl[2*hf+1]);
                    }
            }
        }
        __syncthreads();
        issue(kt + 2);
        CP_WAIT1();
        __syncthreads();
    }

    // epilogue
#pragma unroll
    for (int i = 0; i < 2; i++) {
#pragma unroll
        for (int j = 0; j < 8; j++) {
            int mrow = m0 + wm * 32 + i * 16 + (lane >> 2);
            int ncol = n0 + wn * 64 + j * 8 + (lane & 3) * 2;
#pragma unroll
            for (int hf = 0; hf < 2; hf++) {
                int m = mrow + hf * 8;
                float v0 = acc[i][j][hf*2], v1 = acc[i][j][hf*2+1];
                if (mode == 0) {
                    *(float2*)(Cf + (size_t)m * NDIM + ncol) =
                        make_float2(v0, v1);
                } else {
                    int bb = m >> 11, s = m & 2047;
                    int hh = ncol >> 6, d = ncol & 63;
                    size_t off = ((size_t)(bb*NH + hh) * SEQ + s) * HD + d;
                    if (mode == 1) {
                        *(uint32_t*)(Ch + off) = cvt_h2(v0, v1);
                    } else {
                        uint32_t hp, lp;
                        cvt_hl2(v0, v1, hp, lp);
                        *(uint32_t*)(Ch + off) = hp;
                        *(uint32_t*)(Cl + off) = lp;
                    }
                }
            }
        }
    }
}

// merged Q/K/V projection: grid.y = 192 (seg = y/64: 0=Q, 1=K, 2=V)
__global__ void __launch_bounds__(256, 2)
gemm_qkv(const __half* __restrict__ xq, const __half* __restrict__ xk,
         const __half* __restrict__ xv,
         const __half* __restrict__ wqh, const __half* __restrict__ wql,
         const __half* __restrict__ wkh, const __half* __restrict__ wkl,
         const __half* __restrict__ wvh, const __half* __restrict__ wvl,
         __half* __restrict__ qh, __half* __restrict__ kh,
         __half* __restrict__ kl, __half* __restrict__ vh)
{
    extern __shared__ char smc[];
    const int seg = blockIdx.y >> 6;           // 0,1,2
    const int m0 = (blockIdx.y & 63) * 128;
    const int n0 = blockIdx.x * 128;
    const __half* Ah = (seg == 0) ? xq  : (seg == 1) ? xk  : xv;
    const __half* Wh = (seg == 0) ? wqh : (seg == 1) ? wkh : wvh;
    const __half* Wl = (seg == 0) ? wql : (seg == 1) ? wkl : wvl;
    __half* Ch = (seg == 0) ? qh : (seg == 1) ? kh : vh;
    __half* Cl = (seg == 1) ? kl : nullptr;
    const int mode = (seg == 1) ? 2 : 1;
    gemm_body(Ah, Wh, Wl, nullptr, Ch, Cl, mode, m0, n0, smc);
}

// output projection (fp32 out)
__global__ void __launch_bounds__(256, 2)
gemm_out(const __half* __restrict__ Ah,
         const __half* __restrict__ Wh, const __half* __restrict__ Wl,
         float* __restrict__ Cf)
{
    extern __shared__ char smc[];
    gemm_body(Ah, Wh, Wl, Cf, nullptr, nullptr, 0,
              blockIdx.y * 128, blockIdx.x * 128, smc);
}

// ================= fp16 HMMA fused attention (KTILE=128, interleaved S/O) ======
// S = Qh*(Kh+Kl) ; T = relu(S/8+b)^2 split (Th+Tl) ; O += (Th+Tl)*Vh
#define KTILE 128
#define NCT   (KTILE / 16)            // 8
#define APCH  72
#define A_Q   0
#define A_KH  (A_Q  + 128 * APCH * 2)   // 18432
#define A_KL  (A_KH + KTILE * APCH * 2) // 36864
#define A_VH  (A_KL + KTILE * APCH * 2) // 55296
#define A_MS  (A_VH + KTILE * APCH * 2) // 73728 (128 rows x 16B bit-mask)
#define A_BYTES (A_MS + 128 * 16)       // 75776

__global__ void __launch_bounds__(256, 2)
attn_f16(const __half* __restrict__ qh,
         const __half* __restrict__ kh, const __half* __restrict__ kl,
         const __half* __restrict__ vh,
         const uint32_t* __restrict__ maskb,
         const float* __restrict__ sn_bias,
         __half* __restrict__ oh)
{
    extern __shared__ char sm[];
    const uint32_t smb = smem_u32(sm);
    const int tid  = threadIdx.x;
    const int lane = tid & 31, wid = tid >> 5;
    const int bh = blockIdx.y;
    const int b = bh >> 4, h = bh & 15;
    const int q0g = blockIdx.x * 128;
    const float bias = sn_bias[0];

    // stage Q tile [128 x 64] fp16
    {
        const size_t qbase = ((size_t)bh * SEQ + q0g) * HD;
#pragma unroll
        for (int i = 0; i < 4; i++) {
            int lin = tid + i * 256;        // 0..1023
            int row = lin >> 3, c = lin & 7;
            *(uint4*)(sm + A_Q + (uint32_t)(row * APCH + c * 8) * 2) =
                *(const uint4*)(qh + qbase + (size_t)row * HD + c * 8);
        }
    }
    __syncthreads();

    const int a_r = lane & 15;
    const int a_c = (lane >> 4) << 3;
    const int b_r = (lane & 7) + ((lane >> 4) << 3);
    const int b_c = ((lane >> 3) & 1) << 3;
    const int v_r = ((lane >> 3) & 1) * 8 + (lane & 7);
    const int v_c = (lane >> 4) << 3;
    const int mrow0 = wid * 16 + (lane >> 2);
    const int shl = 2 * (lane & 3);

    // hoist Q fragments for the whole K loop
    uint32_t qf[4][4];
#pragma unroll
    for (int dc = 0; dc < 4; dc++)
        LDSM4(qf[dc], smb + A_Q + ((wid * 16 + a_r) * APCH + dc * 16 + a_c) * 2);

    float oacc[8][4];
#pragma unroll
    for (int j = 0; j < 8; j++)
#pragma unroll
        for (int e = 0; e < 4; e++) oacc[j][e] = 0.f;
    float rsum0 = 0.f, rsum1 = 0.f;

    const size_t kvbase = (size_t)bh * SEQ * HD;
    // bit-packed mask: per q-row SEQ/32 = 64 words = 16 uint4; tile kt = uint4 #kt
    const uint4* mrow_base =
        (const uint4*)(maskb + ((size_t)b * SEQ + q0g) * (SEQ / 32));

    for (int kt = 0; kt < SEQ / KTILE; kt++) {
        __syncthreads();
        // stage K hi/lo, V (128x64) + bit-mask (128 rows x 16B)
        {
            const size_t tb = kvbase + (size_t)kt * KTILE * HD;
#pragma unroll
            for (int i = 0; i < 4; i++) {
                int lin = tid + i * 256;    // 0..1023
                int row = lin >> 3, c = lin & 7;
                size_t off = tb + (size_t)row * HD + c * 8;
                uint32_t doff = (uint32_t)(row * APCH + c * 8) * 2;
                *(uint4*)(sm + A_KH + doff) = *(const uint4*)(kh + off);
                *(uint4*)(sm + A_KL + doff) = *(const uint4*)(kl + off);
                *(uint4*)(sm + A_VH + doff) = *(const uint4*)(vh + off);
            }
            // row r's 64 words = 16 uint4; tile kt (128 bits) = uint4 index r*16+kt
            if (tid < 128)
                *(uint4*)(sm + A_MS + tid * 16) = mrow_base[(size_t)tid * 16 + kt];
        }
        __syncthreads();

        // per-thread mask words for this tile (2 q-rows x 128 k-bits)
        const uint4 mw0 = *(const uint4*)(sm + A_MS + mrow0 * 16);
        const uint4 mw1 = *(const uint4*)(sm + A_MS + (mrow0 + 8) * 16);

        // ---- interleaved S chunk -> T -> O chunk, per 16 k-rows -------------
#pragma unroll
        for (int nc = 0; nc < NCT; nc++) {
            float sc[2][4];
#pragma unroll
            for (int hf = 0; hf < 2; hf++)
#pragma unroll
                for (int e = 0; e < 4; e++) sc[hf][e] = 0.f;

#pragma unroll
            for (int dc = 0; dc < 4; dc++) {
                uint32_t khf[4], klf[4];
                uint32_t ka = smb + A_KH +
                    ((nc * 16 + b_r) * APCH + dc * 16 + b_c) * 2;
                LDSM4(khf, ka);
                LDSM4(klf, ka + (A_KL - A_KH));
#pragma unroll
                for (int hf = 0; hf < 2; hf++) {
                    MMA_F16(sc[hf], qf[dc], khf[2*hf], khf[2*hf+1]);
                    MMA_F16(sc[hf], qf[dc], klf[2*hf], klf[2*hf+1]);
                }
            }

            // mask + bias + relu^2, rowsum, split T to hi/lo fp16 fragments
            uint32_t aph[4], apl[4];
#pragma unroll
            for (int hf = 0; hf < 2; hf++) {
                const int base = nc * 16 + hf * 8;       // 0..120, const
                const uint32_t w0 = u4sel(mw0, base >> 5);
                const uint32_t w1 = u4sel(mw1, base >> 5);
                const int sh = (base & 31) + shl;
                float t0 = fmaxf(fmaf(sc[hf][0], 0.125f, bias), 0.f);
                float t1 = fmaxf(fmaf(sc[hf][1], 0.125f, bias), 0.f);
                float t2 = fmaxf(fmaf(sc[hf][2], 0.125f, bias), 0.f);
                float t3 = fmaxf(fmaf(sc[hf][3], 0.125f, bias), 0.f);
                if ((w0 >> sh) & 1u)       t0 = 0.f;
                if ((w0 >> (sh + 1)) & 1u) t1 = 0.f;
                if ((w1 >> sh) & 1u)       t2 = 0.f;
                if ((w1 >> (sh + 1)) & 1u) t3 = 0.f;
                t0 *= t0; t1 *= t1; t2 *= t2; t3 *= t3;
                rsum0 += t0 + t1;
                rsum1 += t2 + t3;
                uint32_t hp, lp;
                cvt_hl2(t0, t1, hp, lp);
                aph[2*hf + 0] = hp;
                apl[2*hf + 0] = lp;
                cvt_hl2(t2, t3, hp, lp);
                aph[2*hf + 1] = hp;
                apl[2*hf + 1] = lp;
            }

            // O += T * V for this k-chunk (V via ldmatrix.trans)
#pragma unroll
            for (int dch = 0; dch < 4; dch++) {
                uint32_t vf[4];
                LDSM4T(vf, smb + A_VH +
                           ((nc * 16 + v_r) * APCH + dch * 16 + v_c) * 2);
#pragma unroll
                for (int hf = 0; hf < 2; hf++) {
                    int j = dch * 2 + hf;
                    MMA_F16(oacc[j], aph, vf[2*hf], vf[2*hf+1]);
                    MMA_F16(oacc[j], apl, vf[2*hf], vf[2*hf+1]);
                }
            }
        }
    }

    rsum0 += __shfl_xor_sync(0xffffffffu, rsum0, 1);
    rsum0 += __shfl_xor_sync(0xffffffffu, rsum0, 2);
    rsum1 += __shfl_xor_sync(0xffffffffu, rsum1, 1);
    rsum1 += __shfl_xor_sync(0xffffffffu, rsum1, 2);
    const float inv0 = 1.f / (rsum0 + 1e-32f);
    const float inv1 = 1.f / (rsum1 + 1e-32f);

    // store O (fp16) into [B, NQ, HSIZE] layout
    const int qr0 = q0g + mrow0;
#pragma unroll
    for (int j = 0; j < 8; j++) {
        int d = h * HD + j * 8 + 2 * (lane & 3);
        *(uint32_t*)(oh + (size_t)(b * SEQ + qr0) * NDIM + d) =
            cvt_h2(oacc[j][0] * inv0, oacc[j][1] * inv0);
        *(uint32_t*)(oh + (size_t)(b * SEQ + qr0 + 8) * NDIM + d) =
            cvt_h2(oacc[j][2] * inv1, oacc[j][3] * inv1);
    }
}

// ---------------- launcher ----------------------------------------------------
extern "C" void kernel_launch(void* const* d_in, const int* in_sizes, int n_in,
                              void* d_out, int out_size)
{
    const float* iQ      = (const float*)d_in[0];
    const float* iK      = (const float*)d_in[1];
    const float* iV      = (const float*)d_in[2];
    const void*  mask    = d_in[3];
    const float* Wq      = (const float*)d_in[4];
    const float* Wk      = (const float*)d_in[5];
    const float* Wv      = (const float*)d_in[6];
    const float* Wo      = (const float*)d_in[7];
    const float* sn_bias = (const float*)d_in[8];
    float*       out     = (float*)d_out;

    __half *xq, *xk, *xv, *ohb, *wqh, *wql, *wkh, *wkl, *wvh, *wvl, *woh, *wol;
    __half *qh, *kh, *kl, *vh;
    uint32_t* gmb;
    cudaGetSymbolAddress((void**)&xq, g_xq);
    cudaGetSymbolAddress((void**)&xk, g_xk);
    cudaGetSymbolAddress((void**)&xv, g_xv);
    cudaGetSymbolAddress((void**)&ohb, g_oh);
    cudaGetSymbolAddress((void**)&wqh, g_wqh);
    cudaGetSymbolAddress((void**)&wql, g_wql);
    cudaGetSymbolAddress((void**)&wkh, g_wkh);
    cudaGetSymbolAddress((void**)&wkl, g_wkl);
    cudaGetSymbolAddress((void**)&wvh, g_wvh);
    cudaGetSymbolAddress((void**)&wvl, g_wvl);
    cudaGetSymbolAddress((void**)&woh, g_woh);
    cudaGetSymbolAddress((void**)&wol, g_wol);
    cudaGetSymbolAddress((void**)&qh, g_qh);
    cudaGetSymbolAddress((void**)&kh, g_kh);
    cudaGetSymbolAddress((void**)&kl, g_kl);
    cudaGetSymbolAddress((void**)&vh, g_vh);
    cudaGetSymbolAddress((void**)&gmb, g_maskb);

    cudaFuncSetAttribute(gemm_qkv,
                         cudaFuncAttributeMaxDynamicSharedMemorySize, GSMEM);
    cudaFuncSetAttribute(gemm_out,
                         cudaFuncAttributeMaxDynamicSharedMemorySize, GSMEM);
    cudaFuncSetAttribute(attn_f16,
                         cudaFuncAttributeMaxDynamicSharedMemorySize, A_BYTES);

    // mask dtype autodetect + bit-pack
    detect_mask_kernel<<<1, 256>>>((const unsigned int*)mask);
    convert_maskb<<<2048, 256>>>(mask, gmb);

    const size_t nA4 = (size_t)MDIM * KDIM / 4;
    const size_t nW4 = (size_t)NDIM * KDIM / 4;

    // merged converts (2 launches)
    convert_h3<<<4096, 256>>>((const float4*)iQ, (const float4*)iK,
                              (const float4*)iV,
                              (uint2*)xq, (uint2*)xk, (uint2*)xv, nA4);
    convert_hl4<<<2048, 256>>>((const float4*)Wq, (const float4*)Wk,
                               (const float4*)Wv, (const float4*)Wo,
                               (uint2*)wqh, (uint2*)wql, (uint2*)wkh, (uint2*)wkl,
                               (uint2*)wvh, (uint2*)wvl, (uint2*)woh, (uint2*)wol,
                               nW4);

    // merged Q/K/V projections: one launch, 1536 CTAs
    gemm_qkv<<<dim3(NDIM / 128, 192), 256, GSMEM>>>(
        xq, xk, xv, wqh, wql, wkh, wkl, wvh, wvl, qh, kh, kl, vh);

    attn_f16<<<dim3(SEQ / 128, NB * NH), 256, A_BYTES>>>(
        qh, kh, kl, vh, gmb, sn_bias, ohb);

    gemm_out<<<dim3(NDIM / 128, MDIM / 128), 256, GSMEM>>>(ohb, woh, wol, out);
}

// round 14
// speedup vs baseline: 1.2412x; 1.0928x over previous
#include <cuda_runtime.h>
#include <cuda_fp16.h>
#include <cstdint>
#include <cstddef>

// Problem constants
#define SEQ   2048
#define NB    4
#define NH    16
#define HD    64
#define MDIM  8192     // NB*SEQ
#define NDIM  1024
#define KDIM  1024

// ---------------- scratch (static device globals: allocation-free) -------------
__device__ __half g_xq[(size_t)MDIM * KDIM];
__device__ __half g_xk[(size_t)MDIM * KDIM];
__device__ __half g_xv[(size_t)MDIM * KDIM];
__device__ __half g_oh[(size_t)MDIM * NDIM];
__device__ __half g_wqh[(size_t)NDIM * KDIM];
__device__ __half g_wql[(size_t)NDIM * KDIM];
__device__ __half g_wkh[(size_t)NDIM * KDIM];
__device__ __half g_wkl[(size_t)NDIM * KDIM];
__device__ __half g_wvh[(size_t)NDIM * KDIM];
__device__ __half g_wvl[(size_t)NDIM * KDIM];
__device__ __half g_woh[(size_t)NDIM * KDIM];
__device__ __half g_wol[(size_t)NDIM * KDIM];
__device__ __half g_qh[(size_t)NB * NH * SEQ * HD];   // Q (single fp16)
__device__ __half g_kh[(size_t)NB * NH * SEQ * HD];   // K hi
__device__ __half g_kl[(size_t)NB * NH * SEQ * HD];   // K lo
__device__ __half g_vh[(size_t)NB * NH * SEQ * HD];   // V (single fp16)
__device__ uint32_t g_maskb[(size_t)NB * SEQ * SEQ / 32];  // bit-packed mask
__device__ int g_mode;                              // 0=u8, 1=i32, 2=f32

// ================= helpers =====================================================
__device__ __forceinline__ uint32_t smem_u32(const void* p) {
    uint32_t a;
    asm("{ .reg .u64 t; cvta.to.shared.u64 t, %1; cvt.u32.u64 %0, t; }"
        : "=r"(a) : "l"(p));
    return a;
}

__device__ __forceinline__ uint32_t pack_h2(__half a, __half b) {
    __half2 t;
    t.x = a; t.y = b;
    return *(uint32_t*)&t;
}

__device__ __forceinline__ uint32_t cvt_h2(float x0, float x1) {
    return pack_h2(__float2half_rn(x0), __float2half_rn(x1));
}

__device__ __forceinline__ void cvt_hl2(float x0, float x1,
                                        uint32_t& hp, uint32_t& lp) {
    __half h0 = __float2half_rn(x0), h1 = __float2half_rn(x1);
    hp = pack_h2(h0, h1);
    lp = pack_h2(__float2half_rn(x0 - __half2float(h0)),
                 __float2half_rn(x1 - __half2float(h1)));
}

__device__ __forceinline__ uint32_t u4sel(const uint4& v, int i) {
    return (i == 0) ? v.x : (i == 1) ? v.y : (i == 2) ? v.z : v.w;
}

#define LDSM4(r, a) \
    asm volatile("ldmatrix.sync.aligned.m8n8.x4.shared.b16 {%0,%1,%2,%3}, [%4];" \
        : "=r"((r)[0]), "=r"((r)[1]), "=r"((r)[2]), "=r"((r)[3]) : "r"(a))

#define LDSM4T(r, a) \
    asm volatile("ldmatrix.sync.aligned.m8n8.x4.trans.shared.b16 {%0,%1,%2,%3}, [%4];" \
        : "=r"((r)[0]), "=r"((r)[1]), "=r"((r)[2]), "=r"((r)[3]) : "r"(a))

#define MMA_F16(c, a, b0, b1) \
    asm volatile("mma.sync.aligned.m16n8k16.row.col.f32.f16.f16.f32 " \
        "{%0,%1,%2,%3}, {%4,%5,%6,%7}, {%8,%9}, {%0,%1,%2,%3};" \
        : "+f"((c)[0]), "+f"((c)[1]), "+f"((c)[2]), "+f"((c)[3]) \
        : "r"((a)[0]), "r"((a)[1]), "r"((a)[2]), "r"((a)[3]), "r"(b0), "r"(b1))

#define CP_A16(dst, src) \
    asm volatile("cp.async.cg.shared.global [%0], [%1], 16;" :: "r"(dst), "l"(src))
#define CP_COMMIT() asm volatile("cp.async.commit_group;" ::: "memory")
#define CP_WAIT1()  asm volatile("cp.async.wait_group 1;" ::: "memory")

// ---------------- mask dtype detection + bit-pack conversion -------------------
__global__ void detect_mask_kernel(const unsigned int* __restrict__ w)
{
    __shared__ int s_not_i32, s_not_u8;
    if (threadIdx.x == 0) { s_not_i32 = 0; s_not_u8 = 0; }
    __syncthreads();
    int not_i32 = 0, not_u8 = 0;
    for (int i = threadIdx.x; i < 65536; i += 256) {
        unsigned v = w[i];
        unsigned b0 = v & 255u, b1 = (v >> 8) & 255u,
                 b2 = (v >> 16) & 255u, b3 = v >> 24;
        if ((b1 | b2 | b3) != 0u || b0 > 1u) not_i32 = 1;
        if (b0 > 1u || b1 > 1u || b2 > 1u || b3 > 1u) not_u8 = 1;
    }
    if (not_i32) atomicOr(&s_not_i32, 1);
    if (not_u8)  atomicOr(&s_not_u8, 1);
    __syncthreads();
    if (threadIdx.x == 0)
        g_mode = (!s_not_i32) ? 1 : ((!s_not_u8) ? 0 : 2);
}

// build bit-packed mask: word w holds elements [32w, 32w+32), bit set = masked
__global__ void convert_maskb(const void* __restrict__ m, uint32_t* __restrict__ o)
{
    const int mode = g_mode;
    const size_t nw = (size_t)NB * SEQ * SEQ / 32;
    for (size_t w = (size_t)blockIdx.x * blockDim.x + threadIdx.x; w < nw;
         w += (size_t)gridDim.x * blockDim.x) {
        uint32_t bits = 0;
        if (mode == 1) {
            const uint4* p = (const uint4*)((const int*)m + w * 32);
#pragma unroll
            for (int g = 0; g < 8; g++) {
                uint4 v = p[g];
                bits |= (v.x ? 1u : 0u) << (g * 4 + 0);
                bits |= (v.y ? 1u : 0u) << (g * 4 + 1);
                bits |= (v.z ? 1u : 0u) << (g * 4 + 2);
                bits |= (v.w ? 1u : 0u) << (g * 4 + 3);
            }
        } else if (mode == 2) {
            const float4* p = (const float4*)((const float*)m + w * 32);
#pragma unroll
            for (int g = 0; g < 8; g++) {
                float4 v = p[g];
                bits |= (v.x != 0.f ? 1u : 0u) << (g * 4 + 0);
                bits |= (v.y != 0.f ? 1u : 0u) << (g * 4 + 1);
                bits |= (v.z != 0.f ? 1u : 0u) << (g * 4 + 2);
                bits |= (v.w != 0.f ? 1u : 0u) << (g * 4 + 3);
            }
        } else {
            const uint4* p = (const uint4*)((const unsigned char*)m + w * 32);
#pragma unroll
            for (int g = 0; g < 2; g++) {
                uint4 v = p[g];
                uint32_t ws[4] = {v.x, v.y, v.z, v.w};
#pragma unroll
                for (int q = 0; q < 4; q++)
#pragma unroll
                    for (int e = 0; e < 4; e++)
                        bits |= (((ws[q] >> (e * 8)) & 255u) ? 1u : 0u)
                                << (g * 16 + q * 4 + e);
            }
        }
        o[w] = bits;
    }
}

// ---------------- merged fp32 -> fp16 streaming converters ---------------------
__global__ void convert_h3(const float4* __restrict__ i0,
                           const float4* __restrict__ i1,
                           const float4* __restrict__ i2,
                           uint2* __restrict__ o0, uint2* __restrict__ o1,
                           uint2* __restrict__ o2, size_t n4)
{
    for (size_t i = (size_t)blockIdx.x * blockDim.x + threadIdx.x; i < 3 * n4;
         i += (size_t)gridDim.x * blockDim.x) {
        const float4* in = (i < n4) ? i0 : (i < 2 * n4) ? i1 : i2;
        uint2* out = (i < n4) ? o0 : (i < 2 * n4) ? o1 : o2;
        size_t j = (i < n4) ? i : (i < 2 * n4) ? i - n4 : i - 2 * n4;
        float4 x = in[j];
        out[j] = make_uint2(cvt_h2(x.x, x.y), cvt_h2(x.z, x.w));
    }
}

__global__ void convert_hl4(const float4* __restrict__ i0, const float4* __restrict__ i1,
                            const float4* __restrict__ i2, const float4* __restrict__ i3,
                            uint2* __restrict__ h0, uint2* __restrict__ l0,
                            uint2* __restrict__ h1, uint2* __restrict__ l1,
                            uint2* __restrict__ h2, uint2* __restrict__ l2,
                            uint2* __restrict__ h3, uint2* __restrict__ l3,
                            size_t n4)
{
    for (size_t i = (size_t)blockIdx.x * blockDim.x + threadIdx.x; i < 4 * n4;
         i += (size_t)gridDim.x * blockDim.x) {
        int seg = (int)(i / n4);
        size_t j = i - (size_t)seg * n4;
        const float4* in = (seg == 0) ? i0 : (seg == 1) ? i1 : (seg == 2) ? i2 : i3;
        uint2* hh = (seg == 0) ? h0 : (seg == 1) ? h1 : (seg == 2) ? h2 : h3;
        uint2* ll = (seg == 0) ? l0 : (seg == 1) ? l1 : (seg == 2) ? l2 : l3;
        float4 x = in[j];
        uint32_t a0, b0, a1, b1;
        cvt_hl2(x.x, x.y, a0, b0);
        cvt_hl2(x.z, x.w, a1, b1);
        hh[j] = make_uint2(a0, a1);
        ll[j] = make_uint2(b0, b1);
    }
}

// ================= 2-term fp16 HMMA GEMM (GBK=64, 2-stage cp.async) ============
#define GBK  64
#define NKT  (KDIM / GBK)     // 16
#define PADK 72               // fp16 pitch per row (144B, LDSM conflict-free)
#define T_A  0
#define T_WH 18432
#define T_WL 36864
#define STG_B 55296
#define GSMEM (2 * STG_B)     // 108 KB (x2 CTAs = 216 KB <= 228 KB/SM)

__device__ __forceinline__ void gemm_body(
    const __half* __restrict__ Ah,
    const __half* __restrict__ Wh, const __half* __restrict__ Wl,
    float* __restrict__ Cf, __half* __restrict__ Ch, __half* __restrict__ Cl,
    int mode, int m0, int n0, char* smc)
{
    const uint32_t smb = smem_u32(smc);
    const int tid  = threadIdx.x;
    const int lane = tid & 31, wid = tid >> 5;
    const int wm = wid & 3;
    const int wn = wid >> 2;

    const int row0 = tid >> 3;     // 0..31
    const int ch   = tid & 7;      // 16B chunk (8 fp16) within 64-col stage

    float acc[2][8][4];
#pragma unroll
    for (int i = 0; i < 2; i++)
#pragma unroll
        for (int j = 0; j < 8; j++)
#pragma unroll
            for (int q = 0; q < 4; q++) acc[i][j][q] = 0.f;

    auto issue = [&](int kt) {
        if (kt < NKT) {
            const int k0 = kt * GBK;
            const uint32_t sb = smb + (kt & 1) * STG_B;
#pragma unroll
            for (int g = 0; g < 4; g++) {
                int r = row0 + g * 32;
                uint32_t doff = (uint32_t)(r * PADK + ch * 8) * 2;
                const size_t asrc = (size_t)(m0 + r) * KDIM + k0 + ch * 8;
                const size_t wsrc = (size_t)(n0 + r) * KDIM + k0 + ch * 8;
                CP_A16(sb + T_A  + doff, Ah + asrc);
                CP_A16(sb + T_WH + doff, Wh + wsrc);
                CP_A16(sb + T_WL + doff, Wl + wsrc);
            }
        }
        CP_COMMIT();
    };

    issue(0);
    issue(1);
    CP_WAIT1();
    __syncthreads();

    const int a_r = lane & 15;
    const int a_c = (lane >> 4) << 3;
    const int b_r = (lane & 7) + ((lane >> 4) << 3);
    const int b_c = ((lane >> 3) & 1) << 3;

    for (int kt = 0; kt < NKT; kt++) {
        const uint32_t sb = smb + (kt & 1) * STG_B;

#pragma unroll
        for (int ks = 0; ks < 4; ks++) {
            uint32_t af[2][4];
#pragma unroll
            for (int i = 0; i < 2; i++) {
                uint32_t off =
                    ((wm * 32 + i * 16 + a_r) * PADK + a_c + ks * 16) * 2;
                LDSM4(af[i], sb + T_A + off);
            }
#pragma unroll
            for (int p = 0; p < 4; p++) {
                uint32_t bh[4], bl[4];
                uint32_t off =
                    ((wn * 64 + p * 16 + b_r) * PADK + b_c + ks * 16) * 2;
                LDSM4(bh, sb + T_WH + off);
                LDSM4(bl, sb + T_WL + off);
#pragma unroll
                for (int i = 0; i < 2; i++)
#pragma unroll
                    for (int hf = 0; hf < 2; hf++) {
                        int j = p * 2 + hf;
                        MMA_F16(acc[i][j], af[i], bh[2*hf], bh[2*hf+1]);
                        MMA_F16(acc[i][j], af[i], bl[2*hf], bl[2*hf+1]);
                    }
            }
        }
        __syncthreads();
        issue(kt + 2);
        CP_WAIT1();
        __syncthreads();
    }

    // epilogue
#pragma unroll
    for (int i = 0; i < 2; i++) {
#pragma unroll
        for (int j = 0; j < 8; j++) {
            int mrow = m0 + wm * 32 + i * 16 + (lane >> 2);
            int ncol = n0 + wn * 64 + j * 8 + (lane & 3) * 2;
#pragma unroll
            for (int hf = 0; hf < 2; hf++) {
                int m = mrow + hf * 8;
                float v0 = acc[i][j][hf*2], v1 = acc[i][j][hf*2+1];
                if (mode == 0) {
                    *(float2*)(Cf + (size_t)m * NDIM + ncol) =
                        make_float2(v0, v1);
                } else {
                    int bb = m >> 11, s = m & 2047;
                    int hh = ncol >> 6, d = ncol & 63;
                    size_t off = ((size_t)(bb*NH + hh) * SEQ + s) * HD + d;
                    if (mode == 1) {
                        *(uint32_t*)(Ch + off) = cvt_h2(v0, v1);
                    } else {
                        uint32_t hp, lp;
                        cvt_hl2(v0, v1, hp, lp);
                        *(uint32_t*)(Ch + off) = hp;
                        *(uint32_t*)(Cl + off) = lp;
                    }
                }
            }
        }
    }
}

// merged Q/K/V projection: grid.y = 192 (seg = y/64: 0=Q, 1=K, 2=V)
__global__ void __launch_bounds__(256, 2)
gemm_qkv(const __half* __restrict__ xq, const __half* __restrict__ xk,
         const __half* __restrict__ xv,
         const __half* __restrict__ wqh, const __half* __restrict__ wql,
         const __half* __restrict__ wkh, const __half* __restrict__ wkl,
         const __half* __restrict__ wvh, const __half* __restrict__ wvl,
         __half* __restrict__ qh, __half* __restrict__ kh,
         __half* __restrict__ kl, __half* __restrict__ vh)
{
    extern __shared__ char smc[];
    const int seg = blockIdx.y >> 6;           // 0,1,2
    const int m0 = (blockIdx.y & 63) * 128;
    const int n0 = blockIdx.x * 128;
    const __half* Ah = (seg == 0) ? xq  : (seg == 1) ? xk  : xv;
    const __half* Wh = (seg == 0) ? wqh : (seg == 1) ? wkh : wvh;
    const __half* Wl = (seg == 0) ? wql : (seg == 1) ? wkl : wvl;
    __half* Ch = (seg == 0) ? qh : (seg == 1) ? kh : vh;
    __half* Cl = (seg == 1) ? kl : nullptr;
    const int mode = (seg == 1) ? 2 : 1;
    gemm_body(Ah, Wh, Wl, nullptr, Ch, Cl, mode, m0, n0, smc);
}

// output projection (fp32 out)
__global__ void __launch_bounds__(256, 2)
gemm_out(const __half* __restrict__ Ah,
         const __half* __restrict__ Wh, const __half* __restrict__ Wl,
         float* __restrict__ Cf)
{
    extern __shared__ char smc[];
    gemm_body(Ah, Wh, Wl, Cf, nullptr, nullptr, 0,
              blockIdx.y * 128, blockIdx.x * 128, smc);
}

// ================= fp16 HMMA fused attention (KTILE=128, single-T O) ===========
// S = Qh*(Kh+Kl) ; T = relu(S/8+b)^2 (fp32) -> fp16 ; O += T*Vh
#define KTILE 128
#define NCT   (KTILE / 16)            // 8
#define APCH  72
#define A_Q   0
#define A_KH  (A_Q  + 128 * APCH * 2)   // 18432
#define A_KL  (A_KH + KTILE * APCH * 2) // 36864
#define A_VH  (A_KL + KTILE * APCH * 2) // 55296
#define A_MS  (A_VH + KTILE * APCH * 2) // 73728 (128 rows x 16B bit-mask)
#define A_BYTES (A_MS + 128 * 16)       // 75776

__global__ void __launch_bounds__(256, 2)
attn_f16(const __half* __restrict__ qh,
         const __half* __restrict__ kh, const __half* __restrict__ kl,
         const __half* __restrict__ vh,
         const uint32_t* __restrict__ maskb,
         const float* __restrict__ sn_bias,
         __half* __restrict__ oh)
{
    extern __shared__ char sm[];
    const uint32_t smb = smem_u32(sm);
    const int tid  = threadIdx.x;
    const int lane = tid & 31, wid = tid >> 5;
    const int bh = blockIdx.y;
    const int b = bh >> 4, h = bh & 15;
    const int q0g = blockIdx.x * 128;
    const float bias = sn_bias[0];

    // stage Q tile [128 x 64] fp16
    {
        const size_t qbase = ((size_t)bh * SEQ + q0g) * HD;
#pragma unroll
        for (int i = 0; i < 4; i++) {
            int lin = tid + i * 256;        // 0..1023
            int row = lin >> 3, c = lin & 7;
            *(uint4*)(sm + A_Q + (uint32_t)(row * APCH + c * 8) * 2) =
                *(const uint4*)(qh + qbase + (size_t)row * HD + c * 8);
        }
    }
    __syncthreads();

    const int a_r = lane & 15;
    const int a_c = (lane >> 4) << 3;
    const int b_r = (lane & 7) + ((lane >> 4) << 3);
    const int b_c = ((lane >> 3) & 1) << 3;
    const int v_r = ((lane >> 3) & 1) * 8 + (lane & 7);
    const int v_c = (lane >> 4) << 3;
    const int mrow0 = wid * 16 + (lane >> 2);
    const int shl = 2 * (lane & 3);

    // hoist Q fragments for the whole K loop
    uint32_t qf[4][4];
#pragma unroll
    for (int dc = 0; dc < 4; dc++)
        LDSM4(qf[dc], smb + A_Q + ((wid * 16 + a_r) * APCH + dc * 16 + a_c) * 2);

    float oacc[8][4];
#pragma unroll
    for (int j = 0; j < 8; j++)
#pragma unroll
        for (int e = 0; e < 4; e++) oacc[j][e] = 0.f;
    float rsum0 = 0.f, rsum1 = 0.f;

    const size_t kvbase = (size_t)bh * SEQ * HD;
    // bit-packed mask: per q-row SEQ/32 = 64 words = 16 uint4; tile kt = uint4 #kt
    const uint4* mrow_base =
        (const uint4*)(maskb + ((size_t)b * SEQ + q0g) * (SEQ / 32));

    for (int kt = 0; kt < SEQ / KTILE; kt++) {
        __syncthreads();
        // stage K hi/lo, V (128x64) + bit-mask (128 rows x 16B)
        {
            const size_t tb = kvbase + (size_t)kt * KTILE * HD;
#pragma unroll
            for (int i = 0; i < 4; i++) {
                int lin = tid + i * 256;    // 0..1023
                int row = lin >> 3, c = lin & 7;
                size_t off = tb + (size_t)row * HD + c * 8;
                uint32_t doff = (uint32_t)(row * APCH + c * 8) * 2;
                *(uint4*)(sm + A_KH + doff) = *(const uint4*)(kh + off);
                *(uint4*)(sm + A_KL + doff) = *(const uint4*)(kl + off);
                *(uint4*)(sm + A_VH + doff) = *(const uint4*)(vh + off);
            }
            // row r's 64 words = 16 uint4; tile kt (128 bits) = uint4 index r*16+kt
            if (tid < 128)
                *(uint4*)(sm + A_MS + tid * 16) = mrow_base[(size_t)tid * 16 + kt];
        }
        __syncthreads();

        // per-thread mask words for this tile (2 q-rows x 128 k-bits)
        const uint4 mw0 = *(const uint4*)(sm + A_MS + mrow0 * 16);
        const uint4 mw1 = *(const uint4*)(sm + A_MS + (mrow0 + 8) * 16);

        // ---- interleaved S chunk -> T -> O chunk, per 16 k-rows -------------
#pragma unroll
        for (int nc = 0; nc < NCT; nc++) {
            float sc[2][4];
#pragma unroll
            for (int hf = 0; hf < 2; hf++)
#pragma unroll
                for (int e = 0; e < 4; e++) sc[hf][e] = 0.f;

#pragma unroll
            for (int dc = 0; dc < 4; dc++) {
                uint32_t khf[4], klf[4];
                uint32_t ka = smb + A_KH +
                    ((nc * 16 + b_r) * APCH + dc * 16 + b_c) * 2;
                LDSM4(khf, ka);
                LDSM4(klf, ka + (A_KL - A_KH));
#pragma unroll
                for (int hf = 0; hf < 2; hf++) {
                    MMA_F16(sc[hf], qf[dc], khf[2*hf], khf[2*hf+1]);
                    MMA_F16(sc[hf], qf[dc], klf[2*hf], klf[2*hf+1]);
                }
            }

            // mask + bias + relu^2, rowsum, T to single fp16 fragments
            uint32_t aph[4];
#pragma unroll
            for (int hf = 0; hf < 2; hf++) {
                const int base = nc * 16 + hf * 8;       // 0..120, const
                const uint32_t w0 = u4sel(mw0, base >> 5);
                const uint32_t w1 = u4sel(mw1, base >> 5);
                const int sh = (base & 31) + shl;
                float t0 = fmaxf(fmaf(sc[hf][0], 0.125f, bias), 0.f);
                float t1 = fmaxf(fmaf(sc[hf][1], 0.125f, bias), 0.f);
                float t2 = fmaxf(fmaf(sc[hf][2], 0.125f, bias), 0.f);
                float t3 = fmaxf(fmaf(sc[hf][3], 0.125f, bias), 0.f);
                if ((w0 >> sh) & 1u)       t0 = 0.f;
                if ((w0 >> (sh + 1)) & 1u) t1 = 0.f;
                if ((w1 >> sh) & 1u)       t2 = 0.f;
                if ((w1 >> (sh + 1)) & 1u) t3 = 0.f;
                t0 *= t0; t1 *= t1; t2 *= t2; t3 *= t3;
                rsum0 += t0 + t1;
                rsum1 += t2 + t3;
                aph[2*hf + 0] = cvt_h2(t0, t1);
                aph[2*hf + 1] = cvt_h2(t2, t3);
            }

            // O += T * V for this k-chunk (V via ldmatrix.trans)
#pragma unroll
            for (int dch = 0; dch < 4; dch++) {
                uint32_t vf[4];
                LDSM4T(vf, smb + A_VH +
                           ((nc * 16 + v_r) * APCH + dch * 16 + v_c) * 2);
#pragma unroll
                for (int hf = 0; hf < 2; hf++) {
                    int j = dch * 2 + hf;
                    MMA_F16(oacc[j], aph, vf[2*hf], vf[2*hf+1]);
                }
            }
        }
    }

    rsum0 += __shfl_xor_sync(0xffffffffu, rsum0, 1);
    rsum0 += __shfl_xor_sync(0xffffffffu, rsum0, 2);
    rsum1 += __shfl_xor_sync(0xffffffffu, rsum1, 1);
    rsum1 += __shfl_xor_sync(0xffffffffu, rsum1, 2);
    const float inv0 = 1.f / (rsum0 + 1e-32f);
    const float inv1 = 1.f / (rsum1 + 1e-32f);

    // store O (fp16) into [B, NQ, HSIZE] layout
    const int qr0 = q0g + mrow0;
#pragma unroll
    for (int j = 0; j < 8; j++) {
        int d = h * HD + j * 8 + 2 * (lane & 3);
        *(uint32_t*)(oh + (size_t)(b * SEQ + qr0) * NDIM + d) =
            cvt_h2(oacc[j][0] * inv0, oacc[j][1] * inv0);
        *(uint32_t*)(oh + (size_t)(b * SEQ + qr0 + 8) * NDIM + d) =
            cvt_h2(oacc[j][2] * inv1, oacc[j][3] * inv1);
    }
}

// ---------------- launcher ----------------------------------------------------
extern "C" void kernel_launch(void* const* d_in, const int* in_sizes, int n_in,
                              void* d_out, int out_size)
{
    const float* iQ      = (const float*)d_in[0];
    const float* iK      = (const float*)d_in[1];
    const float* iV      = (const float*)d_in[2];
    const void*  mask    = d_in[3];
    const float* Wq      = (const float*)d_in[4];
    const float* Wk      = (const float*)d_in[5];
    const float* Wv      = (const float*)d_in[6];
    const float* Wo      = (const float*)d_in[7];
    const float* sn_bias = (const float*)d_in[8];
    float*       out     = (float*)d_out;

    __half *xq, *xk, *xv, *ohb, *wqh, *wql, *wkh, *wkl, *wvh, *wvl, *woh, *wol;
    __half *qh, *kh, *kl, *vh;
    uint32_t* gmb;
    cudaGetSymbolAddress((void**)&xq, g_xq);
    cudaGetSymbolAddress((void**)&xk, g_xk);
    cudaGetSymbolAddress((void**)&xv, g_xv);
    cudaGetSymbolAddress((void**)&ohb, g_oh);
    cudaGetSymbolAddress((void**)&wqh, g_wqh);
    cudaGetSymbolAddress((void**)&wql, g_wql);
    cudaGetSymbolAddress((void**)&wkh, g_wkh);
    cudaGetSymbolAddress((void**)&wkl, g_wkl);
    cudaGetSymbolAddress((void**)&wvh, g_wvh);
    cudaGetSymbolAddress((void**)&wvl, g_wvl);
    cudaGetSymbolAddress((void**)&woh, g_woh);
    cudaGetSymbolAddress((void**)&wol, g_wol);
    cudaGetSymbolAddress((void**)&qh, g_qh);
    cudaGetSymbolAddress((void**)&kh, g_kh);
    cudaGetSymbolAddress((void**)&kl, g_kl);
    cudaGetSymbolAddress((void**)&vh, g_vh);
    cudaGetSymbolAddress((void**)&gmb, g_maskb);

    cudaFuncSetAttribute(gemm_qkv,
                         cudaFuncAttributeMaxDynamicSharedMemorySize, GSMEM);
    cudaFuncSetAttribute(gemm_out,
                         cudaFuncAttributeMaxDynamicSharedMemorySize, GSMEM);
    cudaFuncSetAttribute(attn_f16,
                         cudaFuncAttributeMaxDynamicSharedMemorySize, A_BYTES);

    // mask dtype autodetect + bit-pack
    detect_mask_kernel<<<1, 256>>>((const unsigned int*)mask);
    convert_maskb<<<2048, 256>>>(mask, gmb);

    const size_t nA4 = (size_t)MDIM * KDIM / 4;
    const size_t nW4 = (size_t)NDIM * KDIM / 4;

    // merged converts (2 launches)
    convert_h3<<<4096, 256>>>((const float4*)iQ, (const float4*)iK,
                              (const float4*)iV,
                              (uint2*)xq, (uint2*)xk, (uint2*)xv, nA4);
    convert_hl4<<<2048, 256>>>((const float4*)Wq, (const float4*)Wk,
                               (const float4*)Wv, (const float4*)Wo,
                               (uint2*)wqh, (uint2*)wql, (uint2*)wkh, (uint2*)wkl,
                               (uint2*)wvh, (uint2*)wvl, (uint2*)woh, (uint2*)wol,
                               nW4);

    // merged Q/K/V projections: one launch, 1536 CTAs
    gemm_qkv<<<dim3(NDIM / 128, 192), 256, GSMEM>>>(
        xq, xk, xv, wqh, wql, wkh, wkl, wvh, wvl, qh, kh, kl, vh);

    attn_f16<<<dim3(SEQ / 128, NB * NH), 256, A_BYTES>>>(
        qh, kh, kl, vh, gmb, sn_bias, ohb);

    gemm_out<<<dim3(NDIM / 128, MDIM / 128), 256, GSMEM>>>(ohb, woh, wol, out);
}

// round 15
// speedup vs baseline: 1.4065x; 1.1332x over previous
#include <cuda_runtime.h>
#include <cuda_fp16.h>
#include <cstdint>
#include <cstddef>

// Problem constants
#define SEQ   2048
#define NB    4
#define NH    16
#define HD    64
#define MDIM  8192     // NB*SEQ
#define NDIM  1024
#define KDIM  1024

// ---------------- scratch (static device globals: allocation-free) -------------
__device__ __half g_xq[(size_t)MDIM * KDIM];
__device__ __half g_xk[(size_t)MDIM * KDIM];
__device__ __half g_xv[(size_t)MDIM * KDIM];
__device__ __half g_oh[(size_t)MDIM * NDIM];
__device__ __half g_wqh[(size_t)NDIM * KDIM];
__device__ __half g_wql[(size_t)NDIM * KDIM];
__device__ __half g_wkh[(size_t)NDIM * KDIM];
__device__ __half g_wkl[(size_t)NDIM * KDIM];
__device__ __half g_wvh[(size_t)NDIM * KDIM];
__device__ __half g_wvl[(size_t)NDIM * KDIM];   // unused (V 1-term) but kept for layout
__device__ __half g_woh[(size_t)NDIM * KDIM];
__device__ __half g_wol[(size_t)NDIM * KDIM];   // unused (O 1-term)
__device__ __half g_qh[(size_t)NB * NH * SEQ * HD];   // Q (single fp16)
__device__ __half g_kh[(size_t)NB * NH * SEQ * HD];   // K hi
__device__ __half g_kl[(size_t)NB * NH * SEQ * HD];   // K lo
__device__ __half g_vh[(size_t)NB * NH * SEQ * HD];   // V (single fp16)
__device__ uint32_t g_maskb[(size_t)NB * SEQ * SEQ / 32];  // bit-packed mask
__device__ int g_mode;                              // 0=u8, 1=i32, 2=f32

// ================= helpers =====================================================
__device__ __forceinline__ uint32_t smem_u32(const void* p) {
    uint32_t a;
    asm("{ .reg .u64 t; cvta.to.shared.u64 t, %1; cvt.u32.u64 %0, t; }"
        : "=r"(a) : "l"(p));
    return a;
}

__device__ __forceinline__ uint32_t pack_h2(__half a, __half b) {
    __half2 t;
    t.x = a; t.y = b;
    return *(uint32_t*)&t;
}

__device__ __forceinline__ uint32_t cvt_h2(float x0, float x1) {
    return pack_h2(__float2half_rn(x0), __float2half_rn(x1));
}

__device__ __forceinline__ void cvt_hl2(float x0, float x1,
                                        uint32_t& hp, uint32_t& lp) {
    __half h0 = __float2half_rn(x0), h1 = __float2half_rn(x1);
    hp = pack_h2(h0, h1);
    lp = pack_h2(__float2half_rn(x0 - __half2float(h0)),
                 __float2half_rn(x1 - __half2float(h1)));
}

__device__ __forceinline__ uint32_t u4sel(const uint4& v, int i) {
    return (i == 0) ? v.x : (i == 1) ? v.y : (i == 2) ? v.z : v.w;
}

#define LDSM4(r, a) \
    asm volatile("ldmatrix.sync.aligned.m8n8.x4.shared.b16 {%0,%1,%2,%3}, [%4];" \
        : "=r"((r)[0]), "=r"((r)[1]), "=r"((r)[2]), "=r"((r)[3]) : "r"(a))

#define LDSM4T(r, a) \
    asm volatile("ldmatrix.sync.aligned.m8n8.x4.trans.shared.b16 {%0,%1,%2,%3}, [%4];" \
        : "=r"((r)[0]), "=r"((r)[1]), "=r"((r)[2]), "=r"((r)[3]) : "r"(a))

#define MMA_F16(c, a, b0, b1) \
    asm volatile("mma.sync.aligned.m16n8k16.row.col.f32.f16.f16.f32 " \
        "{%0,%1,%2,%3}, {%4,%5,%6,%7}, {%8,%9}, {%0,%1,%2,%3};" \
        : "+f"((c)[0]), "+f"((c)[1]), "+f"((c)[2]), "+f"((c)[3]) \
        : "r"((a)[0]), "r"((a)[1]), "r"((a)[2]), "r"((a)[3]), "r"(b0), "r"(b1))

#define CP_A16(dst, src) \
    asm volatile("cp.async.cg.shared.global [%0], [%1], 16;" :: "r"(dst), "l"(src))
#define CP_COMMIT() asm volatile("cp.async.commit_group;" ::: "memory")
#define CP_WAIT1()  asm volatile("cp.async.wait_group 1;" ::: "memory")

// ---------------- mask dtype detection + bit-pack conversion -------------------
__global__ void detect_mask_kernel(const unsigned int* __restrict__ w)
{
    __shared__ int s_not_i32, s_not_u8;
    if (threadIdx.x == 0) { s_not_i32 = 0; s_not_u8 = 0; }
    __syncthreads();
    int not_i32 = 0, not_u8 = 0;
    for (int i = threadIdx.x; i < 65536; i += 256) {
        unsigned v = w[i];
        unsigned b0 = v & 255u, b1 = (v >> 8) & 255u,
                 b2 = (v >> 16) & 255u, b3 = v >> 24;
        if ((b1 | b2 | b3) != 0u || b0 > 1u) not_i32 = 1;
        if (b0 > 1u || b1 > 1u || b2 > 1u || b3 > 1u) not_u8 = 1;
    }
    if (not_i32) atomicOr(&s_not_i32, 1);
    if (not_u8)  atomicOr(&s_not_u8, 1);
    __syncthreads();
    if (threadIdx.x == 0)
        g_mode = (!s_not_i32) ? 1 : ((!s_not_u8) ? 0 : 2);
}

// build bit-packed mask: word w holds elements [32w, 32w+32), bit set = masked
__global__ void convert_maskb(const void* __restrict__ m, uint32_t* __restrict__ o)
{
    const int mode = g_mode;
    const size_t nw = (size_t)NB * SEQ * SEQ / 32;
    for (size_t w = (size_t)blockIdx.x * blockDim.x + threadIdx.x; w < nw;
         w += (size_t)gridDim.x * blockDim.x) {
        uint32_t bits = 0;
        if (mode == 1) {
            const uint4* p = (const uint4*)((const int*)m + w * 32);
#pragma unroll
            for (int g = 0; g < 8; g++) {
                uint4 v = p[g];
                bits |= (v.x ? 1u : 0u) << (g * 4 + 0);
                bits |= (v.y ? 1u : 0u) << (g * 4 + 1);
                bits |= (v.z ? 1u : 0u) << (g * 4 + 2);
                bits |= (v.w ? 1u : 0u) << (g * 4 + 3);
            }
        } else if (mode == 2) {
            const float4* p = (const float4*)((const float*)m + w * 32);
#pragma unroll
            for (int g = 0; g < 8; g++) {
                float4 v = p[g];
                bits |= (v.x != 0.f ? 1u : 0u) << (g * 4 + 0);
                bits |= (v.y != 0.f ? 1u : 0u) << (g * 4 + 1);
                bits |= (v.z != 0.f ? 1u : 0u) << (g * 4 + 2);
                bits |= (v.w != 0.f ? 1u : 0u) << (g * 4 + 3);
            }
        } else {
            const uint4* p = (const uint4*)((const unsigned char*)m + w * 32);
#pragma unroll
            for (int g = 0; g < 2; g++) {
                uint4 v = p[g];
                uint32_t ws[4] = {v.x, v.y, v.z, v.w};
#pragma unroll
                for (int q = 0; q < 4; q++)
#pragma unroll
                    for (int e = 0; e < 4; e++)
                        bits |= (((ws[q] >> (e * 8)) & 255u) ? 1u : 0u)
                                << (g * 16 + q * 4 + e);
            }
        }
        o[w] = bits;
    }
}

// ---------------- merged fp32 -> fp16 streaming converters ---------------------
__global__ void convert_h3(const float4* __restrict__ i0,
                           const float4* __restrict__ i1,
                           const float4* __restrict__ i2,
                           uint2* __restrict__ o0, uint2* __restrict__ o1,
                           uint2* __restrict__ o2, size_t n4)
{
    for (size_t i = (size_t)blockIdx.x * blockDim.x + threadIdx.x; i < 3 * n4;
         i += (size_t)gridDim.x * blockDim.x) {
        const float4* in = (i < n4) ? i0 : (i < 2 * n4) ? i1 : i2;
        uint2* out = (i < n4) ? o0 : (i < 2 * n4) ? o1 : o2;
        size_t j = (i < n4) ? i : (i < 2 * n4) ? i - n4 : i - 2 * n4;
        float4 x = in[j];
        out[j] = make_uint2(cvt_h2(x.x, x.y), cvt_h2(x.z, x.w));
    }
}

// Wq (hi+lo), Wk (hi+lo), Wv (hi only), Wo (hi only)
__global__ void convert_w(const float4* __restrict__ i0, const float4* __restrict__ i1,
                          const float4* __restrict__ i2, const float4* __restrict__ i3,
                          uint2* __restrict__ h0, uint2* __restrict__ l0,
                          uint2* __restrict__ h1, uint2* __restrict__ l1,
                          uint2* __restrict__ h2, uint2* __restrict__ h3,
                          size_t n4)
{
    for (size_t i = (size_t)blockIdx.x * blockDim.x + threadIdx.x; i < 4 * n4;
         i += (size_t)gridDim.x * blockDim.x) {
        int seg = (int)(i / n4);
        size_t j = i - (size_t)seg * n4;
        const float4* in = (seg == 0) ? i0 : (seg == 1) ? i1 : (seg == 2) ? i2 : i3;
        float4 x = in[j];
        if (seg < 2) {
            uint2* hh = (seg == 0) ? h0 : h1;
            uint2* ll = (seg == 0) ? l0 : l1;
            uint32_t a0, b0, a1, b1;
            cvt_hl2(x.x, x.y, a0, b0);
            cvt_hl2(x.z, x.w, a1, b1);
            hh[j] = make_uint2(a0, a1);
            ll[j] = make_uint2(b0, b1);
        } else {
            uint2* hh = (seg == 2) ? h2 : h3;
            hh[j] = make_uint2(cvt_h2(x.x, x.y), cvt_h2(x.z, x.w));
        }
    }
}

// ================= fp16 HMMA GEMM (GBK=64, 2-stage cp.async, 1/2-term) =========
#define GBK  64
#define NKT  (KDIM / GBK)     // 16
#define PADK 72               // fp16 pitch per row (144B, LDSM conflict-free)
#define T_A  0
#define T_WH 18432
#define T_WL 36864
#define STG_B 55296
#define GSMEM (2 * STG_B)     // 108 KB (x2 CTAs = 216 KB <= 228 KB/SM)

template <bool TWO_TERM>
__device__ __forceinline__ void gemm_body(
    const __half* __restrict__ Ah,
    const __half* __restrict__ Wh, const __half* __restrict__ Wl,
    float* __restrict__ Cf, __half* __restrict__ Ch, __half* __restrict__ Cl,
    int mode, int m0, int n0, char* smc)
{
    const uint32_t smb = smem_u32(smc);
    const int tid  = threadIdx.x;
    const int lane = tid & 31, wid = tid >> 5;
    const int wm = wid & 3;
    const int wn = wid >> 2;

    const int row0 = tid >> 3;     // 0..31
    const int ch   = tid & 7;      // 16B chunk (8 fp16) within 64-col stage

    float acc[2][8][4];
#pragma unroll
    for (int i = 0; i < 2; i++)
#pragma unroll
        for (int j = 0; j < 8; j++)
#pragma unroll
            for (int q = 0; q < 4; q++) acc[i][j][q] = 0.f;

    auto issue = [&](int kt) {
        if (kt < NKT) {
            const int k0 = kt * GBK;
            const uint32_t sb = smb + (kt & 1) * STG_B;
#pragma unroll
            for (int g = 0; g < 4; g++) {
                int r = row0 + g * 32;
                uint32_t doff = (uint32_t)(r * PADK + ch * 8) * 2;
                const size_t asrc = (size_t)(m0 + r) * KDIM + k0 + ch * 8;
                const size_t wsrc = (size_t)(n0 + r) * KDIM + k0 + ch * 8;
                CP_A16(sb + T_A  + doff, Ah + asrc);
                CP_A16(sb + T_WH + doff, Wh + wsrc);
                if (TWO_TERM)
                    CP_A16(sb + T_WL + doff, Wl + wsrc);
            }
        }
        CP_COMMIT();
    };

    issue(0);
    issue(1);
    CP_WAIT1();
    __syncthreads();

    const int a_r = lane & 15;
    const int a_c = (lane >> 4) << 3;
    const int b_r = (lane & 7) + ((lane >> 4) << 3);
    const int b_c = ((lane >> 3) & 1) << 3;

    for (int kt = 0; kt < NKT; kt++) {
        const uint32_t sb = smb + (kt & 1) * STG_B;

#pragma unroll
        for (int ks = 0; ks < 4; ks++) {
            uint32_t af[2][4];
#pragma unroll
            for (int i = 0; i < 2; i++) {
                uint32_t off =
                    ((wm * 32 + i * 16 + a_r) * PADK + a_c + ks * 16) * 2;
                LDSM4(af[i], sb + T_A + off);
            }
#pragma unroll
            for (int p = 0; p < 4; p++) {
                uint32_t bh[4], bl[4];
                uint32_t off =
                    ((wn * 64 + p * 16 + b_r) * PADK + b_c + ks * 16) * 2;
                LDSM4(bh, sb + T_WH + off);
                if (TWO_TERM)
                    LDSM4(bl, sb + T_WL + off);
#pragma unroll
                for (int i = 0; i < 2; i++)
#pragma unroll
                    for (int hf = 0; hf < 2; hf++) {
                        int j = p * 2 + hf;
                        MMA_F16(acc[i][j], af[i], bh[2*hf], bh[2*hf+1]);
                        if (TWO_TERM)
                            MMA_F16(acc[i][j], af[i], bl[2*hf], bl[2*hf+1]);
                    }
            }
        }
        __syncthreads();
        issue(kt + 2);
        CP_WAIT1();
        __syncthreads();
    }

    // epilogue
#pragma unroll
    for (int i = 0; i < 2; i++) {
#pragma unroll
        for (int j = 0; j < 8; j++) {
            int mrow = m0 + wm * 32 + i * 16 + (lane >> 2);
            int ncol = n0 + wn * 64 + j * 8 + (lane & 3) * 2;
#pragma unroll
            for (int hf = 0; hf < 2; hf++) {
                int m = mrow + hf * 8;
                float v0 = acc[i][j][hf*2], v1 = acc[i][j][hf*2+1];
                if (mode == 0) {
                    *(float2*)(Cf + (size_t)m * NDIM + ncol) =
                        make_float2(v0, v1);
                } else {
                    int bb = m >> 11, s = m & 2047;
                    int hh = ncol >> 6, d = ncol & 63;
                    size_t off = ((size_t)(bb*NH + hh) * SEQ + s) * HD + d;
                    if (mode == 1) {
                        *(uint32_t*)(Ch + off) = cvt_h2(v0, v1);
                    } else {
                        uint32_t hp, lp;
                        cvt_hl2(v0, v1, hp, lp);
                        *(uint32_t*)(Ch + off) = hp;
                        *(uint32_t*)(Cl + off) = lp;
                    }
                }
            }
        }
    }
}

// merged Q/K/V projection: grid.y = 192 (seg = y/64: 0=Q(2t), 1=K(2t), 2=V(1t))
__global__ void __launch_bounds__(256, 2)
gemm_qkv(const __half* __restrict__ xq, const __half* __restrict__ xk,
         const __half* __restrict__ xv,
         const __half* __restrict__ wqh, const __half* __restrict__ wql,
         const __half* __restrict__ wkh, const __half* __restrict__ wkl,
         const __half* __restrict__ wvh,
         __half* __restrict__ qh, __half* __restrict__ kh,
         __half* __restrict__ kl, __half* __restrict__ vh)
{
    extern __shared__ char smc[];
    const int seg = blockIdx.y >> 6;           // 0,1,2
    const int m0 = (blockIdx.y & 63) * 128;
    const int n0 = blockIdx.x * 128;
    if (seg == 0) {
        gemm_body<true>(xq, wqh, wql, nullptr, qh, nullptr, 1, m0, n0, smc);
    } else if (seg == 1) {
        gemm_body<true>(xk, wkh, wkl, nullptr, kh, kl, 2, m0, n0, smc);
    } else {
        gemm_body<false>(xv, wvh, nullptr, nullptr, vh, nullptr, 1, m0, n0, smc);
    }
}

// output projection (fp32 out, 1-term)
__global__ void __launch_bounds__(256, 2)
gemm_out(const __half* __restrict__ Ah,
         const __half* __restrict__ Wh,
         float* __restrict__ Cf)
{
    extern __shared__ char smc[];
    gemm_body<false>(Ah, Wh, nullptr, Cf, nullptr, nullptr, 0,
                     blockIdx.y * 128, blockIdx.x * 128, smc);
}

// ================= fp16 HMMA fused attention (KTILE=128, single-T O) ===========
// S = Qh*(Kh+Kl) ; T = relu(S/8+b)^2 (fp32) -> fp16 ; O += T*Vh
#define KTILE 128
#define NCT   (KTILE / 16)            // 8
#define APCH  72
#define A_Q   0
#define A_KH  (A_Q  + 128 * APCH * 2)   // 18432
#define A_KL  (A_KH + KTILE * APCH * 2) // 36864
#define A_VH  (A_KL + KTILE * APCH * 2) // 55296
#define A_MS  (A_VH + KTILE * APCH * 2) // 73728 (128 rows x 16B bit-mask)
#define A_BYTES (A_MS + 128 * 16)       // 75776

__global__ void __launch_bounds__(256, 2)
attn_f16(const __half* __restrict__ qh,
         const __half* __restrict__ kh, const __half* __restrict__ kl,
         const __half* __restrict__ vh,
         const uint32_t* __restrict__ maskb,
         const float* __restrict__ sn_bias,
         __half* __restrict__ oh)
{
    extern __shared__ char sm[];
    const uint32_t smb = smem_u32(sm);
    const int tid  = threadIdx.x;
    const int lane = tid & 31, wid = tid >> 5;
    const int bh = blockIdx.y;
    const int b = bh >> 4, h = bh & 15;
    const int q0g = blockIdx.x * 128;
    const float bias = sn_bias[0];

    // stage Q tile [128 x 64] fp16
    {
        const size_t qbase = ((size_t)bh * SEQ + q0g) * HD;
#pragma unroll
        for (int i = 0; i < 4; i++) {
            int lin = tid + i * 256;        // 0..1023
            int row = lin >> 3, c = lin & 7;
            *(uint4*)(sm + A_Q + (uint32_t)(row * APCH + c * 8) * 2) =
                *(const uint4*)(qh + qbase + (size_t)row * HD + c * 8);
        }
    }
    __syncthreads();

    const int a_r = lane & 15;
    const int a_c = (lane >> 4) << 3;
    const int b_r = (lane & 7) + ((lane >> 4) << 3);
    const int b_c = ((lane >> 3) & 1) << 3;
    const int v_r = ((lane >> 3) & 1) * 8 + (lane & 7);
    const int v_c = (lane >> 4) << 3;
    const int mrow0 = wid * 16 + (lane >> 2);
    const int shl = 2 * (lane & 3);

    // hoist Q fragments for the whole K loop
    uint32_t qf[4][4];
#pragma unroll
    for (int dc = 0; dc < 4; dc++)
        LDSM4(qf[dc], smb + A_Q + ((wid * 16 + a_r) * APCH + dc * 16 + a_c) * 2);

    float oacc[8][4];
#pragma unroll
    for (int j = 0; j < 8; j++)
#pragma unroll
        for (int e = 0; e < 4; e++) oacc[j][e] = 0.f;
    float rsum0 = 0.f, rsum1 = 0.f;

    const size_t kvbase = (size_t)bh * SEQ * HD;
    // bit-packed mask: per q-row SEQ/32 = 64 words = 16 uint4; tile kt = uint4 #kt
    const uint4* mrow_base =
        (const uint4*)(maskb + ((size_t)b * SEQ + q0g) * (SEQ / 32));

    for (int kt = 0; kt < SEQ / KTILE; kt++) {
        __syncthreads();
        // stage K hi/lo, V (128x64) + bit-mask (128 rows x 16B)
        {
            const size_t tb = kvbase + (size_t)kt * KTILE * HD;
#pragma unroll
            for (int i = 0; i < 4; i++) {
                int lin = tid + i * 256;    // 0..1023
                int row = lin >> 3, c = lin & 7;
                size_t off = tb + (size_t)row * HD + c * 8;
                uint32_t doff = (uint32_t)(row * APCH + c * 8) * 2;
                *(uint4*)(sm + A_KH + doff) = *(const uint4*)(kh + off);
                *(uint4*)(sm + A_KL + doff) = *(const uint4*)(kl + off);
                *(uint4*)(sm + A_VH + doff) = *(const uint4*)(vh + off);
            }
            // row r's 64 words = 16 uint4; tile kt (128 bits) = uint4 index r*16+kt
            if (tid < 128)
                *(uint4*)(sm + A_MS + tid * 16) = mrow_base[(size_t)tid * 16 + kt];
        }
        __syncthreads();

        // per-thread mask words for this tile (2 q-rows x 128 k-bits)
        const uint4 mw0 = *(const uint4*)(sm + A_MS + mrow0 * 16);
        const uint4 mw1 = *(const uint4*)(sm + A_MS + (mrow0 + 8) * 16);

        // ---- interleaved S chunk -> T -> O chunk, per 16 k-rows -------------
#pragma unroll
        for (int nc = 0; nc < NCT; nc++) {
            float sc[2][4];
#pragma unroll
            for (int hf = 0; hf < 2; hf++)
#pragma unroll
                for (int e = 0; e < 4; e++) sc[hf][e] = 0.f;

#pragma unroll
            for (int dc = 0; dc < 4; dc++) {
                uint32_t khf[4], klf[4];
                uint32_t ka = smb + A_KH +
                    ((nc * 16 + b_r) * APCH + dc * 16 + b_c) * 2;
                LDSM4(khf, ka);
                LDSM4(klf, ka + (A_KL - A_KH));
#pragma unroll
                for (int hf = 0; hf < 2; hf++) {
                    MMA_F16(sc[hf], qf[dc], khf[2*hf], khf[2*hf+1]);
                    MMA_F16(sc[hf], qf[dc], klf[2*hf], klf[2*hf+1]);
                }
            }

            // mask + bias + relu^2, rowsum, T to single fp16 fragments
            uint32_t aph[4];
#pragma unroll
            for (int hf = 0; hf < 2; hf++) {
                const int base = nc * 16 + hf * 8;       // 0..120, const
                const uint32_t w0 = u4sel(mw0, base >> 5);
                const uint32_t w1 = u4sel(mw1, base >> 5);
                const int sh = (base & 31) + shl;
                float t0 = fmaxf(fmaf(sc[hf][0], 0.125f, bias), 0.f);
                float t1 = fmaxf(fmaf(sc[hf][1], 0.125f, bias), 0.f);
                float t2 = fmaxf(fmaf(sc[hf][2], 0.125f, bias), 0.f);
                float t3 = fmaxf(fmaf(sc[hf][3], 0.125f, bias), 0.f);
                if ((w0 >> sh) & 1u)       t0 = 0.f;
                if ((w0 >> (sh + 1)) & 1u) t1 = 0.f;
                if ((w1 >> sh) & 1u)       t2 = 0.f;
                if ((w1 >> (sh + 1)) & 1u) t3 = 0.f;
                t0 *= t0; t1 *= t1; t2 *= t2; t3 *= t3;
                rsum0 += t0 + t1;
                rsum1 += t2 + t3;
                aph[2*hf + 0] = cvt_h2(t0, t1);
                aph[2*hf + 1] = cvt_h2(t2, t3);
            }

            // O += T * V for this k-chunk (V via ldmatrix.trans)
#pragma unroll
            for (int dch = 0; dch < 4; dch++) {
                uint32_t vf[4];
                LDSM4T(vf, smb + A_VH +
                           ((nc * 16 + v_r) * APCH + dch * 16 + v_c) * 2);
#pragma unroll
                for (int hf = 0; hf < 2; hf++) {
                    int j = dch * 2 + hf;
                    MMA_F16(oacc[j], aph, vf[2*hf], vf[2*hf+1]);
                }
            }
        }
    }

    rsum0 += __shfl_xor_sync(0xffffffffu, rsum0, 1);
    rsum0 += __shfl_xor_sync(0xffffffffu, rsum0, 2);
    rsum1 += __shfl_xor_sync(0xffffffffu, rsum1, 1);
    rsum1 += __shfl_xor_sync(0xffffffffu, rsum1, 2);
    const float inv0 = 1.f / (rsum0 + 1e-32f);
    const float inv1 = 1.f / (rsum1 + 1e-32f);

    // store O (fp16) into [B, NQ, HSIZE] layout
    const int qr0 = q0g + mrow0;
#pragma unroll
    for (int j = 0; j < 8; j++) {
        int d = h * HD + j * 8 + 2 * (lane & 3);
        *(uint32_t*)(oh + (size_t)(b * SEQ + qr0) * NDIM + d) =
            cvt_h2(oacc[j][0] * inv0, oacc[j][1] * inv0);
        *(uint32_t*)(oh + (size_t)(b * SEQ + qr0 + 8) * NDIM + d) =
            cvt_h2(oacc[j][2] * inv1, oacc[j][3] * inv1);
    }
}

// ---------------- launcher ----------------------------------------------------
extern "C" void kernel_launch(void* const* d_in, const int* in_sizes, int n_in,
                              void* d_out, int out_size)
{
    const float* iQ      = (const float*)d_in[0];
    const float* iK      = (const float*)d_in[1];
    const float* iV      = (const float*)d_in[2];
    const void*  mask    = d_in[3];
    const float* Wq      = (const float*)d_in[4];
    const float* Wk      = (const float*)d_in[5];
    const float* Wv      = (const float*)d_in[6];
    const float* Wo      = (const float*)d_in[7];
    const float* sn_bias = (const float*)d_in[8];
    float*       out     = (float*)d_out;

    __half *xq, *xk, *xv, *ohb, *wqh, *wql, *wkh, *wkl, *wvh, *woh;
    __half *qh, *kh, *kl, *vh;
    uint32_t* gmb;
    cudaGetSymbolAddress((void**)&xq, g_xq);
    cudaGetSymbolAddress((void**)&xk, g_xk);
    cudaGetSymbolAddress((void**)&xv, g_xv);
    cudaGetSymbolAddress((void**)&ohb, g_oh);
    cudaGetSymbolAddress((void**)&wqh, g_wqh);
    cudaGetSymbolAddress((void**)&wql, g_wql);
    cudaGetSymbolAddress((void**)&wkh, g_wkh);
    cudaGetSymbolAddress((void**)&wkl, g_wkl);
    cudaGetSymbolAddress((void**)&wvh, g_wvh);
    cudaGetSymbolAddress((void**)&woh, g_woh);
    cudaGetSymbolAddress((void**)&qh, g_qh);
    cudaGetSymbolAddress((void**)&kh, g_kh);
    cudaGetSymbolAddress((void**)&kl, g_kl);
    cudaGetSymbolAddress((void**)&vh, g_vh);
    cudaGetSymbolAddress((void**)&gmb, g_maskb);

    cudaFuncSetAttribute(gemm_qkv,
                         cudaFuncAttributeMaxDynamicSharedMemorySize, GSMEM);
    cudaFuncSetAttribute(gemm_out,
                         cudaFuncAttributeMaxDynamicSharedMemorySize, GSMEM);
    cudaFuncSetAttribute(attn_f16,
                         cudaFuncAttributeMaxDynamicSharedMemorySize, A_BYTES);

    // mask dtype autodetect + bit-pack
    detect_mask_kernel<<<1, 256>>>((const unsigned int*)mask);
    convert_maskb<<<2048, 256>>>(mask, gmb);

    const size_t nA4 = (size_t)MDIM * KDIM / 4;
    const size_t nW4 = (size_t)NDIM * KDIM / 4;

    // merged converts (2 launches)
    convert_h3<<<4096, 256>>>((const float4*)iQ, (const float4*)iK,
                              (const float4*)iV,
                              (uint2*)xq, (uint2*)xk, (uint2*)xv, nA4);
    convert_w<<<2048, 256>>>((const float4*)Wq, (const float4*)Wk,
                             (const float4*)Wv, (const float4*)Wo,
                             (uint2*)wqh, (uint2*)wql, (uint2*)wkh, (uint2*)wkl,
                             (uint2*)wvh, (uint2*)woh, nW4);

    // merged Q/K/V projections: one launch, 1536 CTAs
    gemm_qkv<<<dim3(NDIM / 128, 192), 256, GSMEM>>>(
        xq, xk, xv, wqh, wql, wkh, wkl, wvh, qh, kh, kl, vh);

    attn_f16<<<dim3(SEQ / 128, NB * NH), 256, A_BYTES>>>(
        qh, kh, kl, vh, gmb, sn_bias, ohb);

    gemm_out<<<dim3(NDIM / 128, MDIM / 128), 256, GSMEM>>>(ohb, woh, out);
}

// round 16
// speedup vs baseline: 1.6277x; 1.1573x over previous
#include <cuda_runtime.h>
#include <cuda_fp16.h>
#include <cstdint>
#include <cstddef>

// Problem constants
#define SEQ   2048
#define NB    4
#define NH    16
#define HD    64
#define MDIM  8192     // NB*SEQ
#define NDIM  1024
#define KDIM  1024

// ---------------- scratch (static device globals: allocation-free) -------------
__device__ __half g_xq[(size_t)MDIM * KDIM];
__device__ __half g_xk[(size_t)MDIM * KDIM];
__device__ __half g_xv[(size_t)MDIM * KDIM];
__device__ __half g_oh[(size_t)MDIM * NDIM];
__device__ __half g_wqh[(size_t)NDIM * KDIM];
__device__ __half g_wql[(size_t)NDIM * KDIM];
__device__ __half g_wkh[(size_t)NDIM * KDIM];
__device__ __half g_wkl[(size_t)NDIM * KDIM];
__device__ __half g_wvh[(size_t)NDIM * KDIM];
__device__ __half g_woh[(size_t)NDIM * KDIM];
__device__ __half g_qh[(size_t)NB * NH * SEQ * HD];   // Q (single fp16)
__device__ __half g_kh[(size_t)NB * NH * SEQ * HD];   // K (single fp16)
__device__ __half g_vh[(size_t)NB * NH * SEQ * HD];   // V (single fp16)
__device__ uint32_t g_maskb[(size_t)NB * SEQ * SEQ / 32];  // bit-packed mask
__device__ int g_mode;                              // 0=u8, 1=i32, 2=f32

// ================= helpers =====================================================
__device__ __forceinline__ uint32_t smem_u32(const void* p) {
    uint32_t a;
    asm("{ .reg .u64 t; cvta.to.shared.u64 t, %1; cvt.u32.u64 %0, t; }"
        : "=r"(a) : "l"(p));
    return a;
}

__device__ __forceinline__ uint32_t pack_h2(__half a, __half b) {
    __half2 t;
    t.x = a; t.y = b;
    return *(uint32_t*)&t;
}

__device__ __forceinline__ uint32_t cvt_h2(float x0, float x1) {
    return pack_h2(__float2half_rn(x0), __float2half_rn(x1));
}

__device__ __forceinline__ void cvt_hl2(float x0, float x1,
                                        uint32_t& hp, uint32_t& lp) {
    __half h0 = __float2half_rn(x0), h1 = __float2half_rn(x1);
    hp = pack_h2(h0, h1);
    lp = pack_h2(__float2half_rn(x0 - __half2float(h0)),
                 __float2half_rn(x1 - __half2float(h1)));
}

__device__ __forceinline__ uint32_t u4sel(const uint4& v, int i) {
    return (i == 0) ? v.x : (i == 1) ? v.y : (i == 2) ? v.z : v.w;
}

#define LDSM4(r, a) \
    asm volatile("ldmatrix.sync.aligned.m8n8.x4.shared.b16 {%0,%1,%2,%3}, [%4];" \
        : "=r"((r)[0]), "=r"((r)[1]), "=r"((r)[2]), "=r"((r)[3]) : "r"(a))

#define LDSM4T(r, a) \
    asm volatile("ldmatrix.sync.aligned.m8n8.x4.trans.shared.b16 {%0,%1,%2,%3}, [%4];" \
        : "=r"((r)[0]), "=r"((r)[1]), "=r"((r)[2]), "=r"((r)[3]) : "r"(a))

#define MMA_F16(c, a, b0, b1) \
    asm volatile("mma.sync.aligned.m16n8k16.row.col.f32.f16.f16.f32 " \
        "{%0,%1,%2,%3}, {%4,%5,%6,%7}, {%8,%9}, {%0,%1,%2,%3};" \
        : "+f"((c)[0]), "+f"((c)[1]), "+f"((c)[2]), "+f"((c)[3]) \
        : "r"((a)[0]), "r"((a)[1]), "r"((a)[2]), "r"((a)[3]), "r"(b0), "r"(b1))

#define CP_A16(dst, src) \
    asm volatile("cp.async.cg.shared.global [%0], [%1], 16;" :: "r"(dst), "l"(src))
#define CP_COMMIT() asm volatile("cp.async.commit_group;" ::: "memory")
#define CP_WAIT1()  asm volatile("cp.async.wait_group 1;" ::: "memory")

// ---------------- mask dtype detection + bit-pack conversion -------------------
__global__ void detect_mask_kernel(const unsigned int* __restrict__ w)
{
    __shared__ int s_not_i32, s_not_u8;
    if (threadIdx.x == 0) { s_not_i32 = 0; s_not_u8 = 0; }
    __syncthreads();
    int not_i32 = 0, not_u8 = 0;
    for (int i = threadIdx.x; i < 65536; i += 256) {
        unsigned v = w[i];
        unsigned b0 = v & 255u, b1 = (v >> 8) & 255u,
                 b2 = (v >> 16) & 255u, b3 = v >> 24;
        if ((b1 | b2 | b3) != 0u || b0 > 1u) not_i32 = 1;
        if (b0 > 1u || b1 > 1u || b2 > 1u || b3 > 1u) not_u8 = 1;
    }
    if (not_i32) atomicOr(&s_not_i32, 1);
    if (not_u8)  atomicOr(&s_not_u8, 1);
    __syncthreads();
    if (threadIdx.x == 0)
        g_mode = (!s_not_i32) ? 1 : ((!s_not_u8) ? 0 : 2);
}

// build bit-packed mask: word w holds elements [32w, 32w+32), bit set = masked
__global__ void convert_maskb(const void* __restrict__ m, uint32_t* __restrict__ o)
{
    const int mode = g_mode;
    const size_t nw = (size_t)NB * SEQ * SEQ / 32;
    for (size_t w = (size_t)blockIdx.x * blockDim.x + threadIdx.x; w < nw;
         w += (size_t)gridDim.x * blockDim.x) {
        uint32_t bits = 0;
        if (mode == 1) {
            const uint4* p = (const uint4*)((const int*)m + w * 32);
#pragma unroll
            for (int g = 0; g < 8; g++) {
                uint4 v = p[g];
                bits |= (v.x ? 1u : 0u) << (g * 4 + 0);
                bits |= (v.y ? 1u : 0u) << (g * 4 + 1);
                bits |= (v.z ? 1u : 0u) << (g * 4 + 2);
                bits |= (v.w ? 1u : 0u) << (g * 4 + 3);
            }
        } else if (mode == 2) {
            const float4* p = (const float4*)((const float*)m + w * 32);
#pragma unroll
            for (int g = 0; g < 8; g++) {
                float4 v = p[g];
                bits |= (v.x != 0.f ? 1u : 0u) << (g * 4 + 0);
                bits |= (v.y != 0.f ? 1u : 0u) << (g * 4 + 1);
                bits |= (v.z != 0.f ? 1u : 0u) << (g * 4 + 2);
                bits |= (v.w != 0.f ? 1u : 0u) << (g * 4 + 3);
            }
        } else {
            const uint4* p = (const uint4*)((const unsigned char*)m + w * 32);
#pragma unroll
            for (int g = 0; g < 2; g++) {
                uint4 v = p[g];
                uint32_t ws[4] = {v.x, v.y, v.z, v.w};
#pragma unroll
                for (int q = 0; q < 4; q++)
#pragma unroll
                    for (int e = 0; e < 4; e++)
                        bits |= (((ws[q] >> (e * 8)) & 255u) ? 1u : 0u)
                                << (g * 16 + q * 4 + e);
            }
        }
        o[w] = bits;
    }
}

// ---------------- merged fp32 -> fp16 streaming converters ---------------------
__global__ void convert_h3(const float4* __restrict__ i0,
                           const float4* __restrict__ i1,
                           const float4* __restrict__ i2,
                           uint2* __restrict__ o0, uint2* __restrict__ o1,
                           uint2* __restrict__ o2, size_t n4)
{
    for (size_t i = (size_t)blockIdx.x * blockDim.x + threadIdx.x; i < 3 * n4;
         i += (size_t)gridDim.x * blockDim.x) {
        const float4* in = (i < n4) ? i0 : (i < 2 * n4) ? i1 : i2;
        uint2* out = (i < n4) ? o0 : (i < 2 * n4) ? o1 : o2;
        size_t j = (i < n4) ? i : (i < 2 * n4) ? i - n4 : i - 2 * n4;
        float4 x = in[j];
        out[j] = make_uint2(cvt_h2(x.x, x.y), cvt_h2(x.z, x.w));
    }
}

// Wq (hi+lo), Wk (hi+lo), Wv (hi only), Wo (hi only)
__global__ void convert_w(const float4* __restrict__ i0, const float4* __restrict__ i1,
                          const float4* __restrict__ i2, const float4* __restrict__ i3,
                          uint2* __restrict__ h0, uint2* __restrict__ l0,
                          uint2* __restrict__ h1, uint2* __restrict__ l1,
                          uint2* __restrict__ h2, uint2* __restrict__ h3,
                          size_t n4)
{
    for (size_t i = (size_t)blockIdx.x * blockDim.x + threadIdx.x; i < 4 * n4;
         i += (size_t)gridDim.x * blockDim.x) {
        int seg = (int)(i / n4);
        size_t j = i - (size_t)seg * n4;
        const float4* in = (seg == 0) ? i0 : (seg == 1) ? i1 : (seg == 2) ? i2 : i3;
        float4 x = in[j];
        if (seg < 2) {
            uint2* hh = (seg == 0) ? h0 : h1;
            uint2* ll = (seg == 0) ? l0 : l1;
            uint32_t a0, b0, a1, b1;
            cvt_hl2(x.x, x.y, a0, b0);
            cvt_hl2(x.z, x.w, a1, b1);
            hh[j] = make_uint2(a0, a1);
            ll[j] = make_uint2(b0, b1);
        } else {
            uint2* hh = (seg == 2) ? h2 : h3;
            hh[j] = make_uint2(cvt_h2(x.x, x.y), cvt_h2(x.z, x.w));
        }
    }
}

// ================= fp16 HMMA GEMM (GBK=64, 2-stage cp.async, 1/2-term) =========
#define GBK  64
#define NKT  (KDIM / GBK)     // 16
#define PADK 72               // fp16 pitch per row (144B, LDSM conflict-free)
#define T_A  0
#define T_WH 18432
#define T_WL 36864
#define STG_B 55296
#define GSMEM (2 * STG_B)     // 108 KB (x2 CTAs = 216 KB <= 228 KB/SM)

template <bool TWO_TERM>
__device__ __forceinline__ void gemm_body(
    const __half* __restrict__ Ah,
    const __half* __restrict__ Wh, const __half* __restrict__ Wl,
    float* __restrict__ Cf, __half* __restrict__ Ch,
    int mode, int m0, int n0, char* smc)
{
    const uint32_t smb = smem_u32(smc);
    const int tid  = threadIdx.x;
    const int lane = tid & 31, wid = tid >> 5;
    const int wm = wid & 3;
    const int wn = wid >> 2;

    const int row0 = tid >> 3;     // 0..31
    const int ch   = tid & 7;      // 16B chunk (8 fp16) within 64-col stage

    float acc[2][8][4];
#pragma unroll
    for (int i = 0; i < 2; i++)
#pragma unroll
        for (int j = 0; j < 8; j++)
#pragma unroll
            for (int q = 0; q < 4; q++) acc[i][j][q] = 0.f;

    auto issue = [&](int kt) {
        if (kt < NKT) {
            const int k0 = kt * GBK;
            const uint32_t sb = smb + (kt & 1) * STG_B;
#pragma unroll
            for (int g = 0; g < 4; g++) {
                int r = row0 + g * 32;
                uint32_t doff = (uint32_t)(r * PADK + ch * 8) * 2;
                const size_t asrc = (size_t)(m0 + r) * KDIM + k0 + ch * 8;
                const size_t wsrc = (size_t)(n0 + r) * KDIM + k0 + ch * 8;
                CP_A16(sb + T_A  + doff, Ah + asrc);
                CP_A16(sb + T_WH + doff, Wh + wsrc);
                if (TWO_TERM)
                    CP_A16(sb + T_WL + doff, Wl + wsrc);
            }
        }
        CP_COMMIT();
    };

    issue(0);
    issue(1);
    CP_WAIT1();
    __syncthreads();

    const int a_r = lane & 15;
    const int a_c = (lane >> 4) << 3;
    const int b_r = (lane & 7) + ((lane >> 4) << 3);
    const int b_c = ((lane >> 3) & 1) << 3;

    for (int kt = 0; kt < NKT; kt++) {
        const uint32_t sb = smb + (kt & 1) * STG_B;

#pragma unroll
        for (int ks = 0; ks < 4; ks++) {
            uint32_t af[2][4];
#pragma unroll
            for (int i = 0; i < 2; i++) {
                uint32_t off =
                    ((wm * 32 + i * 16 + a_r) * PADK + a_c + ks * 16) * 2;
                LDSM4(af[i], sb + T_A + off);
            }
#pragma unroll
            for (int p = 0; p < 4; p++) {
                uint32_t bh[4], bl[4];
                uint32_t off =
                    ((wn * 64 + p * 16 + b_r) * PADK + b_c + ks * 16) * 2;
                LDSM4(bh, sb + T_WH + off);
                if (TWO_TERM)
                    LDSM4(bl, sb + T_WL + off);
#pragma unroll
                for (int i = 0; i < 2; i++)
#pragma unroll
                    for (int hf = 0; hf < 2; hf++) {
                        int j = p * 2 + hf;
                        MMA_F16(acc[i][j], af[i], bh[2*hf], bh[2*hf+1]);
                        if (TWO_TERM)
                            MMA_F16(acc[i][j], af[i], bl[2*hf], bl[2*hf+1]);
                    }
            }
        }
        __syncthreads();
        issue(kt + 2);
        CP_WAIT1();
        __syncthreads();
    }

    // epilogue
#pragma unroll
    for (int i = 0; i < 2; i++) {
#pragma unroll
        for (int j = 0; j < 8; j++) {
            int mrow = m0 + wm * 32 + i * 16 + (lane >> 2);
            int ncol = n0 + wn * 64 + j * 8 + (lane & 3) * 2;
#pragma unroll
            for (int hf = 0; hf < 2; hf++) {
                int m = mrow + hf * 8;
                float v0 = acc[i][j][hf*2], v1 = acc[i][j][hf*2+1];
                if (mode == 0) {
                    *(float2*)(Cf + (size_t)m * NDIM + ncol) =
                        make_float2(v0, v1);
                } else {
                    int bb = m >> 11, s = m & 2047;
                    int hh = ncol >> 6, d = ncol & 63;
                    size_t off = ((size_t)(bb*NH + hh) * SEQ + s) * HD + d;
                    *(uint32_t*)(Ch + off) = cvt_h2(v0, v1);
                }
            }
        }
    }
}

// merged Q/K/V projection: grid.y = 192 (seg = y/64: 0=Q(2t), 1=K(2t), 2=V(1t))
// all outputs single fp16
__global__ void __launch_bounds__(256, 2)
gemm_qkv(const __half* __restrict__ xq, const __half* __restrict__ xk,
         const __half* __restrict__ xv,
         const __half* __restrict__ wqh, const __half* __restrict__ wql,
         const __half* __restrict__ wkh, const __half* __restrict__ wkl,
         const __half* __restrict__ wvh,
         __half* __restrict__ qh, __half* __restrict__ kh,
         __half* __restrict__ vh)
{
    extern __shared__ char smc[];
    const int seg = blockIdx.y >> 6;           // 0,1,2
    const int m0 = (blockIdx.y & 63) * 128;
    const int n0 = blockIdx.x * 128;
    if (seg == 0) {
        gemm_body<true>(xq, wqh, wql, nullptr, qh, 1, m0, n0, smc);
    } else if (seg == 1) {
        gemm_body<true>(xk, wkh, wkl, nullptr, kh, 1, m0, n0, smc);
    } else {
        gemm_body<false>(xv, wvh, nullptr, nullptr, vh, 1, m0, n0, smc);
    }
}

// output projection (fp32 out, 1-term)
__global__ void __launch_bounds__(256, 2)
gemm_out(const __half* __restrict__ Ah,
         const __half* __restrict__ Wh,
         float* __restrict__ Cf)
{
    extern __shared__ char smc[];
    gemm_body<false>(Ah, Wh, nullptr, Cf, nullptr, 0,
                     blockIdx.y * 128, blockIdx.x * 128, smc);
}

// ================= fp16 HMMA fused attention (KTILE=128, 1-term S and O) =======
// S = Qh*Kh ; T = relu(S/8+b)^2 (fp32) -> fp16 ; O += T*Vh
#define KTILE 128
#define NCT   (KTILE / 16)            // 8
#define APCH  72
#define A_Q   0
#define A_KH  (A_Q  + 128 * APCH * 2)   // 18432
#define A_VH  (A_KH + KTILE * APCH * 2) // 36864
#define A_MS  (A_VH + KTILE * APCH * 2) // 55296 (128 rows x 16B bit-mask)
#define A_BYTES (A_MS + 128 * 16)       // 57344

__global__ void __launch_bounds__(256, 2)
attn_f16(const __half* __restrict__ qh,
         const __half* __restrict__ kh,
         const __half* __restrict__ vh,
         const uint32_t* __restrict__ maskb,
         const float* __restrict__ sn_bias,
         __half* __restrict__ oh)
{
    extern __shared__ char sm[];
    const uint32_t smb = smem_u32(sm);
    const int tid  = threadIdx.x;
    const int lane = tid & 31, wid = tid >> 5;
    const int bh = blockIdx.y;
    const int b = bh >> 4, h = bh & 15;
    const int q0g = blockIdx.x * 128;
    const float bias = sn_bias[0];

    // stage Q tile [128 x 64] fp16
    {
        const size_t qbase = ((size_t)bh * SEQ + q0g) * HD;
#pragma unroll
        for (int i = 0; i < 4; i++) {
            int lin = tid + i * 256;        // 0..1023
            int row = lin >> 3, c = lin & 7;
            *(uint4*)(sm + A_Q + (uint32_t)(row * APCH + c * 8) * 2) =
                *(const uint4*)(qh + qbase + (size_t)row * HD + c * 8);
        }
    }
    __syncthreads();

    const int a_r = lane & 15;
    const int a_c = (lane >> 4) << 3;
    const int b_r = (lane & 7) + ((lane >> 4) << 3);
    const int b_c = ((lane >> 3) & 1) << 3;
    const int v_r = ((lane >> 3) & 1) * 8 + (lane & 7);
    const int v_c = (lane >> 4) << 3;
    const int mrow0 = wid * 16 + (lane >> 2);
    const int shl = 2 * (lane & 3);

    // hoist Q fragments for the whole K loop
    uint32_t qf[4][4];
#pragma unroll
    for (int dc = 0; dc < 4; dc++)
        LDSM4(qf[dc], smb + A_Q + ((wid * 16 + a_r) * APCH + dc * 16 + a_c) * 2);

    float oacc[8][4];
#pragma unroll
    for (int j = 0; j < 8; j++)
#pragma unroll
        for (int e = 0; e < 4; e++) oacc[j][e] = 0.f;
    float rsum0 = 0.f, rsum1 = 0.f;

    const size_t kvbase = (size_t)bh * SEQ * HD;
    // bit-packed mask: per q-row SEQ/32 = 64 words = 16 uint4; tile kt = uint4 #kt
    const uint4* mrow_base =
        (const uint4*)(maskb + ((size_t)b * SEQ + q0g) * (SEQ / 32));

    for (int kt = 0; kt < SEQ / KTILE; kt++) {
        __syncthreads();
        // stage K, V (128x64) + bit-mask (128 rows x 16B)
        {
            const size_t tb = kvbase + (size_t)kt * KTILE * HD;
#pragma unroll
            for (int i = 0; i < 4; i++) {
                int lin = tid + i * 256;    // 0..1023
                int row = lin >> 3, c = lin & 7;
                size_t off = tb + (size_t)row * HD + c * 8;
                uint32_t doff = (uint32_t)(row * APCH + c * 8) * 2;
                *(uint4*)(sm + A_KH + doff) = *(const uint4*)(kh + off);
                *(uint4*)(sm + A_VH + doff) = *(const uint4*)(vh + off);
            }
            // row r's 64 words = 16 uint4; tile kt (128 bits) = uint4 index r*16+kt
            if (tid < 128)
                *(uint4*)(sm + A_MS + tid * 16) = mrow_base[(size_t)tid * 16 + kt];
        }
        __syncthreads();

        // per-thread mask words for this tile (2 q-rows x 128 k-bits)
        const uint4 mw0 = *(const uint4*)(sm + A_MS + mrow0 * 16);
        const uint4 mw1 = *(const uint4*)(sm + A_MS + (mrow0 + 8) * 16);

        // ---- interleaved S chunk -> T -> O chunk, per 16 k-rows -------------
#pragma unroll
        for (int nc = 0; nc < NCT; nc++) {
            float sc[2][4];
#pragma unroll
            for (int hf = 0; hf < 2; hf++)
#pragma unroll
                for (int e = 0; e < 4; e++) sc[hf][e] = 0.f;

#pragma unroll
            for (int dc = 0; dc < 4; dc++) {
                uint32_t khf[4];
                uint32_t ka = smb + A_KH +
                    ((nc * 16 + b_r) * APCH + dc * 16 + b_c) * 2;
                LDSM4(khf, ka);
#pragma unroll
                for (int hf = 0; hf < 2; hf++)
                    MMA_F16(sc[hf], qf[dc], khf[2*hf], khf[2*hf+1]);
            }

            // mask + bias + relu^2, rowsum, T to single fp16 fragments
            uint32_t aph[4];
#pragma unroll
            for (int hf = 0; hf < 2; hf++) {
                const int base = nc * 16 + hf * 8;       // 0..120, const
                const uint32_t w0 = u4sel(mw0, base >> 5);
                const uint32_t w1 = u4sel(mw1, base >> 5);
                const int sh = (base & 31) + shl;
                float t0 = fmaxf(fmaf(sc[hf][0], 0.125f, bias), 0.f);
                float t1 = fmaxf(fmaf(sc[hf][1], 0.125f, bias), 0.f);
                float t2 = fmaxf(fmaf(sc[hf][2], 0.125f, bias), 0.f);
                float t3 = fmaxf(fmaf(sc[hf][3], 0.125f, bias), 0.f);
                if ((w0 >> sh) & 1u)       t0 = 0.f;
                if ((w0 >> (sh + 1)) & 1u) t1 = 0.f;
                if ((w1 >> sh) & 1u)       t2 = 0.f;
                if ((w1 >> (sh + 1)) & 1u) t3 = 0.f;
                t0 *= t0; t1 *= t1; t2 *= t2; t3 *= t3;
                rsum0 += t0 + t1;
                rsum1 += t2 + t3;
                aph[2*hf + 0] = cvt_h2(t0, t1);
                aph[2*hf + 1] = cvt_h2(t2, t3);
            }

            // O += T * V for this k-chunk (V via ldmatrix.trans)
#pragma unroll
            for (int dch = 0; dch < 4; dch++) {
                uint32_t vf[4];
                LDSM4T(vf, smb + A_VH +
                           ((nc * 16 + v_r) * APCH + dch * 16 + v_c) * 2);
#pragma unroll
                for (int hf = 0; hf < 2; hf++) {
                    int j = dch * 2 + hf;
                    MMA_F16(oacc[j], aph, vf[2*hf], vf[2*hf+1]);
                }
            }
        }
    }

    rsum0 += __shfl_xor_sync(0xffffffffu, rsum0, 1);
    rsum0 += __shfl_xor_sync(0xffffffffu, rsum0, 2);
    rsum1 += __shfl_xor_sync(0xffffffffu, rsum1, 1);
    rsum1 += __shfl_xor_sync(0xffffffffu, rsum1, 2);
    const float inv0 = 1.f / (rsum0 + 1e-32f);
    const float inv1 = 1.f / (rsum1 + 1e-32f);

    // store O (fp16) into [B, NQ, HSIZE] layout
    const int qr0 = q0g + mrow0;
#pragma unroll
    for (int j = 0; j < 8; j++) {
        int d = h * HD + j * 8 + 2 * (lane & 3);
        *(uint32_t*)(oh + (size_t)(b * SEQ + qr0) * NDIM + d) =
            cvt_h2(oacc[j][0] * inv0, oacc[j][1] * inv0);
        *(uint32_t*)(oh + (size_t)(b * SEQ + qr0 + 8) * NDIM + d) =
            cvt_h2(oacc[j][2] * inv1, oacc[j][3] * inv1);
    }
}

// ---------------- launcher ----------------------------------------------------
extern "C" void kernel_launch(void* const* d_in, const int* in_sizes, int n_in,
                              void* d_out, int out_size)
{
    const float* iQ      = (const float*)d_in[0];
    const float* iK      = (const float*)d_in[1];
    const float* iV      = (const float*)d_in[2];
    const void*  mask    = d_in[3];
    const float* Wq      = (const float*)d_in[4];
    const float* Wk      = (const float*)d_in[5];
    const float* Wv      = (const float*)d_in[6];
    const float* Wo      = (const float*)d_in[7];
    const float* sn_bias = (const float*)d_in[8];
    float*       out     = (float*)d_out;

    __half *xq, *xk, *xv, *ohb, *wqh, *wql, *wkh, *wkl, *wvh, *woh;
    __half *qh, *kh, *vh;
    uint32_t* gmb;
    cudaGetSymbolAddress((void**)&xq, g_xq);
    cudaGetSymbolAddress((void**)&xk, g_xk);
    cudaGetSymbolAddress((void**)&xv, g_xv);
    cudaGetSymbolAddress((void**)&ohb, g_oh);
    cudaGetSymbolAddress((void**)&wqh, g_wqh);
    cudaGetSymbolAddress((void**)&wql, g_wql);
    cudaGetSymbolAddress((void**)&wkh, g_wkh);
    cudaGetSymbolAddress((void**)&wkl, g_wkl);
    cudaGetSymbolAddress((void**)&wvh, g_wvh);
    cudaGetSymbolAddress((void**)&woh, g_woh);
    cudaGetSymbolAddress((void**)&qh, g_qh);
    cudaGetSymbolAddress((void**)&kh, g_kh);
    cudaGetSymbolAddress((void**)&vh, g_vh);
    cudaGetSymbolAddress((void**)&gmb, g_maskb);

    cudaFuncSetAttribute(gemm_qkv,
                         cudaFuncAttributeMaxDynamicSharedMemorySize, GSMEM);
    cudaFuncSetAttribute(gemm_out,
                         cudaFuncAttributeMaxDynamicSharedMemorySize, GSMEM);
    cudaFuncSetAttribute(attn_f16,
                         cudaFuncAttributeMaxDynamicSharedMemorySize, A_BYTES);

    // mask dtype autodetect + bit-pack
    detect_mask_kernel<<<1, 256>>>((const unsigned int*)mask);
    convert_maskb<<<2048, 256>>>(mask, gmb);

    const size_t nA4 = (size_t)MDIM * KDIM / 4;
    const size_t nW4 = (size_t)NDIM * KDIM / 4;

    // merged converts (2 launches)
    convert_h3<<<4096, 256>>>((const float4*)iQ, (const float4*)iK,
                              (const float4*)iV,
                              (uint2*)xq, (uint2*)xk, (uint2*)xv, nA4);
    convert_w<<<2048, 256>>>((const float4*)Wq, (const float4*)Wk,
                             (const float4*)Wv, (const float4*)Wo,
                             (uint2*)wqh, (uint2*)wql, (uint2*)wkh, (uint2*)wkl,
                             (uint2*)wvh, (uint2*)woh, nW4);

    // merged Q/K/V projections: one launch, 1536 CTAs
    gemm_qkv<<<dim3(NDIM / 128, 192), 256, GSMEM>>>(
        xq, xk, xv, wqh, wql, wkh, wkl, wvh, qh, kh, vh);

    attn_f16<<<dim3(SEQ / 128, NB * NH), 256, A_BYTES>>>(
        qh, kh, vh, gmb, sn_bias, ohb);

    gemm_out<<<dim3(NDIM / 128, MDIM / 128), 256, GSMEM>>>(ohb, woh, out);
}

// round 17
// speedup vs baseline: 1.7136x; 1.0528x over previous
#include <cuda_runtime.h>
#include <cuda_fp16.h>
#include <cstdint>
#include <cstddef>

// Problem constants
#define SEQ   2048
#define NB    4
#define NH    16
#define HD    64
#define MDIM  8192     // NB*SEQ
#define NDIM  1024
#define KDIM  1024

// ---------------- scratch (static device globals: allocation-free) -------------
__device__ __half g_xq[(size_t)MDIM * KDIM];
__device__ __half g_xk[(size_t)MDIM * KDIM];
__device__ __half g_xv[(size_t)MDIM * KDIM];
__device__ __half g_oh[(size_t)MDIM * NDIM];
__device__ __half g_wqh[(size_t)NDIM * KDIM];
__device__ __half g_wql[(size_t)NDIM * KDIM];
__device__ __half g_wkh[(size_t)NDIM * KDIM];
__device__ __half g_wvh[(size_t)NDIM * KDIM];
__device__ __half g_woh[(size_t)NDIM * KDIM];
__device__ __half g_qh[(size_t)NB * NH * SEQ * HD];   // Q (single fp16)
__device__ __half g_kh[(size_t)NB * NH * SEQ * HD];   // K (single fp16)
__device__ __half g_vh[(size_t)NB * NH * SEQ * HD];   // V (single fp16)
__device__ uint32_t g_maskb[(size_t)NB * SEQ * SEQ / 32];  // bit-packed mask
__device__ int g_mode;                              // 0=u8, 1=i32, 2=f32

// ================= helpers =====================================================
__device__ __forceinline__ uint32_t smem_u32(const void* p) {
    uint32_t a;
    asm("{ .reg .u64 t; cvta.to.shared.u64 t, %1; cvt.u32.u64 %0, t; }"
        : "=r"(a) : "l"(p));
    return a;
}

__device__ __forceinline__ uint32_t pack_h2(__half a, __half b) {
    __half2 t;
    t.x = a; t.y = b;
    return *(uint32_t*)&t;
}

__device__ __forceinline__ uint32_t cvt_h2(float x0, float x1) {
    return pack_h2(__float2half_rn(x0), __float2half_rn(x1));
}

__device__ __forceinline__ void cvt_hl2(float x0, float x1,
                                        uint32_t& hp, uint32_t& lp) {
    __half h0 = __float2half_rn(x0), h1 = __float2half_rn(x1);
    hp = pack_h2(h0, h1);
    lp = pack_h2(__float2half_rn(x0 - __half2float(h0)),
                 __float2half_rn(x1 - __half2float(h1)));
}

__device__ __forceinline__ uint32_t u4sel(const uint4& v, int i) {
    return (i == 0) ? v.x : (i == 1) ? v.y : (i == 2) ? v.z : v.w;
}

#define LDSM4(r, a) \
    asm volatile("ldmatrix.sync.aligned.m8n8.x4.shared.b16 {%0,%1,%2,%3}, [%4];" \
        : "=r"((r)[0]), "=r"((r)[1]), "=r"((r)[2]), "=r"((r)[3]) : "r"(a))

#define LDSM4T(r, a) \
    asm volatile("ldmatrix.sync.aligned.m8n8.x4.trans.shared.b16 {%0,%1,%2,%3}, [%4];" \
        : "=r"((r)[0]), "=r"((r)[1]), "=r"((r)[2]), "=r"((r)[3]) : "r"(a))

#define MMA_F16(c, a, b0, b1) \
    asm volatile("mma.sync.aligned.m16n8k16.row.col.f32.f16.f16.f32 " \
        "{%0,%1,%2,%3}, {%4,%5,%6,%7}, {%8,%9}, {%0,%1,%2,%3};" \
        : "+f"((c)[0]), "+f"((c)[1]), "+f"((c)[2]), "+f"((c)[3]) \
        : "r"((a)[0]), "r"((a)[1]), "r"((a)[2]), "r"((a)[3]), "r"(b0), "r"(b1))

#define CP_A16(dst, src) \
    asm volatile("cp.async.cg.shared.global [%0], [%1], 16;" :: "r"(dst), "l"(src))
#define CP_COMMIT() asm volatile("cp.async.commit_group;" ::: "memory")
#define CP_WAIT1()  asm volatile("cp.async.wait_group 1;" ::: "memory")

// ---------------- mask dtype detection + bit-pack conversion -------------------
__global__ void detect_mask_kernel(const unsigned int* __restrict__ w)
{
    __shared__ int s_not_i32, s_not_u8;
    if (threadIdx.x == 0) { s_not_i32 = 0; s_not_u8 = 0; }
    __syncthreads();
    int not_i32 = 0, not_u8 = 0;
    for (int i = threadIdx.x; i < 65536; i += 256) {
        unsigned v = w[i];
        unsigned b0 = v & 255u, b1 = (v >> 8) & 255u,
                 b2 = (v >> 16) & 255u, b3 = v >> 24;
        if ((b1 | b2 | b3) != 0u || b0 > 1u) not_i32 = 1;
        if (b0 > 1u || b1 > 1u || b2 > 1u || b3 > 1u) not_u8 = 1;
    }
    if (not_i32) atomicOr(&s_not_i32, 1);
    if (not_u8)  atomicOr(&s_not_u8, 1);
    __syncthreads();
    if (threadIdx.x == 0)
        g_mode = (!s_not_i32) ? 1 : ((!s_not_u8) ? 0 : 2);
}

// build bit-packed mask: word w holds elements [32w, 32w+32), bit set = masked
__global__ void convert_maskb(const void* __restrict__ m, uint32_t* __restrict__ o)
{
    const int mode = g_mode;
    const size_t nw = (size_t)NB * SEQ * SEQ / 32;
    for (size_t w = (size_t)blockIdx.x * blockDim.x + threadIdx.x; w < nw;
         w += (size_t)gridDim.x * blockDim.x) {
        uint32_t bits = 0;
        if (mode == 1) {
            const uint4* p = (const uint4*)((const int*)m + w * 32);
#pragma unroll
            for (int g = 0; g < 8; g++) {
                uint4 v = p[g];
                bits |= (v.x ? 1u : 0u) << (g * 4 + 0);
                bits |= (v.y ? 1u : 0u) << (g * 4 + 1);
                bits |= (v.z ? 1u : 0u) << (g * 4 + 2);
                bits |= (v.w ? 1u : 0u) << (g * 4 + 3);
            }
        } else if (mode == 2) {
            const float4* p = (const float4*)((const float*)m + w * 32);
#pragma unroll
            for (int g = 0; g < 8; g++) {
                float4 v = p[g];
                bits |= (v.x != 0.f ? 1u : 0u) << (g * 4 + 0);
                bits |= (v.y != 0.f ? 1u : 0u) << (g * 4 + 1);
                bits |= (v.z != 0.f ? 1u : 0u) << (g * 4 + 2);
                bits |= (v.w != 0.f ? 1u : 0u) << (g * 4 + 3);
            }
        } else {
            const uint4* p = (const uint4*)((const unsigned char*)m + w * 32);
#pragma unroll
            for (int g = 0; g < 2; g++) {
                uint4 v = p[g];
                uint32_t ws[4] = {v.x, v.y, v.z, v.w};
#pragma unroll
                for (int q = 0; q < 4; q++)
#pragma unroll
                    for (int e = 0; e < 4; e++)
                        bits |= (((ws[q] >> (e * 8)) & 255u) ? 1u : 0u)
                                << (g * 16 + q * 4 + e);
            }
        }
        o[w] = bits;
    }
}

// ---------------- merged fp32 -> fp16 streaming converters ---------------------
__global__ void convert_h3(const float4* __restrict__ i0,
                           const float4* __restrict__ i1,
                           const float4* __restrict__ i2,
                           uint2* __restrict__ o0, uint2* __restrict__ o1,
                           uint2* __restrict__ o2, size_t n4)
{
    for (size_t i = (size_t)blockIdx.x * blockDim.x + threadIdx.x; i < 3 * n4;
         i += (size_t)gridDim.x * blockDim.x) {
        const float4* in = (i < n4) ? i0 : (i < 2 * n4) ? i1 : i2;
        uint2* out = (i < n4) ? o0 : (i < 2 * n4) ? o1 : o2;
        size_t j = (i < n4) ? i : (i < 2 * n4) ? i - n4 : i - 2 * n4;
        float4 x = in[j];
        out[j] = make_uint2(cvt_h2(x.x, x.y), cvt_h2(x.z, x.w));
    }
}

// Wq (hi+lo), Wk (hi only), Wv (hi only), Wo (hi only)
__global__ void convert_w(const float4* __restrict__ i0, const float4* __restrict__ i1,
                          const float4* __restrict__ i2, const float4* __restrict__ i3,
                          uint2* __restrict__ h0, uint2* __restrict__ l0,
                          uint2* __restrict__ h1, uint2* __restrict__ h2,
                          uint2* __restrict__ h3,
                          size_t n4)
{
    for (size_t i = (size_t)blockIdx.x * blockDim.x + threadIdx.x; i < 4 * n4;
         i += (size_t)gridDim.x * blockDim.x) {
        int seg = (int)(i / n4);
        size_t j = i - (size_t)seg * n4;
        const float4* in = (seg == 0) ? i0 : (seg == 1) ? i1 : (seg == 2) ? i2 : i3;
        float4 x = in[j];
        if (seg == 0) {
            uint32_t a0, b0, a1, b1;
            cvt_hl2(x.x, x.y, a0, b0);
            cvt_hl2(x.z, x.w, a1, b1);
            h0[j] = make_uint2(a0, a1);
            l0[j] = make_uint2(b0, b1);
        } else {
            uint2* hh = (seg == 1) ? h1 : (seg == 2) ? h2 : h3;
            hh[j] = make_uint2(cvt_h2(x.x, x.y), cvt_h2(x.z, x.w));
        }
    }
}

// ================= fp16 HMMA GEMM (GBK=64, 2-stage cp.async, 1/2-term) =========
#define GBK  64
#define NKT  (KDIM / GBK)     // 16
#define PADK 72               // fp16 pitch per row (144B, LDSM conflict-free)
#define T_A  0
#define T_WH 18432
#define T_WL 36864
#define STG_B 55296
#define GSMEM (2 * STG_B)     // 108 KB (x2 CTAs = 216 KB <= 228 KB/SM)

template <bool TWO_TERM>
__device__ __forceinline__ void gemm_body(
    const __half* __restrict__ Ah,
    const __half* __restrict__ Wh, const __half* __restrict__ Wl,
    float* __restrict__ Cf, __half* __restrict__ Ch,
    int mode, int m0, int n0, char* smc)
{
    const uint32_t smb = smem_u32(smc);
    const int tid  = threadIdx.x;
    const int lane = tid & 31, wid = tid >> 5;
    const int wm = wid & 3;
    const int wn = wid >> 2;

    const int row0 = tid >> 3;     // 0..31
    const int ch   = tid & 7;      // 16B chunk (8 fp16) within 64-col stage

    float acc[2][8][4];
#pragma unroll
    for (int i = 0; i < 2; i++)
#pragma unroll
        for (int j = 0; j < 8; j++)
#pragma unroll
            for (int q = 0; q < 4; q++) acc[i][j][q] = 0.f;

    auto issue = [&](int kt) {
        if (kt < NKT) {
            const int k0 = kt * GBK;
            const uint32_t sb = smb + (kt & 1) * STG_B;
#pragma unroll
            for (int g = 0; g < 4; g++) {
                int r = row0 + g * 32;
                uint32_t doff = (uint32_t)(r * PADK + ch * 8) * 2;
                const size_t asrc = (size_t)(m0 + r) * KDIM + k0 + ch * 8;
                const size_t wsrc = (size_t)(n0 + r) * KDIM + k0 + ch * 8;
                CP_A16(sb + T_A  + doff, Ah + asrc);
                CP_A16(sb + T_WH + doff, Wh + wsrc);
                if (TWO_TERM)
                    CP_A16(sb + T_WL + doff, Wl + wsrc);
            }
        }
        CP_COMMIT();
    };

    issue(0);
    issue(1);
    CP_WAIT1();
    __syncthreads();

    const int a_r = lane & 15;
    const int a_c = (lane >> 4) << 3;
    const int b_r = (lane & 7) + ((lane >> 4) << 3);
    const int b_c = ((lane >> 3) & 1) << 3;

    for (int kt = 0; kt < NKT; kt++) {
        const uint32_t sb = smb + (kt & 1) * STG_B;

#pragma unroll
        for (int ks = 0; ks < 4; ks++) {
            uint32_t af[2][4];
#pragma unroll
            for (int i = 0; i < 2; i++) {
                uint32_t off =
                    ((wm * 32 + i * 16 + a_r) * PADK + a_c + ks * 16) * 2;
                LDSM4(af[i], sb + T_A + off);
            }
#pragma unroll
            for (int p = 0; p < 4; p++) {
                uint32_t bh[4], bl[4];
                uint32_t off =
                    ((wn * 64 + p * 16 + b_r) * PADK + b_c + ks * 16) * 2;
                LDSM4(bh, sb + T_WH + off);
                if (TWO_TERM)
                    LDSM4(bl, sb + T_WL + off);
#pragma unroll
                for (int i = 0; i < 2; i++)
#pragma unroll
                    for (int hf = 0; hf < 2; hf++) {
                        int j = p * 2 + hf;
                        MMA_F16(acc[i][j], af[i], bh[2*hf], bh[2*hf+1]);
                        if (TWO_TERM)
                            MMA_F16(acc[i][j], af[i], bl[2*hf], bl[2*hf+1]);
                    }
            }
        }
        __syncthreads();
        issue(kt + 2);
        CP_WAIT1();
        __syncthreads();
    }

    // epilogue
#pragma unroll
    for (int i = 0; i < 2; i++) {
#pragma unroll
        for (int j = 0; j < 8; j++) {
            int mrow = m0 + wm * 32 + i * 16 + (lane >> 2);
            int ncol = n0 + wn * 64 + j * 8 + (lane & 3) * 2;
#pragma unroll
            for (int hf = 0; hf < 2; hf++) {
                int m = mrow + hf * 8;
                float v0 = acc[i][j][hf*2], v1 = acc[i][j][hf*2+1];
                if (mode == 0) {
                    *(float2*)(Cf + (size_t)m * NDIM + ncol) =
                        make_float2(v0, v1);
                } else {
                    int bb = m >> 11, s = m & 2047;
                    int hh = ncol >> 6, d = ncol & 63;
                    size_t off = ((size_t)(bb*NH + hh) * SEQ + s) * HD + d;
                    *(uint32_t*)(Ch + off) = cvt_h2(v0, v1);
                }
            }
        }
    }
}

// merged Q/K/V projection: grid.y = 192 (seg = y/64: 0=Q(2t), 1=K(1t), 2=V(1t))
// all outputs single fp16
__global__ void __launch_bounds__(256, 2)
gemm_qkv(const __half* __restrict__ xq, const __half* __restrict__ xk,
         const __half* __restrict__ xv,
         const __half* __restrict__ wqh, const __half* __restrict__ wql,
         const __half* __restrict__ wkh,
         const __half* __restrict__ wvh,
         __half* __restrict__ qh, __half* __restrict__ kh,
         __half* __restrict__ vh)
{
    extern __shared__ char smc[];
    const int seg = blockIdx.y >> 6;           // 0,1,2
    const int m0 = (blockIdx.y & 63) * 128;
    const int n0 = blockIdx.x * 128;
    if (seg == 0) {
        gemm_body<true>(xq, wqh, wql, nullptr, qh, 1, m0, n0, smc);
    } else if (seg == 1) {
        gemm_body<false>(xk, wkh, nullptr, nullptr, kh, 1, m0, n0, smc);
    } else {
        gemm_body<false>(xv, wvh, nullptr, nullptr, vh, 1, m0, n0, smc);
    }
}

// output projection (fp32 out, 1-term)
__global__ void __launch_bounds__(256, 2)
gemm_out(const __half* __restrict__ Ah,
         const __half* __restrict__ Wh,
         float* __restrict__ Cf)
{
    extern __shared__ char smc[];
    gemm_body<false>(Ah, Wh, nullptr, Cf, nullptr, 0,
                     blockIdx.y * 128, blockIdx.x * 128, smc);
}

// ================= fp16 HMMA fused attention (KTILE=128, 1-term S and O) =======
// S = Qh*Kh ; T = relu(S/8+b)^2 (fp32) -> fp16 ; O += T*Vh
#define KTILE 128
#define NCT   (KTILE / 16)            // 8
#define APCH  72
#define A_Q   0
#define A_KH  (A_Q  + 128 * APCH * 2)   // 18432
#define A_VH  (A_KH + KTILE * APCH * 2) // 36864
#define A_MS  (A_VH + KTILE * APCH * 2) // 55296 (128 rows x 16B bit-mask)
#define A_BYTES (A_MS + 128 * 16)       // 57344

__global__ void __launch_bounds__(256, 2)
attn_f16(const __half* __restrict__ qh,
         const __half* __restrict__ kh,
         const __half* __restrict__ vh,
         const uint32_t* __restrict__ maskb,
         const float* __restrict__ sn_bias,
         __half* __restrict__ oh)
{
    extern __shared__ char sm[];
    const uint32_t smb = smem_u32(sm);
    const int tid  = threadIdx.x;
    const int lane = tid & 31, wid = tid >> 5;
    const int bh = blockIdx.y;
    const int b = bh >> 4, h = bh & 15;
    const int q0g = blockIdx.x * 128;
    const float bias = sn_bias[0];

    // stage Q tile [128 x 64] fp16
    {
        const size_t qbase = ((size_t)bh * SEQ + q0g) * HD;
#pragma unroll
        for (int i = 0; i < 4; i++) {
            int lin = tid + i * 256;        // 0..1023
            int row = lin >> 3, c = lin & 7;
            *(uint4*)(sm + A_Q + (uint32_t)(row * APCH + c * 8) * 2) =
                *(const uint4*)(qh + qbase + (size_t)row * HD + c * 8);
        }
    }
    __syncthreads();

    const int a_r = lane & 15;
    const int a_c = (lane >> 4) << 3;
    const int b_r = (lane & 7) + ((lane >> 4) << 3);
    const int b_c = ((lane >> 3) & 1) << 3;
    const int v_r = ((lane >> 3) & 1) * 8 + (lane & 7);
    const int v_c = (lane >> 4) << 3;
    const int mrow0 = wid * 16 + (lane >> 2);
    const int shl = 2 * (lane & 3);

    // hoist Q fragments for the whole K loop
    uint32_t qf[4][4];
#pragma unroll
    for (int dc = 0; dc < 4; dc++)
        LDSM4(qf[dc], smb + A_Q + ((wid * 16 + a_r) * APCH + dc * 16 + a_c) * 2);

    float oacc[8][4];
#pragma unroll
    for (int j = 0; j < 8; j++)
#pragma unroll
        for (int e = 0; e < 4; e++) oacc[j][e] = 0.f;
    float rsum0 = 0.f, rsum1 = 0.f;

    const size_t kvbase = (size_t)bh * SEQ * HD;
    // bit-packed mask: per q-row SEQ/32 = 64 words = 16 uint4; tile kt = uint4 #kt
    const uint4* mrow_base =
        (const uint4*)(maskb + ((size_t)b * SEQ + q0g) * (SEQ / 32));

    for (int kt = 0; kt < SEQ / KTILE; kt++) {
        __syncthreads();
        // stage K, V (128x64) + bit-mask (128 rows x 16B)
        {
            const size_t tb = kvbase + (size_t)kt * KTILE * HD;
#pragma unroll
            for (int i = 0; i < 4; i++) {
                int lin = tid + i * 256;    // 0..1023
                int row = lin >> 3, c = lin & 7;
                size_t off = tb + (size_t)row * HD + c * 8;
                uint32_t doff = (uint32_t)(row * APCH + c * 8) * 2;
                *(uint4*)(sm + A_KH + doff) = *(const uint4*)(kh + off);
                *(uint4*)(sm + A_VH + doff) = *(const uint4*)(vh + off);
            }
            // row r's 64 words = 16 uint4; tile kt (128 bits) = uint4 index r*16+kt
            if (tid < 128)
                *(uint4*)(sm + A_MS + tid * 16) = mrow_base[(size_t)tid * 16 + kt];
        }
        __syncthreads();

        // per-thread mask words for this tile (2 q-rows x 128 k-bits)
        const uint4 mw0 = *(const uint4*)(sm + A_MS + mrow0 * 16);
        const uint4 mw1 = *(const uint4*)(sm + A_MS + (mrow0 + 8) * 16);

        // ---- interleaved S chunk -> T -> O chunk, per 16 k-rows -------------
#pragma unroll
        for (int nc = 0; nc < NCT; nc++) {
            float sc[2][4];
#pragma unroll
            for (int hf = 0; hf < 2; hf++)
#pragma unroll
                for (int e = 0; e < 4; e++) sc[hf][e] = 0.f;

#pragma unroll
            for (int dc = 0; dc < 4; dc++) {
                uint32_t khf[4];
                uint32_t ka = smb + A_KH +
                    ((nc * 16 + b_r) * APCH + dc * 16 + b_c) * 2;
                LDSM4(khf, ka);
#pragma unroll
                for (int hf = 0; hf < 2; hf++)
                    MMA_F16(sc[hf], qf[dc], khf[2*hf], khf[2*hf+1]);
            }

            // mask + bias + relu^2, rowsum, T to single fp16 fragments
            uint32_t aph[4];
#pragma unroll
            for (int hf = 0; hf < 2; hf++) {
                const int base = nc * 16 + hf * 8;       // 0..120, const
                const uint32_t w0 = u4sel(mw0, base >> 5);
                const uint32_t w1 = u4sel(mw1, base >> 5);
                const int sh = (base & 31) + shl;
                float t0 = fmaxf(fmaf(sc[hf][0], 0.125f, bias), 0.f);
                float t1 = fmaxf(fmaf(sc[hf][1], 0.125f, bias), 0.f);
                float t2 = fmaxf(fmaf(sc[hf][2], 0.125f, bias), 0.f);
                float t3 = fmaxf(fmaf(sc[hf][3], 0.125f, bias), 0.f);
                if ((w0 >> sh) & 1u)       t0 = 0.f;
                if ((w0 >> (sh + 1)) & 1u) t1 = 0.f;
                if ((w1 >> sh) & 1u)       t2 = 0.f;
                if ((w1 >> (sh + 1)) & 1u) t3 = 0.f;
                t0 *= t0; t1 *= t1; t2 *= t2; t3 *= t3;
                rsum0 += t0 + t1;
                rsum1 += t2 + t3;
                aph[2*hf + 0] = cvt_h2(t0, t1);
                aph[2*hf + 1] = cvt_h2(t2, t3);
            }

            // O += T * V for this k-chunk (V via ldmatrix.trans)
#pragma unroll
            for (int dch = 0; dch < 4; dch++) {
                uint32_t vf[4];
                LDSM4T(vf, smb + A_VH +
                           ((nc * 16 + v_r) * APCH + dch * 16 + v_c) * 2);
#pragma unroll
                for (int hf = 0; hf < 2; hf++) {
                    int j = dch * 2 + hf;
                    MMA_F16(oacc[j], aph, vf[2*hf], vf[2*hf+1]);
                }
            }
        }
    }

    rsum0 += __shfl_xor_sync(0xffffffffu, rsum0, 1);
    rsum0 += __shfl_xor_sync(0xffffffffu, rsum0, 2);
    rsum1 += __shfl_xor_sync(0xffffffffu, rsum1, 1);
    rsum1 += __shfl_xor_sync(0xffffffffu, rsum1, 2);
    const float inv0 = 1.f / (rsum0 + 1e-32f);
    const float inv1 = 1.f / (rsum1 + 1e-32f);

    // store O (fp16) into [B, NQ, HSIZE] layout
    const int qr0 = q0g + mrow0;
#pragma unroll
    for (int j = 0; j < 8; j++) {
        int d = h * HD + j * 8 + 2 * (lane & 3);
        *(uint32_t*)(oh + (size_t)(b * SEQ + qr0) * NDIM + d) =
            cvt_h2(oacc[j][0] * inv0, oacc[j][1] * inv0);
        *(uint32_t*)(oh + (size_t)(b * SEQ + qr0 + 8) * NDIM + d) =
            cvt_h2(oacc[j][2] * inv1, oacc[j][3] * inv1);
    }
}

// ---------------- launcher ----------------------------------------------------
extern "C" void kernel_launch(void* const* d_in, const int* in_sizes, int n_in,
                              void* d_out, int out_size)
{
    const float* iQ      = (const float*)d_in[0];
    const float* iK      = (const float*)d_in[1];
    const float* iV      = (const float*)d_in[2];
    const void*  mask    = d_in[3];
    const float* Wq      = (const float*)d_in[4];
    const float* Wk      = (const float*)d_in[5];
    const float* Wv      = (const float*)d_in[6];
    const float* Wo      = (const float*)d_in[7];
    const float* sn_bias = (const float*)d_in[8];
    float*       out     = (float*)d_out;

    __half *xq, *xk, *xv, *ohb, *wqh, *wql, *wkh, *wvh, *woh;
    __half *qh, *kh, *vh;
    uint32_t* gmb;
    cudaGetSymbolAddress((void**)&xq, g_xq);
    cudaGetSymbolAddress((void**)&xk, g_xk);
    cudaGetSymbolAddress((void**)&xv, g_xv);
    cudaGetSymbolAddress((void**)&ohb, g_oh);
    cudaGetSymbolAddress((void**)&wqh, g_wqh);
    cudaGetSymbolAddress((void**)&wql, g_wql);
    cudaGetSymbolAddress((void**)&wkh, g_wkh);
    cudaGetSymbolAddress((void**)&wvh, g_wvh);
    cudaGetSymbolAddress((void**)&woh, g_woh);
    cudaGetSymbolAddress((void**)&qh, g_qh);
    cudaGetSymbolAddress((void**)&kh, g_kh);
    cudaGetSymbolAddress((void**)&vh, g_vh);
    cudaGetSymbolAddress((void**)&gmb, g_maskb);

    cudaFuncSetAttribute(gemm_qkv,
                         cudaFuncAttributeMaxDynamicSharedMemorySize, GSMEM);
    cudaFuncSetAttribute(gemm_out,
                         cudaFuncAttributeMaxDynamicSharedMemorySize, GSMEM);
    cudaFuncSetAttribute(attn_f16,
                         cudaFuncAttributeMaxDynamicSharedMemorySize, A_BYTES);

    // mask dtype autodetect + bit-pack
    detect_mask_kernel<<<1, 256>>>((const unsigned int*)mask);
    convert_maskb<<<2048, 256>>>(mask, gmb);

    const size_t nA4 = (size_t)MDIM * KDIM / 4;
    const size_t nW4 = (size_t)NDIM * KDIM / 4;

    // merged converts (2 launches)
    convert_h3<<<4096, 256>>>((const float4*)iQ, (const float4*)iK,
                              (const float4*)iV,
                              (uint2*)xq, (uint2*)xk, (uint2*)xv, nA4);
    convert_w<<<2048, 256>>>((const float4*)Wq, (const float4*)Wk,
                             (const float4*)Wv, (const float4*)Wo,
                             (uint2*)wqh, (uint2*)wql, (uint2*)wkh,
                             (uint2*)wvh, (uint2*)woh, nW4);

    // merged Q/K/V projections: one launch, 1536 CTAs
    gemm_qkv<<<dim3(NDIM / 128, 192), 256, GSMEM>>>(
        xq, xk, xv, wqh, wql, wkh, wvh, qh, kh, vh);

    attn_f16<<<dim3(SEQ / 128, NB * NH), 256, A_BYTES>>>(
        qh, kh, vh, gmb, sn_bias, ohb);

    gemm_out<<<dim3(NDIM / 128, MDIM / 128), 256, GSMEM>>>(ohb, woh, out);
}